// round 5
// baseline (speedup 1.0000x reference)
#include <cuda_runtime.h>
#include <cuda_bf16.h>
#include <math.h>
#include <stdint.h>

// Problem constants: B=16, C=256, H=W=32
#define PNUM 16384
#define CNUM 256
#define NKTOT 2304
#define CLIP1 0.9999999f
#define MAXN  0.99999f
#define EPSF  1e-15f

#define STAGE_BYTES 98304        // Ahi 16K + Alo 16K + Bhi 32K + Blo 32K
#define YST   264                // ybuf row stride (floats)
#define CONV_SMEM (2*STAGE_BYTES) // 196608; ybuf 135168 fits

// ---------------- device scratch ----------------
__device__ __align__(16) __nv_bfloat16 g_vhi[PNUM*CNUM];
__device__ __align__(16) __nv_bfloat16 g_vlo[PNUM*CNUM];
__device__ __align__(16) __nv_bfloat16 g_zthi1[CNUM*NKTOT];
__device__ __align__(16) __nv_bfloat16 g_ztlo1[CNUM*NKTOT];
__device__ __align__(16) __nv_bfloat16 g_zthi2[CNUM*NKTOT];
__device__ __align__(16) __nv_bfloat16 g_ztlo2[CNUM*NKTOT];
__device__ __align__(16) float g_h [PNUM*CNUM];
__device__ __align__(16) float g_xl[PNUM*CNUM];
__device__ float g_q2[PNUM];
__device__ float g_zn[512];
__device__ float g_pm[128*CNUM];
__device__ float g_pd[128];
__device__ float g_pv[128];
__device__ float g_mu[CNUM];
__device__ float g_sc[8];

// ---------------- PTX helpers (baseline compute_103-safe) ----------------
__device__ __forceinline__ uint32_t smem_u32(const void* p) {
    uint32_t a;
    asm("{ .reg .u64 t; cvta.to.shared.u64 t, %1; cvt.u32.u64 %0, t; }" : "=r"(a) : "l"(p));
    return a;
}
__device__ __forceinline__ void cpa16(uint32_t dst, const void* src) {
    asm volatile("cp.async.cg.shared.global [%0], [%1], 16;" :: "r"(dst), "l"(src) : "memory");
}
__device__ __forceinline__ void cpa16z(uint32_t dst, const void* src, uint32_t srcsz) {
    asm volatile("cp.async.cg.shared.global [%0], [%1], 16, %2;"
        :: "r"(dst), "l"(src), "r"(srcsz) : "memory");
}
__device__ __forceinline__ void cp_commit() {
    asm volatile("cp.async.commit_group;" ::: "memory");
}
template<int N>
__device__ __forceinline__ void cp_wait() {
    asm volatile("cp.async.wait_group %0;" :: "n"(N) : "memory");
}
__device__ __forceinline__ void ldsm4(uint32_t* r, uint32_t addr) {
    asm volatile("ldmatrix.sync.aligned.m8n8.x4.shared.b16 {%0,%1,%2,%3}, [%4];"
        : "=r"(r[0]), "=r"(r[1]), "=r"(r[2]), "=r"(r[3]) : "r"(addr));
}
__device__ __forceinline__ void mma16816(float* d, const uint32_t* a, const uint32_t* b) {
    asm volatile("mma.sync.aligned.m16n8k16.row.col.f32.bf16.bf16.f32 "
        "{%0,%1,%2,%3}, {%4,%5,%6,%7}, {%8,%9}, {%0,%1,%2,%3};"
        : "+f"(d[0]), "+f"(d[1]), "+f"(d[2]), "+f"(d[3])
        : "r"(a[0]), "r"(a[1]), "r"(a[2]), "r"(a[3]), "r"(b[0]), "r"(b[1]));
}

// ---------------- reductions ----------------
__device__ __forceinline__ float warpSum(float v) {
#pragma unroll
    for (int o = 16; o > 0; o >>= 1) v += __shfl_xor_sync(0xffffffffu, v, o);
    return v;
}
template<int K>
__device__ __forceinline__ void blockReduceK(float* v, float* sbuf) {
    int tid = threadIdx.x, lane = tid & 31, wid = tid >> 5;
#pragma unroll
    for (int i = 0; i < K; i++) {
        float x = v[i];
#pragma unroll
        for (int o = 16; o > 0; o >>= 1) x += __shfl_down_sync(0xffffffffu, x, o);
        if (lane == 0) sbuf[i*8 + wid] = x;
    }
    __syncthreads();
    if (tid == 0) {
#pragma unroll
        for (int i = 0; i < K; i++) {
            float s = sbuf[i*8];
            for (int w = 1; w < 8; w++) s += sbuf[i*8 + w];
            sbuf[i*8] = s;
        }
    }
    __syncthreads();
#pragma unroll
    for (int i = 0; i < K; i++) v[i] = sbuf[i*8];
    __syncthreads();
}

// ---------------- bf16 split store ----------------
union BU { uint4 u; __nv_bfloat16 h[8]; };
__device__ __forceinline__ void store_split8(size_t base, const float* v) {
    BU hi, lo;
#pragma unroll
    for (int i = 0; i < 8; i++) {
        __nv_bfloat16 h = __float2bfloat16(v[i]);
        hi.h[i] = h;
        lo.h[i] = __float2bfloat16(v[i] - __bfloat162float(h));
    }
    *(uint4*)(g_vhi + base) = hi.u;
    *(uint4*)(g_vlo + base) = lo.u;
}

// ---------------- z column norms ----------------
__global__ void zn_kernel(const float* __restrict__ z1, const float* __restrict__ z2) {
    int col = blockIdx.x;
    const float* z = (col < 256) ? z1 : z2;
    int j = col & 255;
    float s = 0.f;
    for (int k = threadIdx.x; k < NKTOT; k += 64) {
        float w = z[k*256 + j];
        s += w*w;
    }
#pragma unroll
    for (int o = 16; o > 0; o >>= 1) s += __shfl_down_sync(0xffffffffu, s, o);
    __shared__ float sb[2];
    if ((threadIdx.x & 31) == 0) sb[threadIdx.x >> 5] = s;
    __syncthreads();
    if (threadIdx.x == 0) g_zn[col] = sqrtf(fmaxf(sb[0] + sb[1], EPSF));
}

// ---------------- z split + transpose: z[K,N] fp32 -> zT hi/lo [N,K] bf16 ----------------
__global__ void zsplit_kernel(const float* __restrict__ z1, const float* __restrict__ z2) {
    __shared__ float t[32][33];
    const float* z = blockIdx.z ? z2 : z1;
    __nv_bfloat16* oh = blockIdx.z ? g_zthi2 : g_zthi1;
    __nv_bfloat16* ol = blockIdx.z ? g_ztlo2 : g_ztlo1;
    int kb = blockIdx.x * 32, nb = blockIdx.y * 32;
    int tx = threadIdx.x, ty = threadIdx.y;
#pragma unroll
    for (int i = 0; i < 4; i++)
        t[ty + i*8][tx] = z[(size_t)(kb + ty + i*8)*256 + nb + tx];
    __syncthreads();
#pragma unroll
    for (int i = 0; i < 4; i++) {
        int n = nb + ty + i*8, k = kb + tx;
        float v = t[tx][ty + i*8];
        __nv_bfloat16 h = __float2bfloat16(v);
        oh[(size_t)n*NKTOT + k] = h;
        ol[(size_t)n*NKTOT + k] = __float2bfloat16(v - __bfloat162float(h));
    }
}

// ---------------- xT: x NCHW -> g_xl [p][c] ----------------
__global__ void xT_kernel(const float* __restrict__ x) {
    __shared__ float t[32][33];
    int hw0 = blockIdx.x * 32, c0 = blockIdx.y * 32, b = blockIdx.z;
    int tx = threadIdx.x, ty = threadIdx.y;
#pragma unroll
    for (int i = 0; i < 4; i++)
        t[ty + i*8][tx] = x[(size_t)(b*256 + c0 + ty + i*8)*1024 + hw0 + tx];
    __syncthreads();
#pragma unroll
    for (int i = 0; i < 4; i++)
        g_xl[(size_t)(b*1024 + hw0 + ty + i*8)*256 + c0 + tx] = t[tx][ty + i*8];
}

// ---------------- pre2: coalesced x read -> v hi/lo + q2 ----------------
__global__ void pre2_kernel(const float* __restrict__ x, float scale) {
    __shared__ float sx[256][33];
    int tid = threadIdx.x, lane = tid & 31, w8 = tid >> 5;
    int p0 = blockIdx.x * 32;
    int b = p0 >> 10, hw0 = p0 & 1023;
#pragma unroll 8
    for (int i = 0; i < 32; i++) {
        int c = i*8 + w8;
        sx[c][lane] = x[(size_t)(b*256 + c)*1024 + hw0 + lane];
    }
    __syncthreads();
#pragma unroll
    for (int pp = 0; pp < 4; pp++) {
        int pl = w8*4 + pp;
        int p = p0 + pl;
        float xv[8];
#pragma unroll
        for (int i = 0; i < 8; i++) xv[i] = sx[lane*8 + i][pl];
        float q = 0.f;
#pragma unroll
        for (int i = 0; i < 8; i++) q += xv[i]*xv[i];
        float n2 = warpSum(q);
        float n = sqrtf(fmaxf(n2, EPSF));
        float f = atanhf(fminf(n, CLIP1)) / n * scale;
        float vv[8];
#pragma unroll
        for (int i = 0; i < 8; i++) vv[i] = f * xv[i];
        store_split8((size_t)p*256 + lane*8, vv);
        if (lane == 0) g_q2[p] = f*f*n2;
    }
}

// ---------------- per-pixel s = lam*alpha from 3x3 q2 sums ----------------
__device__ __forceinline__ float s_from_q2(int p) {
    int h = (p >> 5) & 31, w = p & 31;
    float np2 = 0.f;
#pragma unroll
    for (int dy = -1; dy <= 1; dy++)
#pragma unroll
        for (int dx = -1; dx <= 1; dx++) {
            int sh = h + dy, sw = w + dx;
            if ((unsigned)sh < 32u && (unsigned)sw < 32u) np2 += g_q2[p + dy*32 + dx];
        }
    float np = sqrtf(fmaxf(np2, EPSF));
    float th = tanhf(np);
    float uf = th / np;
    float un = th;
    if (un > MAXN) { uf *= MAXN/un; un = MAXN; }
    float lam = 2.0f / fmaxf(1.0f - un*un, EPSF);
    return lam * uf;
}

// ---------------- HMMA conv + fused Poincare-FC epilogue ----------------
// CTA: 128 pixels x 256 outputs. 256 thr = 8 warps (2m x 4n), warp 64x64.
// K = 9 taps x 256 ch, split-3 bf16 (hihi + lohi + hilo), BK=64, 2-stage,
// zero-fill cp.async for out-of-image taps (no halo padding).
__global__ void __launch_bounds__(256, 1) conv_mma(int which) {
    extern __shared__ __align__(16) char dsm[];
    uint32_t sbase = smem_u32(dsm);

    const __nv_bfloat16* zThi = which ? g_zthi2 : g_zthi1;
    const __nv_bfloat16* zTlo = which ? g_ztlo2 : g_ztlo1;
    int znoff = which ? 256 : 0;

    int tid = threadIdx.x, wid = tid >> 5, l = tid & 31;
    int p0 = blockIdx.x << 7;

    // ---- mma lane precompute ----
    int m0 = (wid & 1) << 6;
    int n0 = (wid >> 1) << 6;
    int mi = l >> 3;
    int cA0 = mi >> 1;
    int rA0 = m0 + ((mi & 1) << 3) + (l & 7);
    uint32_t raBase = (uint32_t)(rA0 * 128);
    int sA = rA0 & 7;
    int cB0 = mi & 1;
    int rB0 = n0 + (((mi >> 1) & 1) << 3) + (l & 7);
    uint32_t rbBase = (uint32_t)(rB0 * 128);
    int sB = rB0 & 7;

    float acc[4][8][4];
#pragma unroll
    for (int i = 0; i < 4; i++)
#pragma unroll
        for (int j = 0; j < 8; j++)
#pragma unroll
            for (int k = 0; k < 4; k++) acc[i][j][k] = 0.f;

    int lc = tid & 7;
    int lr0 = tid >> 3;

    auto load_chunk = [&](int kc, int stage) {
        int tap = kc >> 2;
        int dy = tap / 3, dx = tap - dy*3;
        int cb = (kc & 3) << 6;
        int qoff = (dy - 1)*32 + (dx - 1);
        int coff = cb + lc*8;
        uint32_t st = sbase + (uint32_t)stage*STAGE_BYTES;
#pragma unroll
        for (int i = 0; i < 4; i++) {
            int r = lr0 + i*32;
            int p = p0 + r;
            int sh = ((p >> 5) & 31) + dy - 1;
            int sw = (p & 31) + dx - 1;
            bool ok = ((unsigned)sh < 32u) && ((unsigned)sw < 32u);
            int q = ok ? (p + qoff) : p;
            uint32_t sz = ok ? 16u : 0u;
            uint32_t phys = (uint32_t)(r*128 + ((lc ^ (r & 7)) << 4));
            cpa16z(st + phys,         g_vhi + (size_t)q*256 + coff, sz);
            cpa16z(st + 16384 + phys, g_vlo + (size_t)q*256 + coff, sz);
        }
#pragma unroll
        for (int i = 0; i < 8; i++) {
            int n = lr0 + i*32;
            uint32_t phys = (uint32_t)(n*128 + ((lc ^ (n & 7)) << 4));
            size_t src = (size_t)n*NKTOT + tap*256 + coff;
            cpa16(st + 32768 + phys, zThi + src);
            cpa16(st + 65536 + phys, zTlo + src);
        }
        cp_commit();
    };

    load_chunk(0, 0);

    for (int kc = 0; kc < 36; kc++) {
        int stage = kc & 1;
        cp_wait<0>();
        __syncthreads();
        if (kc + 1 < 36) load_chunk(kc + 1, stage ^ 1);

        uint32_t st = sbase + (uint32_t)stage*STAGE_BYTES;
        uint32_t Ahi = st, Alo = st + 16384, Bhi = st + 32768, Blo = st + 65536;
#pragma unroll
        for (int ks = 0; ks < 4; ks++) {
            uint32_t ah[16], al[16], bb[16];
            uint32_t offA = (uint32_t)(((cA0 + 2*ks) ^ sA) << 4);
            uint32_t offB = (uint32_t)(((cB0 + 2*ks) ^ sB) << 4);
#pragma unroll
            for (int mf = 0; mf < 4; mf++) ldsm4(ah + mf*4, Ahi + raBase + mf*2048 + offA);
#pragma unroll
            for (int mf = 0; mf < 4; mf++) ldsm4(al + mf*4, Alo + raBase + mf*2048 + offA);
#pragma unroll
            for (int j = 0; j < 4; j++) ldsm4(bb + j*4, Bhi + rbBase + j*2048 + offB);
#pragma unroll
            for (int nf = 0; nf < 8; nf++) {
                const uint32_t* bp = bb + (nf >> 1)*4 + (nf & 1)*2;
#pragma unroll
                for (int mf = 0; mf < 4; mf++) mma16816(acc[mf][nf], ah + mf*4, bp);
#pragma unroll
                for (int mf = 0; mf < 4; mf++) mma16816(acc[mf][nf], al + mf*4, bp);
            }
#pragma unroll
            for (int j = 0; j < 4; j++) ldsm4(bb + j*4, Blo + rbBase + j*2048 + offB);
#pragma unroll
            for (int nf = 0; nf < 8; nf++) {
                const uint32_t* bp = bb + (nf >> 1)*4 + (nf & 1)*2;
#pragma unroll
                for (int mf = 0; mf < 4; mf++) mma16816(acc[mf][nf], ah + mf*4, bp);
            }
        }
    }
    __syncthreads();

    // ---- fused Poincare-FC epilogue ----
    float* ybuf = (float*)dsm;
    int row0 = m0 + (l >> 2);
    int col0 = n0 + ((l & 3) << 1);
    float sr[4][2];
#pragma unroll
    for (int mf = 0; mf < 4; mf++)
#pragma unroll
        for (int hf = 0; hf < 2; hf++)
            sr[mf][hf] = s_from_q2(p0 + row0 + mf*16 + hf*8);
    float2 zn2[8];
#pragma unroll
    for (int nf = 0; nf < 8; nf++)
        zn2[nf] = *(const float2*)&g_zn[znoff + col0 + nf*8];

#pragma unroll
    for (int mf = 0; mf < 4; mf++)
#pragma unroll
        for (int nf = 0; nf < 8; nf++)
#pragma unroll
            for (int hf = 0; hf < 2; hf++) {
                float s = sr[mf][hf];
                float z0 = zn2[nf].x, z1 = zn2[nf].y;
                float a0 = acc[mf][nf][hf*2], a1 = acc[mf][nf][hf*2 + 1];
                float y0 = sinhf(2.0f*z0*asinhf(a0*s/z0));
                float y1 = sinhf(2.0f*z1*asinhf(a1*s/z1));
                int r = row0 + mf*16 + hf*8;
                *(float2*)&ybuf[r*YST + col0 + nf*8] = make_float2(y0, y1);
            }
    __syncthreads();

    // row reduction + scale + write g_h
    {
        int row = tid >> 1, q = tid & 1;
        const float4* yr = (const float4*)(ybuf + row*YST + q*128);
        float tot = 0.f;
#pragma unroll
        for (int i = 0; i < 32; i++) {
            float4 v = yr[i];
            tot += v.x*v.x + v.y*v.y + v.z*v.z + v.w*v.w;
        }
        tot += __shfl_xor_sync(0xffffffffu, tot, 1);
        float inv = 1.0f / (1.0f + sqrtf(1.0f + tot));
        float4* dst = (float4*)(g_h + (size_t)(p0 + row)*256 + q*128);
#pragma unroll
        for (int i = 0; i < 32; i++) {
            float4 v = yr[i];
            v.x *= inv; v.y *= inv; v.z *= inv; v.w *= inv;
            dst[i] = v;
        }
    }
}

// ---------------- BN phase 1: partial sums (warp-per-pixel) ----------------
__global__ void bnred_w() {
    __shared__ float sm[8][256];
    __shared__ float sd[8];
    int wid = threadIdx.x >> 5, lid = threadIdx.x & 31;
    int p0 = blockIdx.x * 128;
    float accm[8] = {0,0,0,0,0,0,0,0};
    float accd = 0.f;
    for (int i = 0; i < 16; i++) {
        int p = p0 + wid*16 + i;
        const float4* row = (const float4*)(g_h + (size_t)p*256 + lid*8);
        float4 a = row[0], c = row[1];
        float v[8] = {a.x,a.y,a.z,a.w,c.x,c.y,c.z,c.w};
        float q = 0.f;
#pragma unroll
        for (int j = 0; j < 8; j++) q += v[j]*v[j];
        float n2 = warpSum(q);
        float lam = 2.0f / fmaxf(1.0f - n2, EPSF);
#pragma unroll
        for (int j = 0; j < 8; j++) accm[j] += lam * v[j];
        accd += lam - 1.0f;
    }
#pragma unroll
    for (int j = 0; j < 8; j++) sm[wid][lid*8 + j] = accm[j];
    if (lid == 0) sd[wid] = accd;
    __syncthreads();
    int c = threadIdx.x;
    float s = 0.f;
    for (int w = 0; w < 8; w++) s += sm[w][c];
    g_pm[blockIdx.x*256 + c] = s;
    if (c == 0) {
        float d = 0.f;
        for (int w = 0; w < 8; w++) d += sd[w];
        g_pd[blockIdx.x] = d;
    }
}

// ---------------- BN phase 2: gyromidpoint + scalars ----------------
__global__ void bnmu_kernel(const float* __restrict__ bias) {
    __shared__ float sb[24];
    int c = threadIdx.x;
    float msum = 0.f;
    for (int g = 0; g < 128; g++) msum += g_pm[g*256 + c];
    float dv = (c < 128) ? g_pd[c] : 0.f;
    float r1[1] = { dv };
    blockReduceK<1>(r1, sb);
    float den = fmaxf(r1[0], EPSF);
    float m = msum / den;
    float r2[1] = { m*m };
    blockReduceK<1>(r2, sb);
    float nm = sqrtf(fmaxf(r2[0], EPSF));
    float fac = tanhf(0.5f * atanhf(fminf(nm, CLIP1))) / nm;
    float muc = fac * m;
    g_mu[c] = muc;
    float bc = bias[c];
    float r3[3] = { muc*muc, bc*bc, bc*muc };
    blockReduceK<3>(r3, sb);
    if (c == 0) {
        float mu2 = r3[0], b2 = r3[1], bm = r3[2];
        g_sc[0] = mu2;
        g_sc[1] = 2.0f / fmaxf(1.0f - mu2, EPSF);
        g_sc[2] = b2;
        g_sc[3] = 2.0f / fmaxf(1.0f - b2, EPSF);
        g_sc[4] = bm;
    }
}

// ---------------- BN phase 3: partial variance (warp-per-pixel) ----------------
__global__ void bnvar_w() {
    __shared__ float sv[8];
    int wid = threadIdx.x >> 5, lid = threadIdx.x & 31;
    int p0 = blockIdx.x * 128;
    float mu8[8];
#pragma unroll
    for (int j = 0; j < 8; j++) mu8[j] = g_mu[lid*8 + j];
    float mu2 = g_sc[0];
    float acc = 0.f;
    for (int i = 0; i < 16; i++) {
        int p = p0 + wid*16 + i;
        const float4* row = (const float4*)(g_h + (size_t)p*256 + lid*8);
        float4 a = row[0], cc = row[1];
        float v[8] = {a.x,a.y,a.z,a.w,cc.x,cc.y,cc.z,cc.w};
        float q1 = 0.f, q2 = 0.f;
#pragma unroll
        for (int j = 0; j < 8; j++) { q1 += v[j]*v[j]; q2 += v[j]*mu8[j]; }
        float xp2 = warpSum(q1);
        float ip  = warpSum(q2);
        float A = 1.0f - 2.0f*ip + mu2;
        float B = 1.0f - xp2;
        float nn = fmaxf(A*A*xp2 - 2.0f*A*B*ip + B*B*mu2, 0.f);
        float den = fmaxf(1.0f - 2.0f*ip + xp2*mu2, EPSF);
        float nr = sqrtf(fmaxf(nn/(den*den), EPSF));
        float dd = 2.0f * atanhf(fminf(nr, CLIP1));
        acc += dd*dd;
    }
    if (lid == 0) sv[wid] = acc;
    __syncthreads();
    if (threadIdx.x == 0) {
        float s = 0.f;
        for (int w = 0; w < 8; w++) s += sv[w];
        g_pv[blockIdx.x] = s;
    }
}

// ---------------- BN phase 4: finalize rstd ----------------
__global__ void bnfin_kernel(const float* __restrict__ weight) {
    int tid = threadIdx.x;
    float v = g_pv[tid];
#pragma unroll
    for (int o = 16; o > 0; o >>= 1) v += __shfl_down_sync(0xffffffffu, v, o);
    __shared__ float sb[4];
    if ((tid & 31) == 0) sb[tid >> 5] = v;
    __syncthreads();
    if (tid == 0) {
        float var = (sb[0] + sb[1] + sb[2] + sb[3]) / 16384.0f;
        g_sc[5] = sqrtf(weight[0] / fmaxf(var, EPSF));
    }
}

// ---------------- shared BN point transform (warp version) ----------------
__device__ __forceinline__ float bn_point_w(const float* xv, const float* mu8, const float* b8,
                                            float* hc) {
    float mu2 = g_sc[0], lam_mu = g_sc[1], b2 = g_sc[2], lam_b = g_sc[3],
          bm = g_sc[4], rstd = g_sc[5];
    float s0 = 0.f, s1 = 0.f, s2 = 0.f;
#pragma unroll
    for (int i = 0; i < 8; i++) { s0 += xv[i]*xv[i]; s1 += mu8[i]*xv[i]; s2 += b8[i]*xv[i]; }
    float xp2 = warpSum(s0), ip = warpSum(s1), bx = warpSum(s2);
    float A  = 1.0f - 2.0f*ip + xp2;
    float Bc = 1.0f - mu2;
    float den = fmaxf(1.0f - 2.0f*ip + mu2*xp2, EPSF);
    float nd2 = fmaxf(A*A*mu2 - 2.0f*A*Bc*ip + Bc*Bc*xp2, 0.f) / (den*den);
    float nd = sqrtf(fmaxf(nd2, EPSF));
    float cv = (2.0f/lam_mu) * atanhf(fminf(nd, CLIP1)) / nd;
    float uw = cv * (Bc*bx - A*bm) / den;
    float vw = cv * (A*mu2 - Bc*ip) / den;
    float av  = -uw*mu2 - vw - 2.0f*bm*vw;
    float bv2 = -vw*b2 + uw;
    float dgy = fmaxf(1.0f - 2.0f*bm + b2*mu2, EPSF);
    float fac = (lam_mu / lam_b) * rstd;
    float uc[8];
    float t0 = 0.f, t1 = 0.f;
#pragma unroll
    for (int i = 0; i < 8; i++) {
        float vc = cv * (Bc*xv[i] - A*mu8[i]) / den;
        uc[i] = (vc + 2.0f*(av*b8[i] - bv2*mu8[i]) / dgy) * fac;
        t0 += uc[i]*uc[i];
        t1 += b8[i]*uc[i];
    }
    float u2 = warpSum(t0), bu = warpSum(t1);
    float nu = sqrtf(fmaxf(u2, EPSF));
    float tf = tanhf(0.5f * lam_b * nu) / nu;
    float s2m = tf*tf*u2;
    float bs  = tf*bu;
    float A3 = 1.0f + 2.0f*bs + s2m, B3 = 1.0f - b2;
    float den3 = fmaxf(1.0f + 2.0f*bs + b2*s2m, EPSF);
#pragma unroll
    for (int i = 0; i < 8; i++) hc[i] = (A3*b8[i] + B3*tf*uc[i]) / den3;
    float nh2 = fmaxf(A3*A3*b2 + 2.0f*A3*B3*bs + B3*B3*s2m, 0.f) / (den3*den3);
    float nh = sqrtf(fmaxf(nh2, EPSF));
    if (nh > MAXN) {
        float q = MAXN / nh;
#pragma unroll
        for (int i = 0; i < 8; i++) hc[i] *= q;
        nh = MAXN;
    }
    return nh;
}

// ---------------- BN apply + hrelu + pre-for-conv2 (warp-per-pixel) ----------------
__global__ void bnapply_w(const float* __restrict__ bias, float scale) {
    int wid = threadIdx.x >> 5, lid = threadIdx.x & 31;
    int p = blockIdx.x * 8 + wid;
    const float4* row = (const float4*)(g_h + (size_t)p*256 + lid*8);
    float4 a = row[0], cc = row[1];
    float xv[8] = {a.x,a.y,a.z,a.w,cc.x,cc.y,cc.z,cc.w};
    float mu8[8], b8[8];
#pragma unroll
    for (int j = 0; j < 8; j++) { mu8[j] = g_mu[lid*8 + j]; b8[j] = bias[lid*8 + j]; }
    float hc[8];
    float nh = bn_point_w(xv, mu8, b8, hc);
    float lf = atanhf(fminf(nh, CLIP1)) / nh;
    float rc[8];
    float q = 0.f;
#pragma unroll
    for (int i = 0; i < 8; i++) { rc[i] = fmaxf(lf*hc[i], 0.f); q += rc[i]*rc[i]; }
    float rs = warpSum(q);
    float nr = sqrtf(fmaxf(rs, EPSF));
    float ef = tanhf(nr) / nr;
    float nhr = sqrtf(fmaxf(ef*ef*rs, EPSF));
    float adj = 1.0f;
    if (nhr > MAXN) { adj = MAXN/nhr; nhr = MAXN; }
    float f3 = atanhf(fminf(nhr, CLIP1)) / nhr * scale;
    float vv[8];
#pragma unroll
    for (int i = 0; i < 8; i++) vv[i] = f3 * ef * adj * rc[i];
    store_split8((size_t)p*256 + lid*8, vv);
    if (lid == 0) g_q2[p] = f3*f3*nhr*nhr;
}

// ---------------- BN2 apply + residual + hrelu + staged NCHW out ----------------
__global__ void final2_kernel(const float* __restrict__ bias, float* __restrict__ out) {
    __shared__ float so[256][33];
    int tid = threadIdx.x, lane = tid & 31, w8 = tid >> 5;
    int p0 = blockIdx.x * 32;
    int b = p0 >> 10, hw0 = p0 & 1023;
    float mu8[8], b8[8];
#pragma unroll
    for (int j = 0; j < 8; j++) { mu8[j] = g_mu[lane*8 + j]; b8[j] = bias[lane*8 + j]; }
#pragma unroll
    for (int pp = 0; pp < 4; pp++) {
        int pl = w8*4 + pp;
        int p = p0 + pl;
        const float4* row = (const float4*)(g_h + (size_t)p*256 + lane*8);
        float4 a = row[0], cc = row[1];
        float xv[8] = {a.x,a.y,a.z,a.w,cc.x,cc.y,cc.z,cc.w};
        float hc[8];
        float nh = bn_point_w(xv, mu8, b8, hc);
        const float4* rrow = (const float4*)(g_xl + (size_t)p*256 + lane*8);
        float4 r0 = rrow[0], r1 = rrow[1];
        float res[8] = {r0.x,r0.y,r0.z,r0.w,r1.x,r1.y,r1.z,r1.w};
        float q1 = 0.f, q2 = 0.f;
#pragma unroll
        for (int i = 0; i < 8; i++) { q1 += res[i]*res[i]; q2 += hc[i]*res[i]; }
        float y2 = warpSum(q1), xy = warpSum(q2);
        float x2 = nh*nh;
        float A4 = 1.0f + 2.0f*xy + y2, B4 = 1.0f - x2;
        float den4 = fmaxf(1.0f + 2.0f*xy + x2*y2, EPSF);
        float hm[8];
#pragma unroll
        for (int i = 0; i < 8; i++) hm[i] = (A4*hc[i] + B4*res[i]) / den4;
        float nm2 = fmaxf(A4*A4*x2 + 2.0f*A4*B4*xy + B4*B4*y2, 0.f) / (den4*den4);
        float nmv = sqrtf(fmaxf(nm2, EPSF));
        float lf = atanhf(fminf(nmv, CLIP1)) / nmv;
        float rc[8];
        float q = 0.f;
#pragma unroll
        for (int i = 0; i < 8; i++) { rc[i] = fmaxf(lf*hm[i], 0.f); q += rc[i]*rc[i]; }
        float rs = warpSum(q);
        float nr = sqrtf(fmaxf(rs, EPSF));
        float ef = tanhf(nr) / nr;
        float nhr = sqrtf(fmaxf(ef*ef*rs, EPSF));
        float adj = (nhr > MAXN) ? MAXN/nhr : 1.0f;
#pragma unroll
        for (int i = 0; i < 8; i++) so[lane*8 + i][pl] = ef * adj * rc[i];
    }
    __syncthreads();
#pragma unroll 8
    for (int i = 0; i < 32; i++) {
        int c = i*8 + w8;
        out[(size_t)(b*256 + c)*1024 + hw0 + lane] = so[c][lane];
    }
}

// ---------------- launcher ----------------
extern "C" void kernel_launch(void* const* d_in, const int* in_sizes, int n_in,
                              void* d_out, int out_size) {
    const float* x  = (const float*)d_in[0];
    const float* z1 = (const float*)d_in[1];
    const float* z2 = (const float*)d_in[2];
    const float* w1 = (const float*)d_in[3];
    const float* b1 = (const float*)d_in[4];
    const float* w2 = (const float*)d_in[5];
    const float* b2 = (const float*)d_in[6];
    float* out = (float*)d_out;

    // scale = Beta(1152, 0.5) / Beta(128, 0.5)
    double lg = lgamma(1152.0) - lgamma(1152.5) - lgamma(128.0) + lgamma(128.5);
    float scale = (float)exp(lg);

    static int smem_set = 0;
    if (!smem_set) {
        cudaFuncSetAttribute(conv_mma, cudaFuncAttributeMaxDynamicSharedMemorySize, CONV_SMEM);
        smem_set = 1;
    }

    // conv_mma is launch index 3 -> captured by ncu (-s skips land there empirically)
    zn_kernel<<<512, 64>>>(z1, z2);
    zsplit_kernel<<<dim3(72, 8, 2), dim3(32, 8)>>>(z1, z2);
    pre2_kernel<<<PNUM/32, 256>>>(x, scale);
    conv_mma<<<128, 256, CONV_SMEM>>>(0);

    bnred_w<<<128, 256>>>();
    bnmu_kernel<<<1, 256>>>(b1);
    bnvar_w<<<128, 256>>>();
    bnfin_kernel<<<1, 128>>>(w1);
    bnapply_w<<<PNUM/8, 256>>>(b1, scale);

    conv_mma<<<128, 256, CONV_SMEM>>>(1);
    xT_kernel<<<dim3(32, 8, 16), dim3(32, 8)>>>(x);

    bnred_w<<<128, 256>>>();
    bnmu_kernel<<<1, 256>>>(b2);
    bnvar_w<<<128, 256>>>();
    bnfin_kernel<<<1, 128>>>(w2);
    final2_kernel<<<PNUM/32, 256>>>(b2, out);
}

// round 6
// speedup vs baseline: 1.0252x; 1.0252x over previous
#include <cuda_runtime.h>
#include <cuda_bf16.h>
#include <math.h>
#include <stdint.h>

// Problem constants: B=16, C=256, H=W=32
#define PNUM 16384
#define CNUM 256
#define NKTOT 2304
#define CLIP1 0.9999999f
#define MAXN  0.99999f
#define EPSF  1e-15f

#define STAGE_BYTES 32768u       // Ahi 8K + Alo 8K + Bhi 8K + Blo 8K
#define YST2  132                // ybuf row stride (floats)
#define CONV_SMEM (3*32768)      // 96 KB/CTA -> 2 CTAs/SM; ybuf 128*132*4=67.6KB fits

// ---------------- device scratch ----------------
__device__ __align__(16) __nv_bfloat16 g_vhi[PNUM*CNUM];
__device__ __align__(16) __nv_bfloat16 g_vlo[PNUM*CNUM];
__device__ __align__(16) __nv_bfloat16 g_zthi1[CNUM*NKTOT];
__device__ __align__(16) __nv_bfloat16 g_ztlo1[CNUM*NKTOT];
__device__ __align__(16) __nv_bfloat16 g_zthi2[CNUM*NKTOT];
__device__ __align__(16) __nv_bfloat16 g_ztlo2[CNUM*NKTOT];
__device__ __align__(16) float g_h [PNUM*CNUM];   // RAW y (pre-normalization)
__device__ __align__(16) float g_xl[PNUM*CNUM];
__device__ float g_q2[PNUM];
__device__ float g_zn[512];
__device__ float g_pm[128*CNUM];
__device__ float g_pd[128];
__device__ float g_pv[128];
__device__ float g_mu[CNUM];
__device__ float g_sc[8];

// ---------------- PTX helpers (baseline compute_103-safe) ----------------
__device__ __forceinline__ uint32_t smem_u32(const void* p) {
    uint32_t a;
    asm("{ .reg .u64 t; cvta.to.shared.u64 t, %1; cvt.u32.u64 %0, t; }" : "=r"(a) : "l"(p));
    return a;
}
__device__ __forceinline__ void cpa16(uint32_t dst, const void* src) {
    asm volatile("cp.async.cg.shared.global [%0], [%1], 16;" :: "r"(dst), "l"(src) : "memory");
}
__device__ __forceinline__ void cpa16z(uint32_t dst, const void* src, uint32_t srcsz) {
    asm volatile("cp.async.cg.shared.global [%0], [%1], 16, %2;"
        :: "r"(dst), "l"(src), "r"(srcsz) : "memory");
}
__device__ __forceinline__ void cp_commit() {
    asm volatile("cp.async.commit_group;" ::: "memory");
}
template<int N>
__device__ __forceinline__ void cp_wait() {
    asm volatile("cp.async.wait_group %0;" :: "n"(N) : "memory");
}
__device__ __forceinline__ void ldsm4(uint32_t* r, uint32_t addr) {
    asm volatile("ldmatrix.sync.aligned.m8n8.x4.shared.b16 {%0,%1,%2,%3}, [%4];"
        : "=r"(r[0]), "=r"(r[1]), "=r"(r[2]), "=r"(r[3]) : "r"(addr));
}
__device__ __forceinline__ void mma16816(float* d, const uint32_t* a, const uint32_t* b) {
    asm volatile("mma.sync.aligned.m16n8k16.row.col.f32.bf16.bf16.f32 "
        "{%0,%1,%2,%3}, {%4,%5,%6,%7}, {%8,%9}, {%0,%1,%2,%3};"
        : "+f"(d[0]), "+f"(d[1]), "+f"(d[2]), "+f"(d[3])
        : "r"(a[0]), "r"(a[1]), "r"(a[2]), "r"(a[3]), "r"(b[0]), "r"(b[1]));
}

// swizzled physical offset within a [rows][32 bf16] tile (row = 64B, chunk = 16B)
__device__ __forceinline__ uint32_t swz(int r, int c) {
    return (uint32_t)(((r >> 1) << 7) | (((((r & 1) << 2) | c) ^ ((r >> 1) & 7)) << 4));
}

// ---------------- reductions ----------------
__device__ __forceinline__ float warpSum(float v) {
#pragma unroll
    for (int o = 16; o > 0; o >>= 1) v += __shfl_xor_sync(0xffffffffu, v, o);
    return v;
}
template<int K>
__device__ __forceinline__ void blockReduceK(float* v, float* sbuf) {
    int tid = threadIdx.x, lane = tid & 31, wid = tid >> 5;
#pragma unroll
    for (int i = 0; i < K; i++) {
        float x = v[i];
#pragma unroll
        for (int o = 16; o > 0; o >>= 1) x += __shfl_down_sync(0xffffffffu, x, o);
        if (lane == 0) sbuf[i*8 + wid] = x;
    }
    __syncthreads();
    if (tid == 0) {
#pragma unroll
        for (int i = 0; i < K; i++) {
            float s = sbuf[i*8];
            for (int w = 1; w < 8; w++) s += sbuf[i*8 + w];
            sbuf[i*8] = s;
        }
    }
    __syncthreads();
#pragma unroll
    for (int i = 0; i < K; i++) v[i] = sbuf[i*8];
    __syncthreads();
}

// ---------------- bf16 split store ----------------
union BU { uint4 u; __nv_bfloat16 h[8]; };
__device__ __forceinline__ void store_split8(size_t base, const float* v) {
    BU hi, lo;
#pragma unroll
    for (int i = 0; i < 8; i++) {
        __nv_bfloat16 h = __float2bfloat16(v[i]);
        hi.h[i] = h;
        lo.h[i] = __float2bfloat16(v[i] - __bfloat162float(h));
    }
    *(uint4*)(g_vhi + base) = hi.u;
    *(uint4*)(g_vlo + base) = lo.u;
}

// ---------------- z column norms ----------------
__global__ void zn_kernel(const float* __restrict__ z1, const float* __restrict__ z2) {
    int col = blockIdx.x;
    const float* z = (col < 256) ? z1 : z2;
    int j = col & 255;
    float s = 0.f;
    for (int k = threadIdx.x; k < NKTOT; k += 64) {
        float w = z[k*256 + j];
        s += w*w;
    }
#pragma unroll
    for (int o = 16; o > 0; o >>= 1) s += __shfl_down_sync(0xffffffffu, s, o);
    __shared__ float sb[2];
    if ((threadIdx.x & 31) == 0) sb[threadIdx.x >> 5] = s;
    __syncthreads();
    if (threadIdx.x == 0) g_zn[col] = sqrtf(fmaxf(sb[0] + sb[1], EPSF));
}

// ---------------- z split + transpose ----------------
__global__ void zsplit_kernel(const float* __restrict__ z1, const float* __restrict__ z2) {
    __shared__ float t[32][33];
    const float* z = blockIdx.z ? z2 : z1;
    __nv_bfloat16* oh = blockIdx.z ? g_zthi2 : g_zthi1;
    __nv_bfloat16* ol = blockIdx.z ? g_ztlo2 : g_ztlo1;
    int kb = blockIdx.x * 32, nb = blockIdx.y * 32;
    int tx = threadIdx.x, ty = threadIdx.y;
#pragma unroll
    for (int i = 0; i < 4; i++)
        t[ty + i*8][tx] = z[(size_t)(kb + ty + i*8)*256 + nb + tx];
    __syncthreads();
#pragma unroll
    for (int i = 0; i < 4; i++) {
        int n = nb + ty + i*8, k = kb + tx;
        float v = t[tx][ty + i*8];
        __nv_bfloat16 h = __float2bfloat16(v);
        oh[(size_t)n*NKTOT + k] = h;
        ol[(size_t)n*NKTOT + k] = __float2bfloat16(v - __bfloat162float(h));
    }
}

// ---------------- xT: x NCHW -> g_xl [p][c] ----------------
__global__ void xT_kernel(const float* __restrict__ x) {
    __shared__ float t[32][33];
    int hw0 = blockIdx.x * 32, c0 = blockIdx.y * 32, b = blockIdx.z;
    int tx = threadIdx.x, ty = threadIdx.y;
#pragma unroll
    for (int i = 0; i < 4; i++)
        t[ty + i*8][tx] = x[(size_t)(b*256 + c0 + ty + i*8)*1024 + hw0 + tx];
    __syncthreads();
#pragma unroll
    for (int i = 0; i < 4; i++)
        g_xl[(size_t)(b*1024 + hw0 + ty + i*8)*256 + c0 + tx] = t[tx][ty + i*8];
}

// ---------------- pre2: coalesced x read -> v hi/lo + q2 ----------------
__global__ void pre2_kernel(const float* __restrict__ x, float scale) {
    __shared__ float sx[256][33];
    int tid = threadIdx.x, lane = tid & 31, w8 = tid >> 5;
    int p0 = blockIdx.x * 32;
    int b = p0 >> 10, hw0 = p0 & 1023;
#pragma unroll 8
    for (int i = 0; i < 32; i++) {
        int c = i*8 + w8;
        sx[c][lane] = x[(size_t)(b*256 + c)*1024 + hw0 + lane];
    }
    __syncthreads();
#pragma unroll
    for (int pp = 0; pp < 4; pp++) {
        int pl = w8*4 + pp;
        int p = p0 + pl;
        float xv[8];
#pragma unroll
        for (int i = 0; i < 8; i++) xv[i] = sx[lane*8 + i][pl];
        float q = 0.f;
#pragma unroll
        for (int i = 0; i < 8; i++) q += xv[i]*xv[i];
        float n2 = warpSum(q);
        float n = sqrtf(fmaxf(n2, EPSF));
        float f = atanhf(fminf(n, CLIP1)) / n * scale;
        float vv[8];
#pragma unroll
        for (int i = 0; i < 8; i++) vv[i] = f * xv[i];
        store_split8((size_t)p*256 + lane*8, vv);
        if (lane == 0) g_q2[p] = f*f*n2;
    }
}

// ---------------- per-pixel s = lam*alpha from 3x3 q2 sums ----------------
__device__ __forceinline__ float s_from_q2(int p) {
    int h = (p >> 5) & 31, w = p & 31;
    float np2 = 0.f;
#pragma unroll
    for (int dy = -1; dy <= 1; dy++)
#pragma unroll
        for (int dx = -1; dx <= 1; dx++) {
            int sh = h + dy, sw = w + dx;
            if ((unsigned)sh < 32u && (unsigned)sw < 32u) np2 += g_q2[p + dy*32 + dx];
        }
    float np = sqrtf(fmaxf(np2, EPSF));
    float th = tanhf(np);
    float uf = th / np;
    float un = th;
    if (un > MAXN) { uf *= MAXN/un; un = MAXN; }
    float lam = 2.0f / fmaxf(1.0f - un*un, EPSF);
    return lam * uf;
}

// ---------------- HMMA conv + fused Poincare-FC (raw-y output) ----------------
// Grid (128, 2): 128-pixel M-tile x 128-output N-half. 256 thr = 8 warps (4m x 2n),
// warp 32x64, acc=64 regs -> 2 CTAs/SM (16 warps/SM). BK=32, 3-stage.
// Output: RAW y (normalization folded into consumers).
__global__ void __launch_bounds__(256, 2) conv_mma(int which) {
    extern __shared__ __align__(16) char dsm[];
    uint32_t sbase = smem_u32(dsm);

    const __nv_bfloat16* zThi = which ? g_zthi2 : g_zthi1;
    const __nv_bfloat16* zTlo = which ? g_ztlo2 : g_ztlo1;
    int ncol0 = blockIdx.y << 7;
    int znoff = (which ? 256 : 0) + ncol0;

    int tid = threadIdx.x, wid = tid >> 5, l = tid & 31;
    int p0 = blockIdx.x << 7;

    // ---- loader precompute: 2 row-sets (r, r+64), 4 chunks/row ----
    int c4 = tid & 3;
    int r0 = tid >> 2;                       // 0..63
    uint32_t aph0 = swz(r0, c4), aph1 = swz(r0 + 64, c4);
    int ap0 = p0 + r0, ap1 = p0 + r0 + 64;
    int ah0 = (ap0 >> 5) & 31, aw0 = ap0 & 31;
    int ah1 = (ap1 >> 5) & 31, aw1 = ap1 & 31;
    size_t bb0 = (size_t)(ncol0 + r0)*NKTOT + c4*8;
    size_t bb1 = (size_t)(ncol0 + r0 + 64)*NKTOT + c4*8;

    // ---- mma lane precompute ----
    int m0 = (wid & 3) << 5;
    int n0w = (wid >> 2) << 6;
    int mi = l >> 3;
    int rA = m0 + ((mi & 1) << 3) + (l & 7);
    uint32_t qA0 = swz(rA, mi >> 1);
    int rB = n0w + (((mi >> 1) & 1) << 3) + (l & 7);
    uint32_t qB0 = swz(rB, mi & 1);

    float acc[2][8][4];
#pragma unroll
    for (int i = 0; i < 2; i++)
#pragma unroll
        for (int j = 0; j < 8; j++)
#pragma unroll
            for (int k = 0; k < 4; k++) acc[i][j][k] = 0.f;

    auto load_chunk = [&](int kc, int stage) {
        int tap = kc >> 3;
        int dy = tap / 3 - 1, dx = tap % 3 - 1;
        int cb = (kc & 7) << 5;
        int coff = cb + c4*8;
        uint32_t st = sbase + (uint32_t)stage*STAGE_BYTES;
        {
            int sh = ah0 + dy, sw = aw0 + dx;
            bool ok = ((unsigned)sh < 32u) && ((unsigned)sw < 32u);
            int q = ok ? (ap0 + dy*32 + dx) : ap0;
            uint32_t sz = ok ? 16u : 0u;
            cpa16z(st + aph0,        g_vhi + (size_t)q*256 + coff, sz);
            cpa16z(st + 8192 + aph0, g_vlo + (size_t)q*256 + coff, sz);
        }
        {
            int sh = ah1 + dy, sw = aw1 + dx;
            bool ok = ((unsigned)sh < 32u) && ((unsigned)sw < 32u);
            int q = ok ? (ap1 + dy*32 + dx) : ap1;
            uint32_t sz = ok ? 16u : 0u;
            cpa16z(st + aph1,        g_vhi + (size_t)q*256 + coff, sz);
            cpa16z(st + 8192 + aph1, g_vlo + (size_t)q*256 + coff, sz);
        }
        size_t boff = (size_t)tap*256 + cb;
        cpa16(st + 16384 + aph0, zThi + bb0 + boff);
        cpa16(st + 24576 + aph0, zTlo + bb0 + boff);
        cpa16(st + 16384 + aph1, zThi + bb1 + boff);
        cpa16(st + 24576 + aph1, zTlo + bb1 + boff);
        cp_commit();
    };

    load_chunk(0, 0);
    load_chunk(1, 1);

    for (int kc = 0; kc < 72; kc++) {
        int stage = kc % 3;
        if (kc < 70) cp_wait<1>(); else cp_wait<0>();
        __syncthreads();
        if (kc + 2 < 72) load_chunk(kc + 2, (kc + 2) % 3);

        uint32_t st = sbase + (uint32_t)stage*STAGE_BYTES;
        uint32_t Ahi = st, Alo = st + 8192, Bhi = st + 16384, Blo = st + 24576;
#pragma unroll
        for (int ks = 0; ks < 2; ks++) {
            uint32_t kx = (uint32_t)(ks << 5);
            uint32_t qa = qA0 ^ kx, qb = qB0 ^ kx;
            uint32_t ah[8], al[8], bbv[16];
            ldsm4(ah,     Ahi + qa);
            ldsm4(ah + 4, Ahi + qa + 1024);
            ldsm4(al,     Alo + qa);
            ldsm4(al + 4, Alo + qa + 1024);
#pragma unroll
            for (int j = 0; j < 4; j++) ldsm4(bbv + j*4, Bhi + qb + j*1024);
#pragma unroll
            for (int nf = 0; nf < 8; nf++) {
                const uint32_t* bp = bbv + nf*2;
                mma16816(acc[0][nf], ah,     bp);
                mma16816(acc[1][nf], ah + 4, bp);
                mma16816(acc[0][nf], al,     bp);
                mma16816(acc[1][nf], al + 4, bp);
            }
#pragma unroll
            for (int j = 0; j < 4; j++) ldsm4(bbv + j*4, Blo + qb + j*1024);
#pragma unroll
            for (int nf = 0; nf < 8; nf++) {
                const uint32_t* bp = bbv + nf*2;
                mma16816(acc[0][nf], ah,     bp);
                mma16816(acc[1][nf], ah + 4, bp);
            }
        }
    }
    __syncthreads();

    // ---- fused FC epilogue: raw y -> ybuf -> coalesced g_h ----
    float* ybuf = (float*)dsm;
    int row0 = m0 + (l >> 2);
    int col0 = n0w + ((l & 3) << 1);
    float sr[2][2];
#pragma unroll
    for (int mf = 0; mf < 2; mf++)
#pragma unroll
        for (int hf = 0; hf < 2; hf++)
            sr[mf][hf] = s_from_q2(p0 + row0 + mf*16 + hf*8);
    float2 zn2[8];
#pragma unroll
    for (int nf = 0; nf < 8; nf++)
        zn2[nf] = *(const float2*)&g_zn[znoff + col0 + nf*8];

#pragma unroll
    for (int mf = 0; mf < 2; mf++)
#pragma unroll
        for (int nf = 0; nf < 8; nf++)
#pragma unroll
            for (int hf = 0; hf < 2; hf++) {
                float s = sr[mf][hf];
                float z0 = zn2[nf].x, z1 = zn2[nf].y;
                float a0 = acc[mf][nf][hf*2], a1 = acc[mf][nf][hf*2 + 1];
                float y0 = sinhf(2.0f*z0*asinhf(a0*s/z0));
                float y1 = sinhf(2.0f*z1*asinhf(a1*s/z1));
                int r = row0 + mf*16 + hf*8;
                *(float2*)&ybuf[r*YST2 + col0 + nf*8] = make_float2(y0, y1);
            }
    __syncthreads();
    {
        int row = tid >> 1, q = tid & 1;
        const float4* yr = (const float4*)(ybuf + row*YST2 + q*64);
        float4* dst = (float4*)(g_h + (size_t)(p0 + row)*256 + ncol0 + q*64);
#pragma unroll
        for (int i = 0; i < 16; i++) dst[i] = yr[i];
    }
}

// ---------------- BN phase 1: partial sums (raw-y input, inv folded) ----------------
__global__ void bnred_w() {
    __shared__ float sm[8][256];
    __shared__ float sd[8];
    int wid = threadIdx.x >> 5, lid = threadIdx.x & 31;
    int p0 = blockIdx.x * 128;
    float accm[8] = {0,0,0,0,0,0,0,0};
    float accd = 0.f;
    for (int i = 0; i < 16; i++) {
        int p = p0 + wid*16 + i;
        const float4* row = (const float4*)(g_h + (size_t)p*256 + lid*8);
        float4 a = row[0], c = row[1];
        float v[8] = {a.x,a.y,a.z,a.w,c.x,c.y,c.z,c.w};
        float q = 0.f;
#pragma unroll
        for (int j = 0; j < 8; j++) q += v[j]*v[j];
        float tot = warpSum(q);
        float inv = 1.0f / (1.0f + sqrtf(1.0f + tot));
        float n2 = tot*inv*inv;
        float lam = 2.0f / fmaxf(1.0f - n2, EPSF);
        float li = lam * inv;
#pragma unroll
        for (int j = 0; j < 8; j++) accm[j] += li * v[j];
        accd += lam - 1.0f;
    }
#pragma unroll
    for (int j = 0; j < 8; j++) sm[wid][lid*8 + j] = accm[j];
    if (lid == 0) sd[wid] = accd;
    __syncthreads();
    int c = threadIdx.x;
    float s = 0.f;
    for (int w = 0; w < 8; w++) s += sm[w][c];
    g_pm[blockIdx.x*256 + c] = s;
    if (c == 0) {
        float d = 0.f;
        for (int w = 0; w < 8; w++) d += sd[w];
        g_pd[blockIdx.x] = d;
    }
}

// ---------------- BN phase 2: gyromidpoint + scalars ----------------
__global__ void bnmu_kernel(const float* __restrict__ bias) {
    __shared__ float sb[24];
    int c = threadIdx.x;
    float msum = 0.f;
    for (int g = 0; g < 128; g++) msum += g_pm[g*256 + c];
    float dv = (c < 128) ? g_pd[c] : 0.f;
    float r1[1] = { dv };
    blockReduceK<1>(r1, sb);
    float den = fmaxf(r1[0], EPSF);
    float m = msum / den;
    float r2[1] = { m*m };
    blockReduceK<1>(r2, sb);
    float nm = sqrtf(fmaxf(r2[0], EPSF));
    float fac = tanhf(0.5f * atanhf(fminf(nm, CLIP1))) / nm;
    float muc = fac * m;
    g_mu[c] = muc;
    float bc = bias[c];
    float r3[3] = { muc*muc, bc*bc, bc*muc };
    blockReduceK<3>(r3, sb);
    if (c == 0) {
        float mu2 = r3[0], b2 = r3[1], bm = r3[2];
        g_sc[0] = mu2;
        g_sc[1] = 2.0f / fmaxf(1.0f - mu2, EPSF);
        g_sc[2] = b2;
        g_sc[3] = 2.0f / fmaxf(1.0f - b2, EPSF);
        g_sc[4] = bm;
    }
}

// ---------------- BN phase 3: partial variance (raw-y input) ----------------
__global__ void bnvar_w() {
    __shared__ float sv[8];
    int wid = threadIdx.x >> 5, lid = threadIdx.x & 31;
    int p0 = blockIdx.x * 128;
    float mu8[8];
#pragma unroll
    for (int j = 0; j < 8; j++) mu8[j] = g_mu[lid*8 + j];
    float mu2 = g_sc[0];
    float acc = 0.f;
    for (int i = 0; i < 16; i++) {
        int p = p0 + wid*16 + i;
        const float4* row = (const float4*)(g_h + (size_t)p*256 + lid*8);
        float4 a = row[0], cc = row[1];
        float v[8] = {a.x,a.y,a.z,a.w,cc.x,cc.y,cc.z,cc.w};
        float q1 = 0.f, q2 = 0.f;
#pragma unroll
        for (int j = 0; j < 8; j++) { q1 += v[j]*v[j]; q2 += v[j]*mu8[j]; }
        float tot = warpSum(q1);
        float ipr = warpSum(q2);
        float inv = 1.0f / (1.0f + sqrtf(1.0f + tot));
        float xp2 = tot*inv*inv;
        float ip  = ipr*inv;
        float A = 1.0f - 2.0f*ip + mu2;
        float B = 1.0f - xp2;
        float nn = fmaxf(A*A*xp2 - 2.0f*A*B*ip + B*B*mu2, 0.f);
        float den = fmaxf(1.0f - 2.0f*ip + xp2*mu2, EPSF);
        float nr = sqrtf(fmaxf(nn/(den*den), EPSF));
        float dd = 2.0f * atanhf(fminf(nr, CLIP1));
        acc += dd*dd;
    }
    if (lid == 0) sv[wid] = acc;
    __syncthreads();
    if (threadIdx.x == 0) {
        float s = 0.f;
        for (int w = 0; w < 8; w++) s += sv[w];
        g_pv[blockIdx.x] = s;
    }
}

// ---------------- BN phase 4: finalize rstd ----------------
__global__ void bnfin_kernel(const float* __restrict__ weight) {
    int tid = threadIdx.x;
    float v = g_pv[tid];
#pragma unroll
    for (int o = 16; o > 0; o >>= 1) v += __shfl_down_sync(0xffffffffu, v, o);
    __shared__ float sb[4];
    if ((tid & 31) == 0) sb[tid >> 5] = v;
    __syncthreads();
    if (tid == 0) {
        float var = (sb[0] + sb[1] + sb[2] + sb[3]) / 16384.0f;
        g_sc[5] = sqrtf(weight[0] / fmaxf(var, EPSF));
    }
}

// ---------------- shared BN point transform (warp version) ----------------
__device__ __forceinline__ float bn_point_w(const float* xv, const float* mu8, const float* b8,
                                            float* hc) {
    float mu2 = g_sc[0], lam_mu = g_sc[1], b2 = g_sc[2], lam_b = g_sc[3],
          bm = g_sc[4], rstd = g_sc[5];
    float s0 = 0.f, s1 = 0.f, s2 = 0.f;
#pragma unroll
    for (int i = 0; i < 8; i++) { s0 += xv[i]*xv[i]; s1 += mu8[i]*xv[i]; s2 += b8[i]*xv[i]; }
    float xp2 = warpSum(s0), ip = warpSum(s1), bx = warpSum(s2);
    float A  = 1.0f - 2.0f*ip + xp2;
    float Bc = 1.0f - mu2;
    float den = fmaxf(1.0f - 2.0f*ip + mu2*xp2, EPSF);
    float nd2 = fmaxf(A*A*mu2 - 2.0f*A*Bc*ip + Bc*Bc*xp2, 0.f) / (den*den);
    float nd = sqrtf(fmaxf(nd2, EPSF));
    float cv = (2.0f/lam_mu) * atanhf(fminf(nd, CLIP1)) / nd;
    float uw = cv * (Bc*bx - A*bm) / den;
    float vw = cv * (A*mu2 - Bc*ip) / den;
    float av  = -uw*mu2 - vw - 2.0f*bm*vw;
    float bv2 = -vw*b2 + uw;
    float dgy = fmaxf(1.0f - 2.0f*bm + b2*mu2, EPSF);
    float fac = (lam_mu / lam_b) * rstd;
    float uc[8];
    float t0 = 0.f, t1 = 0.f;
#pragma unroll
    for (int i = 0; i < 8; i++) {
        float vc = cv * (Bc*xv[i] - A*mu8[i]) / den;
        uc[i] = (vc + 2.0f*(av*b8[i] - bv2*mu8[i]) / dgy) * fac;
        t0 += uc[i]*uc[i];
        t1 += b8[i]*uc[i];
    }
    float u2 = warpSum(t0), bu = warpSum(t1);
    float nu = sqrtf(fmaxf(u2, EPSF));
    float tf = tanhf(0.5f * lam_b * nu) / nu;
    float s2m = tf*tf*u2;
    float bs  = tf*bu;
    float A3 = 1.0f + 2.0f*bs + s2m, B3 = 1.0f - b2;
    float den3 = fmaxf(1.0f + 2.0f*bs + b2*s2m, EPSF);
#pragma unroll
    for (int i = 0; i < 8; i++) hc[i] = (A3*b8[i] + B3*tf*uc[i]) / den3;
    float nh2 = fmaxf(A3*A3*b2 + 2.0f*A3*B3*bs + B3*B3*s2m, 0.f) / (den3*den3);
    float nh = sqrtf(fmaxf(nh2, EPSF));
    if (nh > MAXN) {
        float q = MAXN / nh;
#pragma unroll
        for (int i = 0; i < 8; i++) hc[i] *= q;
        nh = MAXN;
    }
    return nh;
}

// ---------------- BN apply + hrelu + pre-for-conv2 (raw-y input) ----------------
__global__ void bnapply_w(const float* __restrict__ bias, float scale) {
    int wid = threadIdx.x >> 5, lid = threadIdx.x & 31;
    int p = blockIdx.x * 8 + wid;
    const float4* row = (const float4*)(g_h + (size_t)p*256 + lid*8);
    float4 a = row[0], cc = row[1];
    float xv[8] = {a.x,a.y,a.z,a.w,cc.x,cc.y,cc.z,cc.w};
    float qy = 0.f;
#pragma unroll
    for (int i = 0; i < 8; i++) qy += xv[i]*xv[i];
    float tot = warpSum(qy);
    float inv = 1.0f / (1.0f + sqrtf(1.0f + tot));
#pragma unroll
    for (int i = 0; i < 8; i++) xv[i] *= inv;
    float mu8[8], b8[8];
#pragma unroll
    for (int j = 0; j < 8; j++) { mu8[j] = g_mu[lid*8 + j]; b8[j] = bias[lid*8 + j]; }
    float hc[8];
    float nh = bn_point_w(xv, mu8, b8, hc);
    float lf = atanhf(fminf(nh, CLIP1)) / nh;
    float rc[8];
    float q = 0.f;
#pragma unroll
    for (int i = 0; i < 8; i++) { rc[i] = fmaxf(lf*hc[i], 0.f); q += rc[i]*rc[i]; }
    float rs = warpSum(q);
    float nr = sqrtf(fmaxf(rs, EPSF));
    float ef = tanhf(nr) / nr;
    float nhr = sqrtf(fmaxf(ef*ef*rs, EPSF));
    float adj = 1.0f;
    if (nhr > MAXN) { adj = MAXN/nhr; nhr = MAXN; }
    float f3 = atanhf(fminf(nhr, CLIP1)) / nhr * scale;
    float vv[8];
#pragma unroll
    for (int i = 0; i < 8; i++) vv[i] = f3 * ef * adj * rc[i];
    store_split8((size_t)p*256 + lid*8, vv);
    if (lid == 0) g_q2[p] = f3*f3*nhr*nhr;
}

// ---------------- BN2 apply + residual + hrelu + staged NCHW out ----------------
__global__ void final2_kernel(const float* __restrict__ bias, float* __restrict__ out) {
    __shared__ float so[256][33];
    int tid = threadIdx.x, lane = tid & 31, w8 = tid >> 5;
    int p0 = blockIdx.x * 32;
    int b = p0 >> 10, hw0 = p0 & 1023;
    float mu8[8], b8[8];
#pragma unroll
    for (int j = 0; j < 8; j++) { mu8[j] = g_mu[lane*8 + j]; b8[j] = bias[lane*8 + j]; }
#pragma unroll
    for (int pp = 0; pp < 4; pp++) {
        int pl = w8*4 + pp;
        int p = p0 + pl;
        const float4* row = (const float4*)(g_h + (size_t)p*256 + lane*8);
        float4 a = row[0], cc = row[1];
        float xv[8] = {a.x,a.y,a.z,a.w,cc.x,cc.y,cc.z,cc.w};
        float qy = 0.f;
#pragma unroll
        for (int i = 0; i < 8; i++) qy += xv[i]*xv[i];
        float tot = warpSum(qy);
        float inv = 1.0f / (1.0f + sqrtf(1.0f + tot));
#pragma unroll
        for (int i = 0; i < 8; i++) xv[i] *= inv;
        float hc[8];
        float nh = bn_point_w(xv, mu8, b8, hc);
        const float4* rrow = (const float4*)(g_xl + (size_t)p*256 + lane*8);
        float4 r0 = rrow[0], r1 = rrow[1];
        float res[8] = {r0.x,r0.y,r0.z,r0.w,r1.x,r1.y,r1.z,r1.w};
        float q1 = 0.f, q2 = 0.f;
#pragma unroll
        for (int i = 0; i < 8; i++) { q1 += res[i]*res[i]; q2 += hc[i]*res[i]; }
        float y2 = warpSum(q1), xy = warpSum(q2);
        float x2 = nh*nh;
        float A4 = 1.0f + 2.0f*xy + y2, B4 = 1.0f - x2;
        float den4 = fmaxf(1.0f + 2.0f*xy + x2*y2, EPSF);
        float hm[8];
#pragma unroll
        for (int i = 0; i < 8; i++) hm[i] = (A4*hc[i] + B4*res[i]) / den4;
        float nm2 = fmaxf(A4*A4*x2 + 2.0f*A4*B4*xy + B4*B4*y2, 0.f) / (den4*den4);
        float nmv = sqrtf(fmaxf(nm2, EPSF));
        float lf = atanhf(fminf(nmv, CLIP1)) / nmv;
        float rc[8];
        float q = 0.f;
#pragma unroll
        for (int i = 0; i < 8; i++) { rc[i] = fmaxf(lf*hm[i], 0.f); q += rc[i]*rc[i]; }
        float rs = warpSum(q);
        float nr = sqrtf(fmaxf(rs, EPSF));
        float ef = tanhf(nr) / nr;
        float nhr = sqrtf(fmaxf(ef*ef*rs, EPSF));
        float adj = (nhr > MAXN) ? MAXN/nhr : 1.0f;
#pragma unroll
        for (int i = 0; i < 8; i++) so[lane*8 + i][pl] = ef * adj * rc[i];
    }
    __syncthreads();
#pragma unroll 8
    for (int i = 0; i < 32; i++) {
        int c = i*8 + w8;
        out[(size_t)(b*256 + c)*1024 + hw0 + lane] = so[c][lane];
    }
}

// ---------------- launcher ----------------
extern "C" void kernel_launch(void* const* d_in, const int* in_sizes, int n_in,
                              void* d_out, int out_size) {
    const float* x  = (const float*)d_in[0];
    const float* z1 = (const float*)d_in[1];
    const float* z2 = (const float*)d_in[2];
    const float* w1 = (const float*)d_in[3];
    const float* b1 = (const float*)d_in[4];
    const float* w2 = (const float*)d_in[5];
    const float* b2 = (const float*)d_in[6];
    float* out = (float*)d_out;

    // scale = Beta(1152, 0.5) / Beta(128, 0.5)
    double lg = lgamma(1152.0) - lgamma(1152.5) - lgamma(128.0) + lgamma(128.5);
    float scale = (float)exp(lg);

    static int smem_set = 0;
    if (!smem_set) {
        cudaFuncSetAttribute(conv_mma, cudaFuncAttributeMaxDynamicSharedMemorySize, CONV_SMEM);
        smem_set = 1;
    }

    dim3 cgrid(128, 2);

    // conv_mma at launch index 3 -> captured by ncu
    zn_kernel<<<512, 64>>>(z1, z2);
    zsplit_kernel<<<dim3(72, 8, 2), dim3(32, 8)>>>(z1, z2);
    pre2_kernel<<<PNUM/32, 256>>>(x, scale);
    conv_mma<<<cgrid, 256, CONV_SMEM>>>(0);

    bnred_w<<<128, 256>>>();
    bnmu_kernel<<<1, 256>>>(b1);
    bnvar_w<<<128, 256>>>();
    bnfin_kernel<<<1, 128>>>(w1);
    bnapply_w<<<PNUM/8, 256>>>(b1, scale);

    conv_mma<<<cgrid, 256, CONV_SMEM>>>(1);
    xT_kernel<<<dim3(32, 8, 16), dim3(32, 8)>>>(x);

    bnred_w<<<128, 256>>>();
    bnmu_kernel<<<1, 256>>>(b2);
    bnvar_w<<<128, 256>>>();
    bnfin_kernel<<<1, 128>>>(w2);
    final2_kernel<<<PNUM/32, 256>>>(b2, out);
}

// round 7
// speedup vs baseline: 1.7354x; 1.6927x over previous
#include <cuda_runtime.h>
#include <cuda_bf16.h>
#include <math.h>
#include <stdint.h>

// Problem constants: B=16, C=256, H=W=32
#define PNUM 16384
#define CNUM 256
#define NKTOT 2304
#define CLIP1 0.9999999f
#define MAXN  0.99999f
#define EPSF  1e-15f

#define NPOS 36                  // Winograd F(4,3): 6x6 positions
#define NTIL 1024                // 16 images x 8x8 tiles of 4x4 outputs
#define STAGE_BYTES 32768u       // Ahi 8K + Alo 8K + Bhi 8K + Blo 8K
#define YST2  132
#define CONV_SMEM (3*32768)      // 96 KB -> 2 CTAs/SM

// ---------------- device scratch ----------------
__device__ __align__(16) float g_v [PNUM*CNUM];            // logmap0*scale (fp32)
__device__ __align__(16) __nv_bfloat16 g_Vhi[NPOS*NTIL*CNUM];
__device__ __align__(16) __nv_bfloat16 g_Vlo[NPOS*NTIL*CNUM];
__device__ __align__(16) __nv_bfloat16 g_uhi1[NPOS*CNUM*CNUM];
__device__ __align__(16) __nv_bfloat16 g_ulo1[NPOS*CNUM*CNUM];
__device__ __align__(16) __nv_bfloat16 g_uhi2[NPOS*CNUM*CNUM];
__device__ __align__(16) __nv_bfloat16 g_ulo2[NPOS*CNUM*CNUM];
__device__ __align__(16) float g_m [NPOS*NTIL*CNUM];       // GEMM out (per-position)
__device__ __align__(16) float g_h [PNUM*CNUM];            // RAW y
__device__ __align__(16) float g_xl[PNUM*CNUM];
__device__ float g_q2[PNUM];
__device__ float g_s [PNUM];
__device__ float g_zn[512];
__device__ float g_pm[128*CNUM];
__device__ float g_pd[128];
__device__ float g_pv[128];
__device__ float g_mu[CNUM];
__device__ float g_sc[8];

// ---------------- PTX helpers ----------------
__device__ __forceinline__ uint32_t smem_u32(const void* p) {
    uint32_t a;
    asm("{ .reg .u64 t; cvta.to.shared.u64 t, %1; cvt.u32.u64 %0, t; }" : "=r"(a) : "l"(p));
    return a;
}
__device__ __forceinline__ void cpa16(uint32_t dst, const void* src) {
    asm volatile("cp.async.cg.shared.global [%0], [%1], 16;" :: "r"(dst), "l"(src) : "memory");
}
__device__ __forceinline__ void cp_commit() {
    asm volatile("cp.async.commit_group;" ::: "memory");
}
template<int N>
__device__ __forceinline__ void cp_wait() {
    asm volatile("cp.async.wait_group %0;" :: "n"(N) : "memory");
}
__device__ __forceinline__ void ldsm4(uint32_t* r, uint32_t addr) {
    asm volatile("ldmatrix.sync.aligned.m8n8.x4.shared.b16 {%0,%1,%2,%3}, [%4];"
        : "=r"(r[0]), "=r"(r[1]), "=r"(r[2]), "=r"(r[3]) : "r"(addr));
}
__device__ __forceinline__ void mma16816(float* d, const uint32_t* a, const uint32_t* b) {
    asm volatile("mma.sync.aligned.m16n8k16.row.col.f32.bf16.bf16.f32 "
        "{%0,%1,%2,%3}, {%4,%5,%6,%7}, {%8,%9}, {%0,%1,%2,%3};"
        : "+f"(d[0]), "+f"(d[1]), "+f"(d[2]), "+f"(d[3])
        : "r"(a[0]), "r"(a[1]), "r"(a[2]), "r"(a[3]), "r"(b[0]), "r"(b[1]));
}
__device__ __forceinline__ uint32_t swz(int r, int c) {
    return (uint32_t)(((r >> 1) << 7) | (((((r & 1) << 2) | c) ^ ((r >> 1) & 7)) << 4));
}

// ---------------- reductions ----------------
__device__ __forceinline__ float warpSum(float v) {
#pragma unroll
    for (int o = 16; o > 0; o >>= 1) v += __shfl_xor_sync(0xffffffffu, v, o);
    return v;
}
template<int K>
__device__ __forceinline__ void blockReduceK(float* v, float* sbuf) {
    int tid = threadIdx.x, lane = tid & 31, wid = tid >> 5;
#pragma unroll
    for (int i = 0; i < K; i++) {
        float x = v[i];
#pragma unroll
        for (int o = 16; o > 0; o >>= 1) x += __shfl_down_sync(0xffffffffu, x, o);
        if (lane == 0) sbuf[i*8 + wid] = x;
    }
    __syncthreads();
    if (tid == 0) {
#pragma unroll
        for (int i = 0; i < K; i++) {
            float s = sbuf[i*8];
            for (int w = 1; w < 8; w++) s += sbuf[i*8 + w];
            sbuf[i*8] = s;
        }
    }
    __syncthreads();
#pragma unroll
    for (int i = 0; i < K; i++) v[i] = sbuf[i*8];
    __syncthreads();
}

// ---------------- Winograd 6-point input/data transform (BT rows) ----------------
__device__ __forceinline__ void bt6(const float* in, float* out) {
    out[0] =  4.f*in[0] - 5.f*in[2] + in[4];
    out[1] = -4.f*in[1] - 4.f*in[2] + in[3] + in[4];
    out[2] =  4.f*in[1] - 4.f*in[2] - in[3] + in[4];
    out[3] = -2.f*in[1] -     in[2] + 2.f*in[3] + in[4];
    out[4] =  2.f*in[1] -     in[2] - 2.f*in[3] + in[4];
    out[5] =  4.f*in[1] - 5.f*in[3] + in[5];
}
// G transform: 3 -> 6
__device__ __forceinline__ void g6(const float* in, float* out) {
    out[0] = 0.25f*in[0];
    out[1] = -(in[0] + in[1] + in[2]) * (1.f/6.f);
    out[2] = (-in[0] + in[1] - in[2]) * (1.f/6.f);
    out[3] = in[0]*(1.f/24.f) + in[1]*(1.f/12.f) + in[2]*(1.f/6.f);
    out[4] = in[0]*(1.f/24.f) - in[1]*(1.f/12.f) + in[2]*(1.f/6.f);
    out[5] = in[2];
}
// AT transform: 6 -> 4
__device__ __forceinline__ void at6(const float* in, float* out) {
    out[0] = in[0] + in[1] + in[2] + in[3] + in[4];
    out[1] = in[1] - in[2] + 2.f*(in[3] - in[4]);
    out[2] = in[1] + in[2] + 4.f*(in[3] + in[4]);
    out[3] = in[1] - in[2] + 8.f*(in[3] - in[4]) + in[5];
}

// ---------------- z column norms ----------------
__global__ void zn_kernel(const float* __restrict__ z1, const float* __restrict__ z2) {
    int col = blockIdx.x;
    const float* z = (col < 256) ? z1 : z2;
    int j = col & 255;
    float s = 0.f;
    for (int k = threadIdx.x; k < NKTOT; k += 64) {
        float w = z[k*256 + j];
        s += w*w;
    }
#pragma unroll
    for (int o = 16; o > 0; o >>= 1) s += __shfl_down_sync(0xffffffffu, s, o);
    __shared__ float sb[2];
    if ((threadIdx.x & 31) == 0) sb[threadIdx.x >> 5] = s;
    __syncthreads();
    if (threadIdx.x == 0) g_zn[col] = sqrtf(fmaxf(sb[0] + sb[1], EPSF));
}

// ---------------- U = G z G^T, split bf16, layout [pos][co][ci] ----------------
__global__ void wino_u(const float* __restrict__ z1, const float* __restrict__ z2) {
    const float* z = blockIdx.y ? z2 : z1;
    __nv_bfloat16* uh = blockIdx.y ? g_uhi2 : g_uhi1;
    __nv_bfloat16* ul = blockIdx.y ? g_ulo2 : g_ulo1;
    int co = blockIdx.x, ci = threadIdx.x;
    float g[3][3];
#pragma unroll
    for (int i = 0; i < 3; i++)
#pragma unroll
        for (int j = 0; j < 3; j++)
            g[i][j] = z[(size_t)((i*3 + j)*256 + ci)*256 + co];
    float t[6][3];
#pragma unroll
    for (int j = 0; j < 3; j++) {
        float in[3] = { g[0][j], g[1][j], g[2][j] };
        float out[6];
        g6(in, out);
#pragma unroll
        for (int a = 0; a < 6; a++) t[a][j] = out[a];
    }
#pragma unroll
    for (int a = 0; a < 6; a++) {
        float out[6];
        g6(t[a], out);
#pragma unroll
        for (int b = 0; b < 6; b++) {
            float u = out[b];
            __nv_bfloat16 hi = __float2bfloat16(u);
            size_t idx = ((size_t)((a*6 + b)*256 + co))*256 + ci;
            uh[idx] = hi;
            ul[idx] = __float2bfloat16(u - __bfloat162float(hi));
        }
    }
}

// ---------------- V = B^T d B per tile, split bf16, layout [pos][tile][ci] ----------------
__global__ void wino_in() {
    int t = blockIdx.x, ci = threadIdx.x;
    int b = t >> 6, tr = (t >> 3) & 7, tc = t & 7;
    int base = b << 10;
    float d[6][6];
#pragma unroll
    for (int y = 0; y < 6; y++) {
        int iy = 4*tr - 1 + y;
#pragma unroll
        for (int x = 0; x < 6; x++) {
            int ix = 4*tc - 1 + x;
            bool ok = ((unsigned)iy < 32u) && ((unsigned)ix < 32u);
            d[y][x] = ok ? g_v[(size_t)(base + iy*32 + ix)*256 + ci] : 0.f;
        }
    }
    float e[6][6];
#pragma unroll
    for (int x = 0; x < 6; x++) {
        float in[6] = { d[0][x], d[1][x], d[2][x], d[3][x], d[4][x], d[5][x] };
        float out[6];
        bt6(in, out);
#pragma unroll
        for (int a = 0; a < 6; a++) e[a][x] = out[a];
    }
#pragma unroll
    for (int a = 0; a < 6; a++) {
        float out[6];
        bt6(e[a], out);
#pragma unroll
        for (int bb = 0; bb < 6; bb++) {
            float v = out[bb];
            __nv_bfloat16 hi = __float2bfloat16(v);
            size_t idx = ((size_t)((a*6 + bb)*NTIL + t))*256 + ci;
            g_Vhi[idx] = hi;
            g_Vlo[idx] = __float2bfloat16(v - __bfloat162float(hi));
        }
    }
}

// ---------------- batched Winograd GEMM: M[pos] = V[pos] @ U[pos]^T ----------------
// grid (8 mtiles, 2 nhalf, 36 pos). 256 thr = 8 warps (4m x 2n), warp 32x64,
// split-3 bf16, BK=32, K=256 (8 chunks), 3-stage. Raw fp32 out to g_m.
__global__ void __launch_bounds__(256, 2) wino_gemm(int which) {
    extern __shared__ __align__(16) char dsm[];
    uint32_t sbase = smem_u32(dsm);

    const __nv_bfloat16* Bh = which ? g_uhi2 : g_uhi1;
    const __nv_bfloat16* Bl = which ? g_ulo2 : g_ulo1;
    int t0  = blockIdx.x << 7;
    int nh  = blockIdx.y;
    int pos = blockIdx.z;

    int tid = threadIdx.x, wid = tid >> 5, l = tid & 31;

    // loader precompute: rows r0, r0+64 for A and B
    int c4 = tid & 3;
    int r0 = tid >> 2;
    uint32_t ph0 = swz(r0, c4), ph1 = swz(r0 + 64, c4);
    const __nv_bfloat16* Abase_hi = g_Vhi + ((size_t)pos*NTIL + t0)*256;
    const __nv_bfloat16* Abase_lo = g_Vlo + ((size_t)pos*NTIL + t0)*256;
    const __nv_bfloat16* Bbase_hi = Bh + ((size_t)pos*256 + nh*128)*256;
    const __nv_bfloat16* Bbase_lo = Bl + ((size_t)pos*256 + nh*128)*256;
    size_t a0 = (size_t)r0*256 + c4*8, a1 = (size_t)(r0 + 64)*256 + c4*8;

    // mma lane precompute
    int m0 = (wid & 3) << 5;
    int n0w = (wid >> 2) << 6;
    int mi = l >> 3;
    int rA = m0 + ((mi & 1) << 3) + (l & 7);
    uint32_t qA0 = swz(rA, mi >> 1);
    int rB = n0w + (((mi >> 1) & 1) << 3) + (l & 7);
    uint32_t qB0 = swz(rB, mi & 1);

    float acc[2][8][4];
#pragma unroll
    for (int i = 0; i < 2; i++)
#pragma unroll
        for (int j = 0; j < 8; j++)
#pragma unroll
            for (int k = 0; k < 4; k++) acc[i][j][k] = 0.f;

    auto load_chunk = [&](int kc, int stage) {
        size_t coff = (size_t)(kc << 5);
        uint32_t st = sbase + (uint32_t)stage*STAGE_BYTES;
        cpa16(st + ph0,         Abase_hi + a0 + coff);
        cpa16(st + 8192 + ph0,  Abase_lo + a0 + coff);
        cpa16(st + ph1,         Abase_hi + a1 + coff);
        cpa16(st + 8192 + ph1,  Abase_lo + a1 + coff);
        cpa16(st + 16384 + ph0, Bbase_hi + a0 + coff);
        cpa16(st + 24576 + ph0, Bbase_lo + a0 + coff);
        cpa16(st + 16384 + ph1, Bbase_hi + a1 + coff);
        cpa16(st + 24576 + ph1, Bbase_lo + a1 + coff);
        cp_commit();
    };

    load_chunk(0, 0);
    load_chunk(1, 1);

    for (int kc = 0; kc < 8; kc++) {
        int stage = kc % 3;
        if (kc < 6) cp_wait<1>(); else cp_wait<0>();
        __syncthreads();
        if (kc + 2 < 8) load_chunk(kc + 2, (kc + 2) % 3);

        uint32_t st = sbase + (uint32_t)stage*STAGE_BYTES;
        uint32_t Ahi = st, Alo = st + 8192, Bhi = st + 16384, Blo = st + 24576;
#pragma unroll
        for (int ks = 0; ks < 2; ks++) {
            uint32_t kx = (uint32_t)(ks << 5);
            uint32_t qa = qA0 ^ kx, qb = qB0 ^ kx;
            uint32_t ah[8], al[8], bbv[16];
            ldsm4(ah,     Ahi + qa);
            ldsm4(ah + 4, Ahi + qa + 1024);
            ldsm4(al,     Alo + qa);
            ldsm4(al + 4, Alo + qa + 1024);
#pragma unroll
            for (int j = 0; j < 4; j++) ldsm4(bbv + j*4, Bhi + qb + j*1024);
#pragma unroll
            for (int nf = 0; nf < 8; nf++) {
                const uint32_t* bp = bbv + nf*2;
                mma16816(acc[0][nf], ah,     bp);
                mma16816(acc[1][nf], ah + 4, bp);
                mma16816(acc[0][nf], al,     bp);
                mma16816(acc[1][nf], al + 4, bp);
            }
#pragma unroll
            for (int j = 0; j < 4; j++) ldsm4(bbv + j*4, Blo + qb + j*1024);
#pragma unroll
            for (int nf = 0; nf < 8; nf++) {
                const uint32_t* bp = bbv + nf*2;
                mma16816(acc[0][nf], ah,     bp);
                mma16816(acc[1][nf], ah + 4, bp);
            }
        }
    }
    __syncthreads();

    // stage raw fp32 through smem, then coalesced write to g_m
    float* ybuf = (float*)dsm;
    int row0 = m0 + (l >> 2);
    int col0 = n0w + ((l & 3) << 1);
#pragma unroll
    for (int mf = 0; mf < 2; mf++)
#pragma unroll
        for (int nf = 0; nf < 8; nf++)
#pragma unroll
            for (int hf = 0; hf < 2; hf++) {
                int r = row0 + mf*16 + hf*8;
                *(float2*)&ybuf[r*YST2 + col0 + nf*8] =
                    make_float2(acc[mf][nf][hf*2], acc[mf][nf][hf*2 + 1]);
            }
    __syncthreads();
    {
        int row = tid >> 1, q = tid & 1;
        const float4* yr = (const float4*)(ybuf + row*YST2 + q*64);
        float4* dst = (float4*)(g_m + ((size_t)pos*NTIL + t0 + row)*256 + nh*128 + q*64);
#pragma unroll
        for (int i = 0; i < 16; i++) dst[i] = yr[i];
    }
}

// ---------------- pre2: coalesced x read -> g_v fp32 + q2 ----------------
__global__ void pre2_kernel(const float* __restrict__ x, float scale) {
    __shared__ float sx[256][33];
    int tid = threadIdx.x, lane = tid & 31, w8 = tid >> 5;
    int p0 = blockIdx.x * 32;
    int b = p0 >> 10, hw0 = p0 & 1023;
#pragma unroll 8
    for (int i = 0; i < 32; i++) {
        int c = i*8 + w8;
        sx[c][lane] = x[(size_t)(b*256 + c)*1024 + hw0 + lane];
    }
    __syncthreads();
#pragma unroll
    for (int pp = 0; pp < 4; pp++) {
        int pl = w8*4 + pp;
        int p = p0 + pl;
        float xv[8];
#pragma unroll
        for (int i = 0; i < 8; i++) xv[i] = sx[lane*8 + i][pl];
        float q = 0.f;
#pragma unroll
        for (int i = 0; i < 8; i++) q += xv[i]*xv[i];
        float n2 = warpSum(q);
        float n = sqrtf(fmaxf(n2, EPSF));
        float f = atanhf(fminf(n, CLIP1)) / n * scale;
        float4 o0 = make_float4(f*xv[0], f*xv[1], f*xv[2], f*xv[3]);
        float4 o1 = make_float4(f*xv[4], f*xv[5], f*xv[6], f*xv[7]);
        float* dst = g_v + (size_t)p*256 + lane*8;
        *(float4*)dst = o0;
        *(float4*)(dst + 4) = o1;
        if (lane == 0) g_q2[p] = f*f*n2;
    }
}

// ---------------- per-pixel s = lam*alpha from 3x3 q2 sums ----------------
__global__ void s_kernel() {
    int p = blockIdx.x*256 + threadIdx.x;
    int h = (p >> 5) & 31, w = p & 31;
    float np2 = 0.f;
#pragma unroll
    for (int dy = -1; dy <= 1; dy++)
#pragma unroll
        for (int dx = -1; dx <= 1; dx++) {
            int sh = h + dy, sw = w + dx;
            if ((unsigned)sh < 32u && (unsigned)sw < 32u) np2 += g_q2[p + dy*32 + dx];
        }
    float np = sqrtf(fmaxf(np2, EPSF));
    float th = tanhf(np);
    float uf = th / np;
    float un = th;
    if (un > MAXN) { uf *= MAXN/un; un = MAXN; }
    float lam = 2.0f / fmaxf(1.0f - un*un, EPSF);
    g_s[p] = lam * uf;
}

// ---------------- output transform + FC epilogue -> raw y in g_h ----------------
__global__ void wino_out(int znoff) {
    int t = blockIdx.x, co = threadIdx.x;
    int b = t >> 6, tr = (t >> 3) & 7, tc = t & 7;
    float m[36];
#pragma unroll
    for (int pos = 0; pos < 36; pos++)
        m[pos] = g_m[((size_t)pos*NTIL + t)*256 + co];
    float Z[4][6];
#pragma unroll
    for (int bb = 0; bb < 6; bb++) {
        float in[6] = { m[bb], m[6+bb], m[12+bb], m[18+bb], m[24+bb], m[30+bb] };
        float out[4];
        at6(in, out);
#pragma unroll
        for (int r = 0; r < 4; r++) Z[r][bb] = out[r];
    }
    float zn = g_zn[znoff + co];
    int prow = (b << 10) + (4*tr)*32 + 4*tc;
#pragma unroll
    for (int r = 0; r < 4; r++) {
        float Y[4];
        at6(Z[r], Y);
#pragma unroll
        for (int c = 0; c < 4; c++) {
            int p = prow + r*32 + c;
            float s = g_s[p];
            float tt = Y[c] * s / zn;
            float y = sinhf(2.0f * zn * asinhf(tt));
            g_h[(size_t)p*256 + co] = y;
        }
    }
}

// ---------------- xT: x NCHW -> g_xl [p][c] ----------------
__global__ void xT_kernel(const float* __restrict__ x) {
    __shared__ float t[32][33];
    int hw0 = blockIdx.x * 32, c0 = blockIdx.y * 32, b = blockIdx.z;
    int tx = threadIdx.x, ty = threadIdx.y;
#pragma unroll
    for (int i = 0; i < 4; i++)
        t[ty + i*8][tx] = x[(size_t)(b*256 + c0 + ty + i*8)*1024 + hw0 + tx];
    __syncthreads();
#pragma unroll
    for (int i = 0; i < 4; i++)
        g_xl[(size_t)(b*1024 + hw0 + ty + i*8)*256 + c0 + tx] = t[tx][ty + i*8];
}

// ---------------- BN phase 1 (raw-y input) ----------------
__global__ void bnred_w() {
    __shared__ float sm[8][256];
    __shared__ float sd[8];
    int wid = threadIdx.x >> 5, lid = threadIdx.x & 31;
    int p0 = blockIdx.x * 128;
    float accm[8] = {0,0,0,0,0,0,0,0};
    float accd = 0.f;
    for (int i = 0; i < 16; i++) {
        int p = p0 + wid*16 + i;
        const float4* row = (const float4*)(g_h + (size_t)p*256 + lid*8);
        float4 a = row[0], c = row[1];
        float v[8] = {a.x,a.y,a.z,a.w,c.x,c.y,c.z,c.w};
        float q = 0.f;
#pragma unroll
        for (int j = 0; j < 8; j++) q += v[j]*v[j];
        float tot = warpSum(q);
        float inv = 1.0f / (1.0f + sqrtf(1.0f + tot));
        float n2 = tot*inv*inv;
        float lam = 2.0f / fmaxf(1.0f - n2, EPSF);
        float li = lam * inv;
#pragma unroll
        for (int j = 0; j < 8; j++) accm[j] += li * v[j];
        accd += lam - 1.0f;
    }
#pragma unroll
    for (int j = 0; j < 8; j++) sm[wid][lid*8 + j] = accm[j];
    if (lid == 0) sd[wid] = accd;
    __syncthreads();
    int c = threadIdx.x;
    float s = 0.f;
    for (int w = 0; w < 8; w++) s += sm[w][c];
    g_pm[blockIdx.x*256 + c] = s;
    if (c == 0) {
        float d = 0.f;
        for (int w = 0; w < 8; w++) d += sd[w];
        g_pd[blockIdx.x] = d;
    }
}

// ---------------- BN phase 2 ----------------
__global__ void bnmu_kernel(const float* __restrict__ bias) {
    __shared__ float sb[24];
    int c = threadIdx.x;
    float msum = 0.f;
    for (int g = 0; g < 128; g++) msum += g_pm[g*256 + c];
    float dv = (c < 128) ? g_pd[c] : 0.f;
    float r1[1] = { dv };
    blockReduceK<1>(r1, sb);
    float den = fmaxf(r1[0], EPSF);
    float m = msum / den;
    float r2[1] = { m*m };
    blockReduceK<1>(r2, sb);
    float nm = sqrtf(fmaxf(r2[0], EPSF));
    float fac = tanhf(0.5f * atanhf(fminf(nm, CLIP1))) / nm;
    float muc = fac * m;
    g_mu[c] = muc;
    float bc = bias[c];
    float r3[3] = { muc*muc, bc*bc, bc*muc };
    blockReduceK<3>(r3, sb);
    if (c == 0) {
        float mu2 = r3[0], b2 = r3[1], bm = r3[2];
        g_sc[0] = mu2;
        g_sc[1] = 2.0f / fmaxf(1.0f - mu2, EPSF);
        g_sc[2] = b2;
        g_sc[3] = 2.0f / fmaxf(1.0f - b2, EPSF);
        g_sc[4] = bm;
    }
}

// ---------------- BN phase 3 (raw-y input) ----------------
__global__ void bnvar_w() {
    __shared__ float sv[8];
    int wid = threadIdx.x >> 5, lid = threadIdx.x & 31;
    int p0 = blockIdx.x * 128;
    float mu8[8];
#pragma unroll
    for (int j = 0; j < 8; j++) mu8[j] = g_mu[lid*8 + j];
    float mu2 = g_sc[0];
    float acc = 0.f;
    for (int i = 0; i < 16; i++) {
        int p = p0 + wid*16 + i;
        const float4* row = (const float4*)(g_h + (size_t)p*256 + lid*8);
        float4 a = row[0], cc = row[1];
        float v[8] = {a.x,a.y,a.z,a.w,cc.x,cc.y,cc.z,cc.w};
        float q1 = 0.f, q2 = 0.f;
#pragma unroll
        for (int j = 0; j < 8; j++) { q1 += v[j]*v[j]; q2 += v[j]*mu8[j]; }
        float tot = warpSum(q1);
        float ipr = warpSum(q2);
        float inv = 1.0f / (1.0f + sqrtf(1.0f + tot));
        float xp2 = tot*inv*inv;
        float ip  = ipr*inv;
        float A = 1.0f - 2.0f*ip + mu2;
        float B = 1.0f - xp2;
        float nn = fmaxf(A*A*xp2 - 2.0f*A*B*ip + B*B*mu2, 0.f);
        float den = fmaxf(1.0f - 2.0f*ip + xp2*mu2, EPSF);
        float nr = sqrtf(fmaxf(nn/(den*den), EPSF));
        float dd = 2.0f * atanhf(fminf(nr, CLIP1));
        acc += dd*dd;
    }
    if (lid == 0) sv[wid] = acc;
    __syncthreads();
    if (threadIdx.x == 0) {
        float s = 0.f;
        for (int w = 0; w < 8; w++) s += sv[w];
        g_pv[blockIdx.x] = s;
    }
}

// ---------------- BN phase 4 ----------------
__global__ void bnfin_kernel(const float* __restrict__ weight) {
    int tid = threadIdx.x;
    float v = g_pv[tid];
#pragma unroll
    for (int o = 16; o > 0; o >>= 1) v += __shfl_down_sync(0xffffffffu, v, o);
    __shared__ float sb[4];
    if ((tid & 31) == 0) sb[tid >> 5] = v;
    __syncthreads();
    if (tid == 0) {
        float var = (sb[0] + sb[1] + sb[2] + sb[3]) / 16384.0f;
        g_sc[5] = sqrtf(weight[0] / fmaxf(var, EPSF));
    }
}

// ---------------- shared BN point transform ----------------
__device__ __forceinline__ float bn_point_w(const float* xv, const float* mu8, const float* b8,
                                            float* hc) {
    float mu2 = g_sc[0], lam_mu = g_sc[1], b2 = g_sc[2], lam_b = g_sc[3],
          bm = g_sc[4], rstd = g_sc[5];
    float s0 = 0.f, s1 = 0.f, s2 = 0.f;
#pragma unroll
    for (int i = 0; i < 8; i++) { s0 += xv[i]*xv[i]; s1 += mu8[i]*xv[i]; s2 += b8[i]*xv[i]; }
    float xp2 = warpSum(s0), ip = warpSum(s1), bx = warpSum(s2);
    float A  = 1.0f - 2.0f*ip + xp2;
    float Bc = 1.0f - mu2;
    float den = fmaxf(1.0f - 2.0f*ip + mu2*xp2, EPSF);
    float nd2 = fmaxf(A*A*mu2 - 2.0f*A*Bc*ip + Bc*Bc*xp2, 0.f) / (den*den);
    float nd = sqrtf(fmaxf(nd2, EPSF));
    float cv = (2.0f/lam_mu) * atanhf(fminf(nd, CLIP1)) / nd;
    float uw = cv * (Bc*bx - A*bm) / den;
    float vw = cv * (A*mu2 - Bc*ip) / den;
    float av  = -uw*mu2 - vw - 2.0f*bm*vw;
    float bv2 = -vw*b2 + uw;
    float dgy = fmaxf(1.0f - 2.0f*bm + b2*mu2, EPSF);
    float fac = (lam_mu / lam_b) * rstd;
    float uc[8];
    float t0 = 0.f, t1 = 0.f;
#pragma unroll
    for (int i = 0; i < 8; i++) {
        float vc = cv * (Bc*xv[i] - A*mu8[i]) / den;
        uc[i] = (vc + 2.0f*(av*b8[i] - bv2*mu8[i]) / dgy) * fac;
        t0 += uc[i]*uc[i];
        t1 += b8[i]*uc[i];
    }
    float u2 = warpSum(t0), bu = warpSum(t1);
    float nu = sqrtf(fmaxf(u2, EPSF));
    float tf = tanhf(0.5f * lam_b * nu) / nu;
    float s2m = tf*tf*u2;
    float bs  = tf*bu;
    float A3 = 1.0f + 2.0f*bs + s2m, B3 = 1.0f - b2;
    float den3 = fmaxf(1.0f + 2.0f*bs + b2*s2m, EPSF);
#pragma unroll
    for (int i = 0; i < 8; i++) hc[i] = (A3*b8[i] + B3*tf*uc[i]) / den3;
    float nh2 = fmaxf(A3*A3*b2 + 2.0f*A3*B3*bs + B3*B3*s2m, 0.f) / (den3*den3);
    float nh = sqrtf(fmaxf(nh2, EPSF));
    if (nh > MAXN) {
        float q = MAXN / nh;
#pragma unroll
        for (int i = 0; i < 8; i++) hc[i] *= q;
        nh = MAXN;
    }
    return nh;
}

// ---------------- BN apply + hrelu + pre-for-conv2 (writes g_v fp32) ----------------
__global__ void bnapply_w(const float* __restrict__ bias, float scale) {
    int wid = threadIdx.x >> 5, lid = threadIdx.x & 31;
    int p = blockIdx.x * 8 + wid;
    const float4* row = (const float4*)(g_h + (size_t)p*256 + lid*8);
    float4 a = row[0], cc = row[1];
    float xv[8] = {a.x,a.y,a.z,a.w,cc.x,cc.y,cc.z,cc.w};
    float qy = 0.f;
#pragma unroll
    for (int i = 0; i < 8; i++) qy += xv[i]*xv[i];
    float tot = warpSum(qy);
    float inv = 1.0f / (1.0f + sqrtf(1.0f + tot));
#pragma unroll
    for (int i = 0; i < 8; i++) xv[i] *= inv;
    float mu8[8], b8[8];
#pragma unroll
    for (int j = 0; j < 8; j++) { mu8[j] = g_mu[lid*8 + j]; b8[j] = bias[lid*8 + j]; }
    float hc[8];
    float nh = bn_point_w(xv, mu8, b8, hc);
    float lf = atanhf(fminf(nh, CLIP1)) / nh;
    float rc[8];
    float q = 0.f;
#pragma unroll
    for (int i = 0; i < 8; i++) { rc[i] = fmaxf(lf*hc[i], 0.f); q += rc[i]*rc[i]; }
    float rs = warpSum(q);
    float nr = sqrtf(fmaxf(rs, EPSF));
    float ef = tanhf(nr) / nr;
    float nhr = sqrtf(fmaxf(ef*ef*rs, EPSF));
    float adj = 1.0f;
    if (nhr > MAXN) { adj = MAXN/nhr; nhr = MAXN; }
    float f3 = atanhf(fminf(nhr, CLIP1)) / nhr * scale;
    float g = f3 * ef * adj;
    float4 o0 = make_float4(g*rc[0], g*rc[1], g*rc[2], g*rc[3]);
    float4 o1 = make_float4(g*rc[4], g*rc[5], g*rc[6], g*rc[7]);
    float* dst = g_v + (size_t)p*256 + lid*8;
    *(float4*)dst = o0;
    *(float4*)(dst + 4) = o1;
    if (lid == 0) g_q2[p] = f3*f3*nhr*nhr;
}

// ---------------- BN2 apply + residual + hrelu + staged NCHW out ----------------
__global__ void final2_kernel(const float* __restrict__ bias, float* __restrict__ out) {
    __shared__ float so[256][33];
    int tid = threadIdx.x, lane = tid & 31, w8 = tid >> 5;
    int p0 = blockIdx.x * 32;
    int b = p0 >> 10, hw0 = p0 & 1023;
    float mu8[8], b8[8];
#pragma unroll
    for (int j = 0; j < 8; j++) { mu8[j] = g_mu[lane*8 + j]; b8[j] = bias[lane*8 + j]; }
#pragma unroll
    for (int pp = 0; pp < 4; pp++) {
        int pl = w8*4 + pp;
        int p = p0 + pl;
        const float4* row = (const float4*)(g_h + (size_t)p*256 + lane*8);
        float4 a = row[0], cc = row[1];
        float xv[8] = {a.x,a.y,a.z,a.w,cc.x,cc.y,cc.z,cc.w};
        float qy = 0.f;
#pragma unroll
        for (int i = 0; i < 8; i++) qy += xv[i]*xv[i];
        float tot = warpSum(qy);
        float inv = 1.0f / (1.0f + sqrtf(1.0f + tot));
#pragma unroll
        for (int i = 0; i < 8; i++) xv[i] *= inv;
        float hc[8];
        float nh = bn_point_w(xv, mu8, b8, hc);
        const float4* rrow = (const float4*)(g_xl + (size_t)p*256 + lane*8);
        float4 r0 = rrow[0], r1 = rrow[1];
        float res[8] = {r0.x,r0.y,r0.z,r0.w,r1.x,r1.y,r1.z,r1.w};
        float q1 = 0.f, q2 = 0.f;
#pragma unroll
        for (int i = 0; i < 8; i++) { q1 += res[i]*res[i]; q2 += hc[i]*res[i]; }
        float y2 = warpSum(q1), xy = warpSum(q2);
        float x2 = nh*nh;
        float A4 = 1.0f + 2.0f*xy + y2, B4 = 1.0f - x2;
        float den4 = fmaxf(1.0f + 2.0f*xy + x2*y2, EPSF);
        float hm[8];
#pragma unroll
        for (int i = 0; i < 8; i++) hm[i] = (A4*hc[i] + B4*res[i]) / den4;
        float nm2 = fmaxf(A4*A4*x2 + 2.0f*A4*B4*xy + B4*B4*y2, 0.f) / (den4*den4);
        float nmv = sqrtf(fmaxf(nm2, EPSF));
        float lf = atanhf(fminf(nmv, CLIP1)) / nmv;
        float rc[8];
        float q = 0.f;
#pragma unroll
        for (int i = 0; i < 8; i++) { rc[i] = fmaxf(lf*hm[i], 0.f); q += rc[i]*rc[i]; }
        float rs = warpSum(q);
        float nr = sqrtf(fmaxf(rs, EPSF));
        float ef = tanhf(nr) / nr;
        float nhr = sqrtf(fmaxf(ef*ef*rs, EPSF));
        float adj = (nhr > MAXN) ? MAXN/nhr : 1.0f;
#pragma unroll
        for (int i = 0; i < 8; i++) so[lane*8 + i][pl] = ef * adj * rc[i];
    }
    __syncthreads();
#pragma unroll 8
    for (int i = 0; i < 32; i++) {
        int c = i*8 + w8;
        out[(size_t)(b*256 + c)*1024 + hw0 + lane] = so[c][lane];
    }
}

// ---------------- launcher ----------------
extern "C" void kernel_launch(void* const* d_in, const int* in_sizes, int n_in,
                              void* d_out, int out_size) {
    const float* x  = (const float*)d_in[0];
    const float* z1 = (const float*)d_in[1];
    const float* z2 = (const float*)d_in[2];
    const float* w1 = (const float*)d_in[3];
    const float* b1 = (const float*)d_in[4];
    const float* w2 = (const float*)d_in[5];
    const float* b2 = (const float*)d_in[6];
    float* out = (float*)d_out;

    // scale = Beta(1152, 0.5) / Beta(128, 0.5)
    double lg = lgamma(1152.0) - lgamma(1152.5) - lgamma(128.0) + lgamma(128.5);
    float scale = (float)exp(lg);

    static int smem_set = 0;
    if (!smem_set) {
        cudaFuncSetAttribute(wino_gemm, cudaFuncAttributeMaxDynamicSharedMemorySize, CONV_SMEM);
        smem_set = 1;
    }

    dim3 ggrid(8, 2, 36);

    pre2_kernel<<<PNUM/32, 256>>>(x, scale);     // 0
    wino_u<<<dim3(256, 2), 256>>>(z1, z2);       // 1
    wino_in<<<NTIL, 256>>>();                    // 2
    wino_gemm<<<ggrid, 256, CONV_SMEM>>>(0);     // 3  <- ncu capture target
    zn_kernel<<<512, 64>>>(z1, z2);
    s_kernel<<<64, 256>>>();
    wino_out<<<NTIL, 256>>>(0);

    bnred_w<<<128, 256>>>();
    bnmu_kernel<<<1, 256>>>(b1);
    bnvar_w<<<128, 256>>>();
    bnfin_kernel<<<1, 128>>>(w1);
    bnapply_w<<<PNUM/8, 256>>>(b1, scale);

    wino_in<<<NTIL, 256>>>();
    wino_gemm<<<ggrid, 256, CONV_SMEM>>>(1);
    s_kernel<<<64, 256>>>();
    wino_out<<<NTIL, 256>>>(256);
    xT_kernel<<<dim3(32, 8, 16), dim3(32, 8)>>>(x);

    bnred_w<<<128, 256>>>();
    bnmu_kernel<<<1, 256>>>(b2);
    bnvar_w<<<128, 256>>>();
    bnfin_kernel<<<1, 128>>>(w2);
    final2_kernel<<<PNUM/32, 256>>>(b2, out);
}

// round 8
// speedup vs baseline: 1.8263x; 1.0524x over previous
#include <cuda_runtime.h>
#include <cuda_bf16.h>
#include <math.h>
#include <stdint.h>

// Problem constants: B=16, C=256, H=W=32
#define PNUM 16384
#define CNUM 256
#define NKTOT 2304
#define CLIP1 0.9999999f
#define MAXN  0.99999f
#define EPSF  1e-15f

#define NPOS 36                  // Winograd F(4,3): 6x6 positions
#define NTIL 1024                // 16 images x 8x8 tiles of 4x4 outputs
#define STAGE_BYTES 32768u       // Ahi 8K + Alo 8K + Bhi 8K + Blo 8K
#define YST2  132
#define CONV_SMEM (3*32768)      // 96 KB -> 2 CTAs/SM

// ---------------- device scratch ----------------
__device__ __align__(16) float g_v [PNUM*CNUM];            // logmap0*scale (fp32)
__device__ __align__(16) __nv_bfloat16 g_Vhi[NPOS*NTIL*CNUM];
__device__ __align__(16) __nv_bfloat16 g_Vlo[NPOS*NTIL*CNUM];
__device__ __align__(16) __nv_bfloat16 g_uhi1[NPOS*CNUM*CNUM];
__device__ __align__(16) __nv_bfloat16 g_ulo1[NPOS*CNUM*CNUM];
__device__ __align__(16) __nv_bfloat16 g_uhi2[NPOS*CNUM*CNUM];
__device__ __align__(16) __nv_bfloat16 g_ulo2[NPOS*CNUM*CNUM];
__device__ __align__(16) float g_m [NPOS*NTIL*CNUM];       // GEMM out (per-position)
__device__ __align__(16) float g_h [PNUM*CNUM];            // RAW y
__device__ __align__(16) float g_xl[PNUM*CNUM];
__device__ float g_q2[PNUM];
__device__ float g_zn[512];
__device__ float g_pm[128*CNUM];
__device__ float g_pd[128];
__device__ float g_pv[128];
__device__ float g_mu[CNUM];
__device__ float g_sc[8];

// ---------------- PTX helpers ----------------
__device__ __forceinline__ uint32_t smem_u32(const void* p) {
    uint32_t a;
    asm("{ .reg .u64 t; cvta.to.shared.u64 t, %1; cvt.u32.u64 %0, t; }" : "=r"(a) : "l"(p));
    return a;
}
__device__ __forceinline__ void cpa16(uint32_t dst, const void* src) {
    asm volatile("cp.async.cg.shared.global [%0], [%1], 16;" :: "r"(dst), "l"(src) : "memory");
}
__device__ __forceinline__ void cp_commit() {
    asm volatile("cp.async.commit_group;" ::: "memory");
}
template<int N>
__device__ __forceinline__ void cp_wait() {
    asm volatile("cp.async.wait_group %0;" :: "n"(N) : "memory");
}
__device__ __forceinline__ void ldsm4(uint32_t* r, uint32_t addr) {
    asm volatile("ldmatrix.sync.aligned.m8n8.x4.shared.b16 {%0,%1,%2,%3}, [%4];"
        : "=r"(r[0]), "=r"(r[1]), "=r"(r[2]), "=r"(r[3]) : "r"(addr));
}
__device__ __forceinline__ void mma16816(float* d, const uint32_t* a, const uint32_t* b) {
    asm volatile("mma.sync.aligned.m16n8k16.row.col.f32.bf16.bf16.f32 "
        "{%0,%1,%2,%3}, {%4,%5,%6,%7}, {%8,%9}, {%0,%1,%2,%3};"
        : "+f"(d[0]), "+f"(d[1]), "+f"(d[2]), "+f"(d[3])
        : "r"(a[0]), "r"(a[1]), "r"(a[2]), "r"(a[3]), "r"(b[0]), "r"(b[1]));
}
__device__ __forceinline__ uint32_t swz(int r, int c) {
    return (uint32_t)(((r >> 1) << 7) | (((((r & 1) << 2) | c) ^ ((r >> 1) & 7)) << 4));
}

// ---------------- reductions ----------------
__device__ __forceinline__ float warpSum(float v) {
#pragma unroll
    for (int o = 16; o > 0; o >>= 1) v += __shfl_xor_sync(0xffffffffu, v, o);
    return v;
}
template<int K>
__device__ __forceinline__ void blockReduceK(float* v, float* sbuf) {
    int tid = threadIdx.x, lane = tid & 31, wid = tid >> 5;
#pragma unroll
    for (int i = 0; i < K; i++) {
        float x = v[i];
#pragma unroll
        for (int o = 16; o > 0; o >>= 1) x += __shfl_down_sync(0xffffffffu, x, o);
        if (lane == 0) sbuf[i*8 + wid] = x;
    }
    __syncthreads();
    if (tid == 0) {
#pragma unroll
        for (int i = 0; i < K; i++) {
            float s = sbuf[i*8];
            for (int w = 1; w < 8; w++) s += sbuf[i*8 + w];
            sbuf[i*8] = s;
        }
    }
    __syncthreads();
#pragma unroll
    for (int i = 0; i < K; i++) v[i] = sbuf[i*8];
    __syncthreads();
}

// ---------------- Winograd transforms ----------------
__device__ __forceinline__ void bt6(const float* in, float* out) {
    out[0] =  4.f*in[0] - 5.f*in[2] + in[4];
    out[1] = -4.f*in[1] - 4.f*in[2] + in[3] + in[4];
    out[2] =  4.f*in[1] - 4.f*in[2] - in[3] + in[4];
    out[3] = -2.f*in[1] -     in[2] + 2.f*in[3] + in[4];
    out[4] =  2.f*in[1] -     in[2] - 2.f*in[3] + in[4];
    out[5] =  4.f*in[1] - 5.f*in[3] + in[5];
}
__device__ __forceinline__ void g6(const float* in, float* out) {
    out[0] = 0.25f*in[0];
    out[1] = -(in[0] + in[1] + in[2]) * (1.f/6.f);
    out[2] = (-in[0] + in[1] - in[2]) * (1.f/6.f);
    out[3] = in[0]*(1.f/24.f) + in[1]*(1.f/12.f) + in[2]*(1.f/6.f);
    out[4] = in[0]*(1.f/24.f) - in[1]*(1.f/12.f) + in[2]*(1.f/6.f);
    out[5] = in[2];
}
__device__ __forceinline__ void at6(const float* in, float* out) {
    out[0] = in[0] + in[1] + in[2] + in[3] + in[4];
    out[1] = in[1] - in[2] + 2.f*(in[3] - in[4]);
    out[2] = in[1] + in[2] + 4.f*(in[3] + in[4]);
    out[3] = in[1] - in[2] + 8.f*(in[3] - in[4]) + in[5];
}

// ---------------- U = G z G^T (+ fused z column norms) ----------------
__global__ void wino_u(const float* __restrict__ z1, const float* __restrict__ z2) {
    __shared__ float sb[8];
    const float* z = blockIdx.y ? z2 : z1;
    __nv_bfloat16* uh = blockIdx.y ? g_uhi2 : g_uhi1;
    __nv_bfloat16* ul = blockIdx.y ? g_ulo2 : g_ulo1;
    int co = blockIdx.x, ci = threadIdx.x;
    float g[3][3];
    float nsum = 0.f;
#pragma unroll
    for (int i = 0; i < 3; i++)
#pragma unroll
        for (int j = 0; j < 3; j++) {
            float w = z[(size_t)((i*3 + j)*256 + ci)*256 + co];
            g[i][j] = w;
            nsum += w*w;
        }
    float r1[1] = { nsum };
    blockReduceK<1>(r1, sb);
    if (ci == 0) g_zn[blockIdx.y*256 + co] = sqrtf(fmaxf(r1[0], EPSF));

    float t[6][3];
#pragma unroll
    for (int j = 0; j < 3; j++) {
        float in[3] = { g[0][j], g[1][j], g[2][j] };
        float out[6];
        g6(in, out);
#pragma unroll
        for (int a = 0; a < 6; a++) t[a][j] = out[a];
    }
#pragma unroll
    for (int a = 0; a < 6; a++) {
        float out[6];
        g6(t[a], out);
#pragma unroll
        for (int b = 0; b < 6; b++) {
            float u = out[b];
            __nv_bfloat16 hi = __float2bfloat16(u);
            size_t idx = ((size_t)((a*6 + b)*256 + co))*256 + ci;
            uh[idx] = hi;
            ul[idx] = __float2bfloat16(u - __bfloat162float(hi));
        }
    }
}

// ---------------- V = B^T d B per tile ----------------
__global__ void wino_in() {
    int t = blockIdx.x, ci = threadIdx.x;
    int b = t >> 6, tr = (t >> 3) & 7, tc = t & 7;
    int base = b << 10;
    float d[6][6];
#pragma unroll
    for (int y = 0; y < 6; y++) {
        int iy = 4*tr - 1 + y;
#pragma unroll
        for (int x = 0; x < 6; x++) {
            int ix = 4*tc - 1 + x;
            bool ok = ((unsigned)iy < 32u) && ((unsigned)ix < 32u);
            d[y][x] = ok ? g_v[(size_t)(base + iy*32 + ix)*256 + ci] : 0.f;
        }
    }
    float e[6][6];
#pragma unroll
    for (int x = 0; x < 6; x++) {
        float in[6] = { d[0][x], d[1][x], d[2][x], d[3][x], d[4][x], d[5][x] };
        float out[6];
        bt6(in, out);
#pragma unroll
        for (int a = 0; a < 6; a++) e[a][x] = out[a];
    }
#pragma unroll
    for (int a = 0; a < 6; a++) {
        float out[6];
        bt6(e[a], out);
#pragma unroll
        for (int bb = 0; bb < 6; bb++) {
            float v = out[bb];
            __nv_bfloat16 hi = __float2bfloat16(v);
            size_t idx = ((size_t)((a*6 + bb)*NTIL + t))*256 + ci;
            g_Vhi[idx] = hi;
            g_Vlo[idx] = __float2bfloat16(v - __bfloat162float(hi));
        }
    }
}

// ---------------- batched Winograd GEMM: M[pos] = V[pos] @ U[pos]^T ----------------
// grid (8 mtiles, 2 nhalf, 36 pos). 256 thr = 8 warps (4m x 2n), warp 32x64,
// split-3 bf16 in 3 grouped passes (acc-reuse gap = 16 MMAs), BK=32, 3-stage.
__global__ void __launch_bounds__(256, 2) wino_gemm(int which) {
    extern __shared__ __align__(16) char dsm[];
    uint32_t sbase = smem_u32(dsm);

    const __nv_bfloat16* Bh = which ? g_uhi2 : g_uhi1;
    const __nv_bfloat16* Bl = which ? g_ulo2 : g_ulo1;
    int t0  = blockIdx.x << 7;
    int nh  = blockIdx.y;
    int pos = blockIdx.z;

    int tid = threadIdx.x, wid = tid >> 5, l = tid & 31;

    int c4 = tid & 3;
    int r0 = tid >> 2;
    uint32_t ph0 = swz(r0, c4), ph1 = swz(r0 + 64, c4);
    const __nv_bfloat16* Abase_hi = g_Vhi + ((size_t)pos*NTIL + t0)*256;
    const __nv_bfloat16* Abase_lo = g_Vlo + ((size_t)pos*NTIL + t0)*256;
    const __nv_bfloat16* Bbase_hi = Bh + ((size_t)pos*256 + nh*128)*256;
    const __nv_bfloat16* Bbase_lo = Bl + ((size_t)pos*256 + nh*128)*256;
    size_t a0 = (size_t)r0*256 + c4*8, a1 = (size_t)(r0 + 64)*256 + c4*8;

    int m0 = (wid & 3) << 5;
    int n0w = (wid >> 2) << 6;
    int mi = l >> 3;
    int rA = m0 + ((mi & 1) << 3) + (l & 7);
    uint32_t qA0 = swz(rA, mi >> 1);
    int rB = n0w + (((mi >> 1) & 1) << 3) + (l & 7);
    uint32_t qB0 = swz(rB, mi & 1);

    float acc[2][8][4];
#pragma unroll
    for (int i = 0; i < 2; i++)
#pragma unroll
        for (int j = 0; j < 8; j++)
#pragma unroll
            for (int k = 0; k < 4; k++) acc[i][j][k] = 0.f;

    auto load_chunk = [&](int kc, int stage) {
        size_t coff = (size_t)(kc << 5);
        uint32_t st = sbase + (uint32_t)stage*STAGE_BYTES;
        cpa16(st + ph0,         Abase_hi + a0 + coff);
        cpa16(st + 8192 + ph0,  Abase_lo + a0 + coff);
        cpa16(st + ph1,         Abase_hi + a1 + coff);
        cpa16(st + 8192 + ph1,  Abase_lo + a1 + coff);
        cpa16(st + 16384 + ph0, Bbase_hi + a0 + coff);
        cpa16(st + 24576 + ph0, Bbase_lo + a0 + coff);
        cpa16(st + 16384 + ph1, Bbase_hi + a1 + coff);
        cpa16(st + 24576 + ph1, Bbase_lo + a1 + coff);
        cp_commit();
    };

    load_chunk(0, 0);
    load_chunk(1, 1);

    for (int kc = 0; kc < 8; kc++) {
        int stage = kc % 3;
        if (kc < 6) cp_wait<1>(); else cp_wait<0>();
        __syncthreads();
        if (kc + 2 < 8) load_chunk(kc + 2, (kc + 2) % 3);

        uint32_t st = sbase + (uint32_t)stage*STAGE_BYTES;
        uint32_t Ahi = st, Alo = st + 8192, Bhi = st + 16384, Blo = st + 24576;
#pragma unroll
        for (int ks = 0; ks < 2; ks++) {
            uint32_t kx = (uint32_t)(ks << 5);
            uint32_t qa = qA0 ^ kx, qb = qB0 ^ kx;
            uint32_t ah[8], al[8], bbv[16];
            ldsm4(ah,     Ahi + qa);
            ldsm4(ah + 4, Ahi + qa + 1024);
            ldsm4(al,     Alo + qa);
            ldsm4(al + 4, Alo + qa + 1024);
#pragma unroll
            for (int j = 0; j < 4; j++) ldsm4(bbv + j*4, Bhi + qb + j*1024);
            // group 1: A_hi x B_hi (16 MMAs, all-distinct accs)
#pragma unroll
            for (int nf = 0; nf < 8; nf++) {
                const uint32_t* bp = bbv + nf*2;
                mma16816(acc[0][nf], ah,     bp);
                mma16816(acc[1][nf], ah + 4, bp);
            }
            // group 2: A_lo x B_hi
#pragma unroll
            for (int nf = 0; nf < 8; nf++) {
                const uint32_t* bp = bbv + nf*2;
                mma16816(acc[0][nf], al,     bp);
                mma16816(acc[1][nf], al + 4, bp);
            }
            // group 3: A_hi x B_lo
#pragma unroll
            for (int j = 0; j < 4; j++) ldsm4(bbv + j*4, Blo + qb + j*1024);
#pragma unroll
            for (int nf = 0; nf < 8; nf++) {
                const uint32_t* bp = bbv + nf*2;
                mma16816(acc[0][nf], ah,     bp);
                mma16816(acc[1][nf], ah + 4, bp);
            }
        }
    }
    __syncthreads();

    float* ybuf = (float*)dsm;
    int row0 = m0 + (l >> 2);
    int col0 = n0w + ((l & 3) << 1);
#pragma unroll
    for (int mf = 0; mf < 2; mf++)
#pragma unroll
        for (int nf = 0; nf < 8; nf++)
#pragma unroll
            for (int hf = 0; hf < 2; hf++) {
                int r = row0 + mf*16 + hf*8;
                *(float2*)&ybuf[r*YST2 + col0 + nf*8] =
                    make_float2(acc[mf][nf][hf*2], acc[mf][nf][hf*2 + 1]);
            }
    __syncthreads();
    {
        int row = tid >> 1, q = tid & 1;
        const float4* yr = (const float4*)(ybuf + row*YST2 + q*64);
        float4* dst = (float4*)(g_m + ((size_t)pos*NTIL + t0 + row)*256 + nh*128 + q*64);
#pragma unroll
        for (int i = 0; i < 16; i++) dst[i] = yr[i];
    }
}

// ---------------- pre2: coalesced x read -> g_v fp32 + q2 + g_xl (fused xT) ----------------
__global__ void pre2_kernel(const float* __restrict__ x, float scale) {
    __shared__ float sx[256][33];
    int tid = threadIdx.x, lane = tid & 31, w8 = tid >> 5;
    int p0 = blockIdx.x * 32;
    int b = p0 >> 10, hw0 = p0 & 1023;
#pragma unroll 8
    for (int i = 0; i < 32; i++) {
        int c = i*8 + w8;
        sx[c][lane] = x[(size_t)(b*256 + c)*1024 + hw0 + lane];
    }
    __syncthreads();
    // fused xT: write g_xl [p][c] coalesced
#pragma unroll 8
    for (int pl = 0; pl < 32; pl++)
        g_xl[(size_t)(p0 + pl)*256 + tid] = sx[tid][pl];
#pragma unroll
    for (int pp = 0; pp < 4; pp++) {
        int pl = w8*4 + pp;
        int p = p0 + pl;
        float xv[8];
#pragma unroll
        for (int i = 0; i < 8; i++) xv[i] = sx[lane*8 + i][pl];
        float q = 0.f;
#pragma unroll
        for (int i = 0; i < 8; i++) q += xv[i]*xv[i];
        float n2 = warpSum(q);
        float n = sqrtf(fmaxf(n2, EPSF));
        float f = atanhf(fminf(n, CLIP1)) / n * scale;
        float4 o0 = make_float4(f*xv[0], f*xv[1], f*xv[2], f*xv[3]);
        float4 o1 = make_float4(f*xv[4], f*xv[5], f*xv[6], f*xv[7]);
        float* dst = g_v + (size_t)p*256 + lane*8;
        *(float4*)dst = o0;
        *(float4*)(dst + 4) = o1;
        if (lane == 0) g_q2[p] = f*f*n2;
    }
}

// ---------------- per-pixel s = lam*alpha from 3x3 q2 sums ----------------
__device__ __forceinline__ float s_from_q2(int p) {
    int h = (p >> 5) & 31, w = p & 31;
    float np2 = 0.f;
#pragma unroll
    for (int dy = -1; dy <= 1; dy++)
#pragma unroll
        for (int dx = -1; dx <= 1; dx++) {
            int sh = h + dy, sw = w + dx;
            if ((unsigned)sh < 32u && (unsigned)sw < 32u) np2 += g_q2[p + dy*32 + dx];
        }
    float np = sqrtf(fmaxf(np2, EPSF));
    float th = tanhf(np);
    float uf = th / np;
    float un = th;
    if (un > MAXN) { uf *= MAXN/un; un = MAXN; }
    float lam = 2.0f / fmaxf(1.0f - un*un, EPSF);
    return lam * uf;
}

// ---------------- output transform + fused s + FC epilogue -> raw y in g_h ----------------
__global__ void wino_out(int znoff) {
    __shared__ float ss[16];
    int t = blockIdx.x, co = threadIdx.x;
    int b = t >> 6, tr = (t >> 3) & 7, tc = t & 7;
    int prow = (b << 10) + (4*tr)*32 + 4*tc;
    if (co < 16) {
        int r = co >> 2, c = co & 3;
        ss[co] = s_from_q2(prow + r*32 + c);
    }
    float m[36];
#pragma unroll
    for (int pos = 0; pos < 36; pos++)
        m[pos] = g_m[((size_t)pos*NTIL + t)*256 + co];
    float Z[4][6];
#pragma unroll
    for (int bb = 0; bb < 6; bb++) {
        float in[6] = { m[bb], m[6+bb], m[12+bb], m[18+bb], m[24+bb], m[30+bb] };
        float out[4];
        at6(in, out);
#pragma unroll
        for (int r = 0; r < 4; r++) Z[r][bb] = out[r];
    }
    float zn = g_zn[znoff + co];
    __syncthreads();
#pragma unroll
    for (int r = 0; r < 4; r++) {
        float Y[4];
        at6(Z[r], Y);
#pragma unroll
        for (int c = 0; c < 4; c++) {
            int p = prow + r*32 + c;
            float s = ss[r*4 + c];
            float tt = Y[c] * s / zn;
            float y = sinhf(2.0f * zn * asinhf(tt));
            g_h[(size_t)p*256 + co] = y;
        }
    }
}

// ---------------- BN phase 1 (raw-y input) ----------------
__global__ void bnred_w() {
    __shared__ float sm[8][256];
    __shared__ float sd[8];
    int wid = threadIdx.x >> 5, lid = threadIdx.x & 31;
    int p0 = blockIdx.x * 128;
    float accm[8] = {0,0,0,0,0,0,0,0};
    float accd = 0.f;
    for (int i = 0; i < 16; i++) {
        int p = p0 + wid*16 + i;
        const float4* row = (const float4*)(g_h + (size_t)p*256 + lid*8);
        float4 a = row[0], c = row[1];
        float v[8] = {a.x,a.y,a.z,a.w,c.x,c.y,c.z,c.w};
        float q = 0.f;
#pragma unroll
        for (int j = 0; j < 8; j++) q += v[j]*v[j];
        float tot = warpSum(q);
        float inv = 1.0f / (1.0f + sqrtf(1.0f + tot));
        float n2 = tot*inv*inv;
        float lam = 2.0f / fmaxf(1.0f - n2, EPSF);
        float li = lam * inv;
#pragma unroll
        for (int j = 0; j < 8; j++) accm[j] += li * v[j];
        accd += lam - 1.0f;
    }
#pragma unroll
    for (int j = 0; j < 8; j++) sm[wid][lid*8 + j] = accm[j];
    if (lid == 0) sd[wid] = accd;
    __syncthreads();
    int c = threadIdx.x;
    float s = 0.f;
    for (int w = 0; w < 8; w++) s += sm[w][c];
    g_pm[blockIdx.x*256 + c] = s;
    if (c == 0) {
        float d = 0.f;
        for (int w = 0; w < 8; w++) d += sd[w];
        g_pd[blockIdx.x] = d;
    }
}

// ---------------- BN phase 2 ----------------
__global__ void bnmu_kernel(const float* __restrict__ bias) {
    __shared__ float sb[24];
    int c = threadIdx.x;
    float msum = 0.f;
    for (int g = 0; g < 128; g++) msum += g_pm[g*256 + c];
    float dv = (c < 128) ? g_pd[c] : 0.f;
    float r1[1] = { dv };
    blockReduceK<1>(r1, sb);
    float den = fmaxf(r1[0], EPSF);
    float m = msum / den;
    float r2[1] = { m*m };
    blockReduceK<1>(r2, sb);
    float nm = sqrtf(fmaxf(r2[0], EPSF));
    float fac = tanhf(0.5f * atanhf(fminf(nm, CLIP1))) / nm;
    float muc = fac * m;
    g_mu[c] = muc;
    float bc = bias[c];
    float r3[3] = { muc*muc, bc*bc, bc*muc };
    blockReduceK<3>(r3, sb);
    if (c == 0) {
        float mu2 = r3[0], b2 = r3[1], bm = r3[2];
        g_sc[0] = mu2;
        g_sc[1] = 2.0f / fmaxf(1.0f - mu2, EPSF);
        g_sc[2] = b2;
        g_sc[3] = 2.0f / fmaxf(1.0f - b2, EPSF);
        g_sc[4] = bm;
    }
}

// ---------------- BN phase 3 (raw-y input) ----------------
__global__ void bnvar_w() {
    __shared__ float sv[8];
    int wid = threadIdx.x >> 5, lid = threadIdx.x & 31;
    int p0 = blockIdx.x * 128;
    float mu8[8];
#pragma unroll
    for (int j = 0; j < 8; j++) mu8[j] = g_mu[lid*8 + j];
    float mu2 = g_sc[0];
    float acc = 0.f;
    for (int i = 0; i < 16; i++) {
        int p = p0 + wid*16 + i;
        const float4* row = (const float4*)(g_h + (size_t)p*256 + lid*8);
        float4 a = row[0], cc = row[1];
        float v[8] = {a.x,a.y,a.z,a.w,cc.x,cc.y,cc.z,cc.w};
        float q1 = 0.f, q2 = 0.f;
#pragma unroll
        for (int j = 0; j < 8; j++) { q1 += v[j]*v[j]; q2 += v[j]*mu8[j]; }
        float tot = warpSum(q1);
        float ipr = warpSum(q2);
        float inv = 1.0f / (1.0f + sqrtf(1.0f + tot));
        float xp2 = tot*inv*inv;
        float ip  = ipr*inv;
        float A = 1.0f - 2.0f*ip + mu2;
        float B = 1.0f - xp2;
        float nn = fmaxf(A*A*xp2 - 2.0f*A*B*ip + B*B*mu2, 0.f);
        float den = fmaxf(1.0f - 2.0f*ip + xp2*mu2, EPSF);
        float nr = sqrtf(fmaxf(nn/(den*den), EPSF));
        float dd = 2.0f * atanhf(fminf(nr, CLIP1));
        acc += dd*dd;
    }
    if (lid == 0) sv[wid] = acc;
    __syncthreads();
    if (threadIdx.x == 0) {
        float s = 0.f;
        for (int w = 0; w < 8; w++) s += sv[w];
        g_pv[blockIdx.x] = s;
    }
}

// ---------------- BN phase 4 ----------------
__global__ void bnfin_kernel(const float* __restrict__ weight) {
    int tid = threadIdx.x;
    float v = g_pv[tid];
#pragma unroll
    for (int o = 16; o > 0; o >>= 1) v += __shfl_down_sync(0xffffffffu, v, o);
    __shared__ float sb[4];
    if ((tid & 31) == 0) sb[tid >> 5] = v;
    __syncthreads();
    if (tid == 0) {
        float var = (sb[0] + sb[1] + sb[2] + sb[3]) / 16384.0f;
        g_sc[5] = sqrtf(weight[0] / fmaxf(var, EPSF));
    }
}

// ---------------- shared BN point transform ----------------
__device__ __forceinline__ float bn_point_w(const float* xv, const float* mu8, const float* b8,
                                            float* hc) {
    float mu2 = g_sc[0], lam_mu = g_sc[1], b2 = g_sc[2], lam_b = g_sc[3],
          bm = g_sc[4], rstd = g_sc[5];
    float s0 = 0.f, s1 = 0.f, s2 = 0.f;
#pragma unroll
    for (int i = 0; i < 8; i++) { s0 += xv[i]*xv[i]; s1 += mu8[i]*xv[i]; s2 += b8[i]*xv[i]; }
    float xp2 = warpSum(s0), ip = warpSum(s1), bx = warpSum(s2);
    float A  = 1.0f - 2.0f*ip + xp2;
    float Bc = 1.0f - mu2;
    float den = fmaxf(1.0f - 2.0f*ip + mu2*xp2, EPSF);
    float nd2 = fmaxf(A*A*mu2 - 2.0f*A*Bc*ip + Bc*Bc*xp2, 0.f) / (den*den);
    float nd = sqrtf(fmaxf(nd2, EPSF));
    float cv = (2.0f/lam_mu) * atanhf(fminf(nd, CLIP1)) / nd;
    float uw = cv * (Bc*bx - A*bm) / den;
    float vw = cv * (A*mu2 - Bc*ip) / den;
    float av  = -uw*mu2 - vw - 2.0f*bm*vw;
    float bv2 = -vw*b2 + uw;
    float dgy = fmaxf(1.0f - 2.0f*bm + b2*mu2, EPSF);
    float fac = (lam_mu / lam_b) * rstd;
    float uc[8];
    float t0 = 0.f, t1 = 0.f;
#pragma unroll
    for (int i = 0; i < 8; i++) {
        float vc = cv * (Bc*xv[i] - A*mu8[i]) / den;
        uc[i] = (vc + 2.0f*(av*b8[i] - bv2*mu8[i]) / dgy) * fac;
        t0 += uc[i]*uc[i];
        t1 += b8[i]*uc[i];
    }
    float u2 = warpSum(t0), bu = warpSum(t1);
    float nu = sqrtf(fmaxf(u2, EPSF));
    float tf = tanhf(0.5f * lam_b * nu) / nu;
    float s2m = tf*tf*u2;
    float bs  = tf*bu;
    float A3 = 1.0f + 2.0f*bs + s2m, B3 = 1.0f - b2;
    float den3 = fmaxf(1.0f + 2.0f*bs + b2*s2m, EPSF);
#pragma unroll
    for (int i = 0; i < 8; i++) hc[i] = (A3*b8[i] + B3*tf*uc[i]) / den3;
    float nh2 = fmaxf(A3*A3*b2 + 2.0f*A3*B3*bs + B3*B3*s2m, 0.f) / (den3*den3);
    float nh = sqrtf(fmaxf(nh2, EPSF));
    if (nh > MAXN) {
        float q = MAXN / nh;
#pragma unroll
        for (int i = 0; i < 8; i++) hc[i] *= q;
        nh = MAXN;
    }
    return nh;
}

// ---------------- BN apply + hrelu + pre-for-conv2 (writes g_v fp32) ----------------
__global__ void bnapply_w(const float* __restrict__ bias, float scale) {
    int wid = threadIdx.x >> 5, lid = threadIdx.x & 31;
    int p = blockIdx.x * 8 + wid;
    const float4* row = (const float4*)(g_h + (size_t)p*256 + lid*8);
    float4 a = row[0], cc = row[1];
    float xv[8] = {a.x,a.y,a.z,a.w,cc.x,cc.y,cc.z,cc.w};
    float qy = 0.f;
#pragma unroll
    for (int i = 0; i < 8; i++) qy += xv[i]*xv[i];
    float tot = warpSum(qy);
    float inv = 1.0f / (1.0f + sqrtf(1.0f + tot));
#pragma unroll
    for (int i = 0; i < 8; i++) xv[i] *= inv;
    float mu8[8], b8[8];
#pragma unroll
    for (int j = 0; j < 8; j++) { mu8[j] = g_mu[lid*8 + j]; b8[j] = bias[lid*8 + j]; }
    float hc[8];
    float nh = bn_point_w(xv, mu8, b8, hc);
    float lf = atanhf(fminf(nh, CLIP1)) / nh;
    float rc[8];
    float q = 0.f;
#pragma unroll
    for (int i = 0; i < 8; i++) { rc[i] = fmaxf(lf*hc[i], 0.f); q += rc[i]*rc[i]; }
    float rs = warpSum(q);
    float nr = sqrtf(fmaxf(rs, EPSF));
    float ef = tanhf(nr) / nr;
    float nhr = sqrtf(fmaxf(ef*ef*rs, EPSF));
    float adj = 1.0f;
    if (nhr > MAXN) { adj = MAXN/nhr; nhr = MAXN; }
    float f3 = atanhf(fminf(nhr, CLIP1)) / nhr * scale;
    float g = f3 * ef * adj;
    float4 o0 = make_float4(g*rc[0], g*rc[1], g*rc[2], g*rc[3]);
    float4 o1 = make_float4(g*rc[4], g*rc[5], g*rc[6], g*rc[7]);
    float* dst = g_v + (size_t)p*256 + lid*8;
    *(float4*)dst = o0;
    *(float4*)(dst + 4) = o1;
    if (lid == 0) g_q2[p] = f3*f3*nhr*nhr;
}

// ---------------- BN2 apply + residual + hrelu + staged NCHW out ----------------
__global__ void final2_kernel(const float* __restrict__ bias, float* __restrict__ out) {
    __shared__ float so[256][33];
    int tid = threadIdx.x, lane = tid & 31, w8 = tid >> 5;
    int p0 = blockIdx.x * 32;
    int b = p0 >> 10, hw0 = p0 & 1023;
    float mu8[8], b8[8];
#pragma unroll
    for (int j = 0; j < 8; j++) { mu8[j] = g_mu[lane*8 + j]; b8[j] = bias[lane*8 + j]; }
#pragma unroll
    for (int pp = 0; pp < 4; pp++) {
        int pl = w8*4 + pp;
        int p = p0 + pl;
        const float4* row = (const float4*)(g_h + (size_t)p*256 + lane*8);
        float4 a = row[0], cc = row[1];
        float xv[8] = {a.x,a.y,a.z,a.w,cc.x,cc.y,cc.z,cc.w};
        float qy = 0.f;
#pragma unroll
        for (int i = 0; i < 8; i++) qy += xv[i]*xv[i];
        float tot = warpSum(qy);
        float inv = 1.0f / (1.0f + sqrtf(1.0f + tot));
#pragma unroll
        for (int i = 0; i < 8; i++) xv[i] *= inv;
        float hc[8];
        float nh = bn_point_w(xv, mu8, b8, hc);
        const float4* rrow = (const float4*)(g_xl + (size_t)p*256 + lane*8);
        float4 r0 = rrow[0], r1 = rrow[1];
        float res[8] = {r0.x,r0.y,r0.z,r0.w,r1.x,r1.y,r1.z,r1.w};
        float q1 = 0.f, q2 = 0.f;
#pragma unroll
        for (int i = 0; i < 8; i++) { q1 += res[i]*res[i]; q2 += hc[i]*res[i]; }
        float y2 = warpSum(q1), xy = warpSum(q2);
        float x2 = nh*nh;
        float A4 = 1.0f + 2.0f*xy + y2, B4 = 1.0f - x2;
        float den4 = fmaxf(1.0f + 2.0f*xy + x2*y2, EPSF);
        float hm[8];
#pragma unroll
        for (int i = 0; i < 8; i++) hm[i] = (A4*hc[i] + B4*res[i]) / den4;
        float nm2 = fmaxf(A4*A4*x2 + 2.0f*A4*B4*xy + B4*B4*y2, 0.f) / (den4*den4);
        float nmv = sqrtf(fmaxf(nm2, EPSF));
        float lf = atanhf(fminf(nmv, CLIP1)) / nmv;
        float rc[8];
        float q = 0.f;
#pragma unroll
        for (int i = 0; i < 8; i++) { rc[i] = fmaxf(lf*hm[i], 0.f); q += rc[i]*rc[i]; }
        float rs = warpSum(q);
        float nr = sqrtf(fmaxf(rs, EPSF));
        float ef = tanhf(nr) / nr;
        float nhr = sqrtf(fmaxf(ef*ef*rs, EPSF));
        float adj = (nhr > MAXN) ? MAXN/nhr : 1.0f;
#pragma unroll
        for (int i = 0; i < 8; i++) so[lane*8 + i][pl] = ef * adj * rc[i];
    }
    __syncthreads();
#pragma unroll 8
    for (int i = 0; i < 32; i++) {
        int c = i*8 + w8;
        out[(size_t)(b*256 + c)*1024 + hw0 + lane] = so[c][lane];
    }
}

// ---------------- launcher ----------------
extern "C" void kernel_launch(void* const* d_in, const int* in_sizes, int n_in,
                              void* d_out, int out_size) {
    const float* x  = (const float*)d_in[0];
    const float* z1 = (const float*)d_in[1];
    const float* z2 = (const float*)d_in[2];
    const float* w1 = (const float*)d_in[3];
    const float* b1 = (const float*)d_in[4];
    const float* w2 = (const float*)d_in[5];
    const float* b2 = (const float*)d_in[6];
    float* out = (float*)d_out;

    // scale = Beta(1152, 0.5) / Beta(128, 0.5)
    double lg = lgamma(1152.0) - lgamma(1152.5) - lgamma(128.0) + lgamma(128.5);
    float scale = (float)exp(lg);

    static int smem_set = 0;
    if (!smem_set) {
        cudaFuncSetAttribute(wino_gemm, cudaFuncAttributeMaxDynamicSharedMemorySize, CONV_SMEM);
        smem_set = 1;
    }

    dim3 ggrid(8, 2, 36);

    pre2_kernel<<<PNUM/32, 256>>>(x, scale);     // 0 (also writes g_xl)
    wino_u<<<dim3(256, 2), 256>>>(z1, z2);       // 1 (also writes g_zn)
    wino_in<<<NTIL, 256>>>();                    // 2
    wino_gemm<<<ggrid, 256, CONV_SMEM>>>(0);     // 3  <- ncu capture target
    wino_out<<<NTIL, 256>>>(0);

    bnred_w<<<128, 256>>>();
    bnmu_kernel<<<1, 256>>>(b1);
    bnvar_w<<<128, 256>>>();
    bnfin_kernel<<<1, 128>>>(w1);
    bnapply_w<<<PNUM/8, 256>>>(b1, scale);

    wino_in<<<NTIL, 256>>>();
    wino_gemm<<<ggrid, 256, CONV_SMEM>>>(1);
    wino_out<<<NTIL, 256>>>(256);

    bnred_w<<<128, 256>>>();
    bnmu_kernel<<<1, 256>>>(b2);
    bnvar_w<<<128, 256>>>();
    bnfin_kernel<<<1, 128>>>(w2);
    final2_kernel<<<PNUM/32, 256>>>(b2, out);
}

// round 9
// speedup vs baseline: 1.8705x; 1.0242x over previous
#include <cuda_runtime.h>
#include <cuda_bf16.h>
#include <math.h>
#include <stdint.h>

// Problem constants: B=16, C=256, H=W=32
#define PNUM 16384
#define CNUM 256
#define NKTOT 2304
#define CLIP1 0.9999999f
#define MAXN  0.99999f
#define EPSF  1e-15f

#define NPOS 36
#define NTIL 1024
#define STAGE_BYTES 32768u
#define YST2  132
#define CONV_SMEM (3*32768)

// ---------------- device scratch ----------------
__device__ __align__(16) float g_v [PNUM*CNUM];
__device__ __align__(16) __nv_bfloat16 g_Vhi[NPOS*NTIL*CNUM];
__device__ __align__(16) __nv_bfloat16 g_Vlo[NPOS*NTIL*CNUM];
__device__ __align__(16) __nv_bfloat16 g_uhi1[NPOS*CNUM*CNUM];
__device__ __align__(16) __nv_bfloat16 g_ulo1[NPOS*CNUM*CNUM];
__device__ __align__(16) __nv_bfloat16 g_uhi2[NPOS*CNUM*CNUM];
__device__ __align__(16) __nv_bfloat16 g_ulo2[NPOS*CNUM*CNUM];
__device__ __align__(16) float g_m [NPOS*NTIL*CNUM];
__device__ __align__(16) float g_h [PNUM*CNUM];
__device__ __align__(16) float g_xl[PNUM*CNUM];
__device__ float g_q2[PNUM];
__device__ float g_zn[512];
__device__ float g_pm[256*CNUM];
__device__ float g_pd[256];
__device__ float g_pv[256];
__device__ float g_mu[CNUM];
__device__ float g_sc[8];
__device__ int   g_ctr = 0;

// ---------------- PTX helpers ----------------
__device__ __forceinline__ uint32_t smem_u32(const void* p) {
    uint32_t a;
    asm("{ .reg .u64 t; cvta.to.shared.u64 t, %1; cvt.u32.u64 %0, t; }" : "=r"(a) : "l"(p));
    return a;
}
__device__ __forceinline__ void cpa16(uint32_t dst, const void* src) {
    asm volatile("cp.async.cg.shared.global [%0], [%1], 16;" :: "r"(dst), "l"(src) : "memory");
}
__device__ __forceinline__ void cp_commit() {
    asm volatile("cp.async.commit_group;" ::: "memory");
}
template<int N>
__device__ __forceinline__ void cp_wait() {
    asm volatile("cp.async.wait_group %0;" :: "n"(N) : "memory");
}
__device__ __forceinline__ void ldsm4(uint32_t* r, uint32_t addr) {
    asm volatile("ldmatrix.sync.aligned.m8n8.x4.shared.b16 {%0,%1,%2,%3}, [%4];"
        : "=r"(r[0]), "=r"(r[1]), "=r"(r[2]), "=r"(r[3]) : "r"(addr));
}
__device__ __forceinline__ void mma16816(float* d, const uint32_t* a, const uint32_t* b) {
    asm volatile("mma.sync.aligned.m16n8k16.row.col.f32.bf16.bf16.f32 "
        "{%0,%1,%2,%3}, {%4,%5,%6,%7}, {%8,%9}, {%0,%1,%2,%3};"
        : "+f"(d[0]), "+f"(d[1]), "+f"(d[2]), "+f"(d[3])
        : "r"(a[0]), "r"(a[1]), "r"(a[2]), "r"(a[3]), "r"(b[0]), "r"(b[1]));
}
__device__ __forceinline__ uint32_t swz(int r, int c) {
    return (uint32_t)(((r >> 1) << 7) | (((((r & 1) << 2) | c) ^ ((r >> 1) & 7)) << 4));
}

// ---------------- reductions ----------------
__device__ __forceinline__ float warpSum(float v) {
#pragma unroll
    for (int o = 16; o > 0; o >>= 1) v += __shfl_xor_sync(0xffffffffu, v, o);
    return v;
}
template<int K>
__device__ __forceinline__ void blockReduceK(float* v, float* sbuf) {
    int tid = threadIdx.x, lane = tid & 31, wid = tid >> 5;
#pragma unroll
    for (int i = 0; i < K; i++) {
        float x = v[i];
#pragma unroll
        for (int o = 16; o > 0; o >>= 1) x += __shfl_down_sync(0xffffffffu, x, o);
        if (lane == 0) sbuf[i*8 + wid] = x;
    }
    __syncthreads();
    if (tid == 0) {
#pragma unroll
        for (int i = 0; i < K; i++) {
            float s = sbuf[i*8];
            for (int w = 1; w < 8; w++) s += sbuf[i*8 + w];
            sbuf[i*8] = s;
        }
    }
    __syncthreads();
#pragma unroll
    for (int i = 0; i < K; i++) v[i] = sbuf[i*8];
    __syncthreads();
}

// ---------------- Winograd transforms ----------------
__device__ __forceinline__ void bt6(const float* in, float* out) {
    out[0] =  4.f*in[0] - 5.f*in[2] + in[4];
    out[1] = -4.f*in[1] - 4.f*in[2] + in[3] + in[4];
    out[2] =  4.f*in[1] - 4.f*in[2] - in[3] + in[4];
    out[3] = -2.f*in[1] -     in[2] + 2.f*in[3] + in[4];
    out[4] =  2.f*in[1] -     in[2] - 2.f*in[3] + in[4];
    out[5] =  4.f*in[1] - 5.f*in[3] + in[5];
}
__device__ __forceinline__ void g6(const float* in, float* out) {
    out[0] = 0.25f*in[0];
    out[1] = -(in[0] + in[1] + in[2]) * (1.f/6.f);
    out[2] = (-in[0] + in[1] - in[2]) * (1.f/6.f);
    out[3] = in[0]*(1.f/24.f) + in[1]*(1.f/12.f) + in[2]*(1.f/6.f);
    out[4] = in[0]*(1.f/24.f) - in[1]*(1.f/12.f) + in[2]*(1.f/6.f);
    out[5] = in[2];
}
__device__ __forceinline__ void at6(const float* in, float* out) {
    out[0] = in[0] + in[1] + in[2] + in[3] + in[4];
    out[1] = in[1] - in[2] + 2.f*(in[3] - in[4]);
    out[2] = in[1] + in[2] + 4.f*(in[3] + in[4]);
    out[3] = in[1] - in[2] + 8.f*(in[3] - in[4]) + in[5];
}

// ---------------- U = G z G^T (+ fused z column norms), one weight set ----------------
__global__ void wino_u(const float* __restrict__ z, int which) {
    __shared__ float sb[8];
    __nv_bfloat16* uh = which ? g_uhi2 : g_uhi1;
    __nv_bfloat16* ul = which ? g_ulo2 : g_ulo1;
    int co = blockIdx.x, ci = threadIdx.x;
    float g[3][3];
    float nsum = 0.f;
#pragma unroll
    for (int i = 0; i < 3; i++)
#pragma unroll
        for (int j = 0; j < 3; j++) {
            float w = z[(size_t)((i*3 + j)*256 + ci)*256 + co];
            g[i][j] = w;
            nsum += w*w;
        }
    float r1[1] = { nsum };
    blockReduceK<1>(r1, sb);
    if (ci == 0) g_zn[which*256 + co] = sqrtf(fmaxf(r1[0], EPSF));

    float t[6][3];
#pragma unroll
    for (int j = 0; j < 3; j++) {
        float in[3] = { g[0][j], g[1][j], g[2][j] };
        float out[6];
        g6(in, out);
#pragma unroll
        for (int a = 0; a < 6; a++) t[a][j] = out[a];
    }
#pragma unroll
    for (int a = 0; a < 6; a++) {
        float out[6];
        g6(t[a], out);
#pragma unroll
        for (int b = 0; b < 6; b++) {
            float u = out[b];
            __nv_bfloat16 hi = __float2bfloat16(u);
            size_t idx = ((size_t)((a*6 + b)*256 + co))*256 + ci;
            uh[idx] = hi;
            ul[idx] = __float2bfloat16(u - __bfloat162float(hi));
        }
    }
}

// ---------------- V = B^T d B per tile ----------------
__global__ void wino_in() {
    int t = blockIdx.x, ci = threadIdx.x;
    int b = t >> 6, tr = (t >> 3) & 7, tc = t & 7;
    int base = b << 10;
    float d[6][6];
#pragma unroll
    for (int y = 0; y < 6; y++) {
        int iy = 4*tr - 1 + y;
#pragma unroll
        for (int x = 0; x < 6; x++) {
            int ix = 4*tc - 1 + x;
            bool ok = ((unsigned)iy < 32u) && ((unsigned)ix < 32u);
            d[y][x] = ok ? g_v[(size_t)(base + iy*32 + ix)*256 + ci] : 0.f;
        }
    }
    float e[6][6];
#pragma unroll
    for (int x = 0; x < 6; x++) {
        float in[6] = { d[0][x], d[1][x], d[2][x], d[3][x], d[4][x], d[5][x] };
        float out[6];
        bt6(in, out);
#pragma unroll
        for (int a = 0; a < 6; a++) e[a][x] = out[a];
    }
#pragma unroll
    for (int a = 0; a < 6; a++) {
        float out[6];
        bt6(e[a], out);
#pragma unroll
        for (int bb = 0; bb < 6; bb++) {
            float v = out[bb];
            __nv_bfloat16 hi = __float2bfloat16(v);
            size_t idx = ((size_t)((a*6 + bb)*NTIL + t))*256 + ci;
            g_Vhi[idx] = hi;
            g_Vlo[idx] = __float2bfloat16(v - __bfloat162float(hi));
        }
    }
}

// ---------------- batched Winograd GEMM ----------------
__global__ void __launch_bounds__(256, 2) wino_gemm(int which) {
    extern __shared__ __align__(16) char dsm[];
    uint32_t sbase = smem_u32(dsm);

    const __nv_bfloat16* Bh = which ? g_uhi2 : g_uhi1;
    const __nv_bfloat16* Bl = which ? g_ulo2 : g_ulo1;
    int t0  = blockIdx.x << 7;
    int nh  = blockIdx.y;
    int pos = blockIdx.z;

    int tid = threadIdx.x, wid = tid >> 5, l = tid & 31;

    int c4 = tid & 3;
    int r0 = tid >> 2;
    uint32_t ph0 = swz(r0, c4), ph1 = swz(r0 + 64, c4);
    const __nv_bfloat16* Abase_hi = g_Vhi + ((size_t)pos*NTIL + t0)*256;
    const __nv_bfloat16* Abase_lo = g_Vlo + ((size_t)pos*NTIL + t0)*256;
    const __nv_bfloat16* Bbase_hi = Bh + ((size_t)pos*256 + nh*128)*256;
    const __nv_bfloat16* Bbase_lo = Bl + ((size_t)pos*256 + nh*128)*256;
    size_t a0 = (size_t)r0*256 + c4*8, a1 = (size_t)(r0 + 64)*256 + c4*8;

    int m0 = (wid & 3) << 5;
    int n0w = (wid >> 2) << 6;
    int mi = l >> 3;
    int rA = m0 + ((mi & 1) << 3) + (l & 7);
    uint32_t qA0 = swz(rA, mi >> 1);
    int rB = n0w + (((mi >> 1) & 1) << 3) + (l & 7);
    uint32_t qB0 = swz(rB, mi & 1);

    float acc[2][8][4];
#pragma unroll
    for (int i = 0; i < 2; i++)
#pragma unroll
        for (int j = 0; j < 8; j++)
#pragma unroll
            for (int k = 0; k < 4; k++) acc[i][j][k] = 0.f;

    auto load_chunk = [&](int kc, int stage) {
        size_t coff = (size_t)(kc << 5);
        uint32_t st = sbase + (uint32_t)stage*STAGE_BYTES;
        cpa16(st + ph0,         Abase_hi + a0 + coff);
        cpa16(st + 8192 + ph0,  Abase_lo + a0 + coff);
        cpa16(st + ph1,         Abase_hi + a1 + coff);
        cpa16(st + 8192 + ph1,  Abase_lo + a1 + coff);
        cpa16(st + 16384 + ph0, Bbase_hi + a0 + coff);
        cpa16(st + 24576 + ph0, Bbase_lo + a0 + coff);
        cpa16(st + 16384 + ph1, Bbase_hi + a1 + coff);
        cpa16(st + 24576 + ph1, Bbase_lo + a1 + coff);
        cp_commit();
    };

    load_chunk(0, 0);
    load_chunk(1, 1);

    for (int kc = 0; kc < 8; kc++) {
        int stage = kc % 3;
        if (kc < 6) cp_wait<1>(); else cp_wait<0>();
        __syncthreads();
        if (kc + 2 < 8) load_chunk(kc + 2, (kc + 2) % 3);

        uint32_t st = sbase + (uint32_t)stage*STAGE_BYTES;
        uint32_t Ahi = st, Alo = st + 8192, Bhi = st + 16384, Blo = st + 24576;
#pragma unroll
        for (int ks = 0; ks < 2; ks++) {
            uint32_t kx = (uint32_t)(ks << 5);
            uint32_t qa = qA0 ^ kx, qb = qB0 ^ kx;
            uint32_t ah[8], al[8], bbv[16];
            ldsm4(ah,     Ahi + qa);
            ldsm4(ah + 4, Ahi + qa + 1024);
            ldsm4(al,     Alo + qa);
            ldsm4(al + 4, Alo + qa + 1024);
#pragma unroll
            for (int j = 0; j < 4; j++) ldsm4(bbv + j*4, Bhi + qb + j*1024);
#pragma unroll
            for (int nf = 0; nf < 8; nf++) {
                const uint32_t* bp = bbv + nf*2;
                mma16816(acc[0][nf], ah,     bp);
                mma16816(acc[1][nf], ah + 4, bp);
            }
#pragma unroll
            for (int nf = 0; nf < 8; nf++) {
                const uint32_t* bp = bbv + nf*2;
                mma16816(acc[0][nf], al,     bp);
                mma16816(acc[1][nf], al + 4, bp);
            }
#pragma unroll
            for (int j = 0; j < 4; j++) ldsm4(bbv + j*4, Blo + qb + j*1024);
#pragma unroll
            for (int nf = 0; nf < 8; nf++) {
                const uint32_t* bp = bbv + nf*2;
                mma16816(acc[0][nf], ah,     bp);
                mma16816(acc[1][nf], ah + 4, bp);
            }
        }
    }
    __syncthreads();

    float* ybuf = (float*)dsm;
    int row0 = m0 + (l >> 2);
    int col0 = n0w + ((l & 3) << 1);
#pragma unroll
    for (int mf = 0; mf < 2; mf++)
#pragma unroll
        for (int nf = 0; nf < 8; nf++)
#pragma unroll
            for (int hf = 0; hf < 2; hf++) {
                int r = row0 + mf*16 + hf*8;
                *(float2*)&ybuf[r*YST2 + col0 + nf*8] =
                    make_float2(acc[mf][nf][hf*2], acc[mf][nf][hf*2 + 1]);
            }
    __syncthreads();
    {
        int row = tid >> 1, q = tid & 1;
        const float4* yr = (const float4*)(ybuf + row*YST2 + q*64);
        float4* dst = (float4*)(g_m + ((size_t)pos*NTIL + t0 + row)*256 + nh*128 + q*64);
#pragma unroll
        for (int i = 0; i < 16; i++) dst[i] = yr[i];
    }
}

// ---------------- pre2 (+ fused xT) ----------------
__global__ void pre2_kernel(const float* __restrict__ x, float scale) {
    __shared__ float sx[256][33];
    int tid = threadIdx.x, lane = tid & 31, w8 = tid >> 5;
    int p0 = blockIdx.x * 32;
    int b = p0 >> 10, hw0 = p0 & 1023;
#pragma unroll 8
    for (int i = 0; i < 32; i++) {
        int c = i*8 + w8;
        sx[c][lane] = x[(size_t)(b*256 + c)*1024 + hw0 + lane];
    }
    __syncthreads();
#pragma unroll 8
    for (int pl = 0; pl < 32; pl++)
        g_xl[(size_t)(p0 + pl)*256 + tid] = sx[tid][pl];
#pragma unroll
    for (int pp = 0; pp < 4; pp++) {
        int pl = w8*4 + pp;
        int p = p0 + pl;
        float xv[8];
#pragma unroll
        for (int i = 0; i < 8; i++) xv[i] = sx[lane*8 + i][pl];
        float q = 0.f;
#pragma unroll
        for (int i = 0; i < 8; i++) q += xv[i]*xv[i];
        float n2 = warpSum(q);
        float n = sqrtf(fmaxf(n2, EPSF));
        float f = atanhf(fminf(n, CLIP1)) / n * scale;
        float4 o0 = make_float4(f*xv[0], f*xv[1], f*xv[2], f*xv[3]);
        float4 o1 = make_float4(f*xv[4], f*xv[5], f*xv[6], f*xv[7]);
        float* dst = g_v + (size_t)p*256 + lane*8;
        *(float4*)dst = o0;
        *(float4*)(dst + 4) = o1;
        if (lane == 0) g_q2[p] = f*f*n2;
    }
}

// ---------------- per-pixel s ----------------
__device__ __forceinline__ float s_from_q2(int p) {
    int h = (p >> 5) & 31, w = p & 31;
    float np2 = 0.f;
#pragma unroll
    for (int dy = -1; dy <= 1; dy++)
#pragma unroll
        for (int dx = -1; dx <= 1; dx++) {
            int sh = h + dy, sw = w + dx;
            if ((unsigned)sh < 32u && (unsigned)sw < 32u) np2 += g_q2[p + dy*32 + dx];
        }
    float np = sqrtf(fmaxf(np2, EPSF));
    float th = tanhf(np);
    float uf = th / np;
    float un = th;
    if (un > MAXN) { uf *= MAXN/un; un = MAXN; }
    float lam = 2.0f / fmaxf(1.0f - un*un, EPSF);
    return lam * uf;
}

// ---------------- output transform + fused s + FC epilogue ----------------
__global__ void wino_out(int znoff) {
    __shared__ float ss[16];
    int t = blockIdx.x, co = threadIdx.x;
    int b = t >> 6, tr = (t >> 3) & 7, tc = t & 7;
    int prow = (b << 10) + (4*tr)*32 + 4*tc;
    if (co < 16) {
        int r = co >> 2, c = co & 3;
        ss[co] = s_from_q2(prow + r*32 + c);
    }
    float m[36];
#pragma unroll
    for (int pos = 0; pos < 36; pos++)
        m[pos] = g_m[((size_t)pos*NTIL + t)*256 + co];
    float Z[4][6];
#pragma unroll
    for (int bb = 0; bb < 6; bb++) {
        float in[6] = { m[bb], m[6+bb], m[12+bb], m[18+bb], m[24+bb], m[30+bb] };
        float out[4];
        at6(in, out);
#pragma unroll
        for (int r = 0; r < 4; r++) Z[r][bb] = out[r];
    }
    float zn = g_zn[znoff + co];
    __syncthreads();
#pragma unroll
    for (int r = 0; r < 4; r++) {
        float Y[4];
        at6(Z[r], Y);
#pragma unroll
        for (int c = 0; c < 4; c++) {
            int p = prow + r*32 + c;
            float s = ss[r*4 + c];
            float tt = Y[c] * s / zn;
            float y = sinhf(2.0f * zn * asinhf(tt));
            g_h[(size_t)p*256 + co] = y;
        }
    }
}

// ---------------- BN phase 1: 256 blocks x 64 pixels ----------------
__global__ void bnred_w() {
    __shared__ float sm[8][256];
    __shared__ float sd[8];
    int wid = threadIdx.x >> 5, lid = threadIdx.x & 31;
    int p0 = blockIdx.x * 64;
    float accm[8] = {0,0,0,0,0,0,0,0};
    float accd = 0.f;
    for (int i = 0; i < 8; i++) {
        int p = p0 + wid*8 + i;
        const float4* row = (const float4*)(g_h + (size_t)p*256 + lid*8);
        float4 a = row[0], c = row[1];
        float v[8] = {a.x,a.y,a.z,a.w,c.x,c.y,c.z,c.w};
        float q = 0.f;
#pragma unroll
        for (int j = 0; j < 8; j++) q += v[j]*v[j];
        float tot = warpSum(q);
        float inv = 1.0f / (1.0f + sqrtf(1.0f + tot));
        float n2 = tot*inv*inv;
        float lam = 2.0f / fmaxf(1.0f - n2, EPSF);
        float li = lam * inv;
#pragma unroll
        for (int j = 0; j < 8; j++) accm[j] += li * v[j];
        accd += lam - 1.0f;
    }
#pragma unroll
    for (int j = 0; j < 8; j++) sm[wid][lid*8 + j] = accm[j];
    if (lid == 0) sd[wid] = accd;
    __syncthreads();
    int c = threadIdx.x;
    float s = 0.f;
    for (int w = 0; w < 8; w++) s += sm[w][c];
    g_pm[blockIdx.x*256 + c] = s;
    if (c == 0) {
        float d = 0.f;
        for (int w = 0; w < 8; w++) d += sd[w];
        g_pd[blockIdx.x] = d;
    }
}

// ---------------- BN phase 2 ----------------
__global__ void bnmu_kernel(const float* __restrict__ bias) {
    __shared__ float sb[24];
    int c = threadIdx.x;
    float msum = 0.f;
    for (int g = 0; g < 256; g++) msum += g_pm[g*256 + c];
    float dv = g_pd[c];
    float r1[1] = { dv };
    blockReduceK<1>(r1, sb);
    float den = fmaxf(r1[0], EPSF);
    float m = msum / den;
    float r2[1] = { m*m };
    blockReduceK<1>(r2, sb);
    float nm = sqrtf(fmaxf(r2[0], EPSF));
    float fac = tanhf(0.5f * atanhf(fminf(nm, CLIP1))) / nm;
    float muc = fac * m;
    g_mu[c] = muc;
    float bc = bias[c];
    float r3[3] = { muc*muc, bc*bc, bc*muc };
    blockReduceK<3>(r3, sb);
    if (c == 0) {
        float mu2 = r3[0], b2 = r3[1], bm = r3[2];
        g_sc[0] = mu2;
        g_sc[1] = 2.0f / fmaxf(1.0f - mu2, EPSF);
        g_sc[2] = b2;
        g_sc[3] = 2.0f / fmaxf(1.0f - b2, EPSF);
        g_sc[4] = bm;
    }
}

// ---------------- BN phase 3: 256 blocks x 64 pixels + fused finalize ----------------
__global__ void bnvar_w(const float* __restrict__ weight) {
    __shared__ float sv[8];
    __shared__ int slast;
    int wid = threadIdx.x >> 5, lid = threadIdx.x & 31;
    int p0 = blockIdx.x * 64;
    float mu8[8];
#pragma unroll
    for (int j = 0; j < 8; j++) mu8[j] = g_mu[lid*8 + j];
    float mu2 = g_sc[0];
    float acc = 0.f;
    for (int i = 0; i < 8; i++) {
        int p = p0 + wid*8 + i;
        const float4* row = (const float4*)(g_h + (size_t)p*256 + lid*8);
        float4 a = row[0], cc = row[1];
        float v[8] = {a.x,a.y,a.z,a.w,cc.x,cc.y,cc.z,cc.w};
        float q1 = 0.f, q2 = 0.f;
#pragma unroll
        for (int j = 0; j < 8; j++) { q1 += v[j]*v[j]; q2 += v[j]*mu8[j]; }
        float tot = warpSum(q1);
        float ipr = warpSum(q2);
        float inv = 1.0f / (1.0f + sqrtf(1.0f + tot));
        float xp2 = tot*inv*inv;
        float ip  = ipr*inv;
        float A = 1.0f - 2.0f*ip + mu2;
        float B = 1.0f - xp2;
        float nn = fmaxf(A*A*xp2 - 2.0f*A*B*ip + B*B*mu2, 0.f);
        float den = fmaxf(1.0f - 2.0f*ip + xp2*mu2, EPSF);
        float nr = sqrtf(fmaxf(nn/(den*den), EPSF));
        float dd = 2.0f * atanhf(fminf(nr, CLIP1));
        acc += dd*dd;
    }
    if (lid == 0) sv[wid] = acc;
    __syncthreads();
    if (threadIdx.x == 0) {
        float s = 0.f;
        for (int w = 0; w < 8; w++) s += sv[w];
        g_pv[blockIdx.x] = s;
        __threadfence();
        slast = (atomicAdd(&g_ctr, 1) == 255);
    }
    __syncthreads();
    if (slast) {
        // last block: reduce all 256 partials deterministically
        float v = g_pv[threadIdx.x];
        __shared__ float sb[8];
        float r[1] = { v };
        blockReduceK<1>(r, sb);
        if (threadIdx.x == 0) {
            float var = r[0] / 16384.0f;
            g_sc[5] = sqrtf(weight[0] / fmaxf(var, EPSF));
            g_ctr = 0;   // reset for next launch / graph replay
        }
    }
}

// ---------------- shared BN point transform ----------------
__device__ __forceinline__ float bn_point_w(const float* xv, const float* mu8, const float* b8,
                                            float* hc) {
    float mu2 = g_sc[0], lam_mu = g_sc[1], b2 = g_sc[2], lam_b = g_sc[3],
          bm = g_sc[4], rstd = g_sc[5];
    float s0 = 0.f, s1 = 0.f, s2 = 0.f;
#pragma unroll
    for (int i = 0; i < 8; i++) { s0 += xv[i]*xv[i]; s1 += mu8[i]*xv[i]; s2 += b8[i]*xv[i]; }
    float xp2 = warpSum(s0), ip = warpSum(s1), bx = warpSum(s2);
    float A  = 1.0f - 2.0f*ip + xp2;
    float Bc = 1.0f - mu2;
    float den = fmaxf(1.0f - 2.0f*ip + mu2*xp2, EPSF);
    float nd2 = fmaxf(A*A*mu2 - 2.0f*A*Bc*ip + Bc*Bc*xp2, 0.f) / (den*den);
    float nd = sqrtf(fmaxf(nd2, EPSF));
    float cv = (2.0f/lam_mu) * atanhf(fminf(nd, CLIP1)) / nd;
    float uw = cv * (Bc*bx - A*bm) / den;
    float vw = cv * (A*mu2 - Bc*ip) / den;
    float av  = -uw*mu2 - vw - 2.0f*bm*vw;
    float bv2 = -vw*b2 + uw;
    float dgy = fmaxf(1.0f - 2.0f*bm + b2*mu2, EPSF);
    float fac = (lam_mu / lam_b) * rstd;
    float uc[8];
    float t0 = 0.f, t1 = 0.f;
#pragma unroll
    for (int i = 0; i < 8; i++) {
        float vc = cv * (Bc*xv[i] - A*mu8[i]) / den;
        uc[i] = (vc + 2.0f*(av*b8[i] - bv2*mu8[i]) / dgy) * fac;
        t0 += uc[i]*uc[i];
        t1 += b8[i]*uc[i];
    }
    float u2 = warpSum(t0), bu = warpSum(t1);
    float nu = sqrtf(fmaxf(u2, EPSF));
    float tf = tanhf(0.5f * lam_b * nu) / nu;
    float s2m = tf*tf*u2;
    float bs  = tf*bu;
    float A3 = 1.0f + 2.0f*bs + s2m, B3 = 1.0f - b2;
    float den3 = fmaxf(1.0f + 2.0f*bs + b2*s2m, EPSF);
#pragma unroll
    for (int i = 0; i < 8; i++) hc[i] = (A3*b8[i] + B3*tf*uc[i]) / den3;
    float nh2 = fmaxf(A3*A3*b2 + 2.0f*A3*B3*bs + B3*B3*s2m, 0.f) / (den3*den3);
    float nh = sqrtf(fmaxf(nh2, EPSF));
    if (nh > MAXN) {
        float q = MAXN / nh;
#pragma unroll
        for (int i = 0; i < 8; i++) hc[i] *= q;
        nh = MAXN;
    }
    return nh;
}

// ---------------- BN apply + hrelu + pre-for-conv2 ----------------
__global__ void bnapply_w(const float* __restrict__ bias, float scale) {
    int wid = threadIdx.x >> 5, lid = threadIdx.x & 31;
    int p = blockIdx.x * 8 + wid;
    const float4* row = (const float4*)(g_h + (size_t)p*256 + lid*8);
    float4 a = row[0], cc = row[1];
    float xv[8] = {a.x,a.y,a.z,a.w,cc.x,cc.y,cc.z,cc.w};
    float qy = 0.f;
#pragma unroll
    for (int i = 0; i < 8; i++) qy += xv[i]*xv[i];
    float tot = warpSum(qy);
    float inv = 1.0f / (1.0f + sqrtf(1.0f + tot));
#pragma unroll
    for (int i = 0; i < 8; i++) xv[i] *= inv;
    float mu8[8], b8[8];
#pragma unroll
    for (int j = 0; j < 8; j++) { mu8[j] = g_mu[lid*8 + j]; b8[j] = bias[lid*8 + j]; }
    float hc[8];
    float nh = bn_point_w(xv, mu8, b8, hc);
    float lf = atanhf(fminf(nh, CLIP1)) / nh;
    float rc[8];
    float q = 0.f;
#pragma unroll
    for (int i = 0; i < 8; i++) { rc[i] = fmaxf(lf*hc[i], 0.f); q += rc[i]*rc[i]; }
    float rs = warpSum(q);
    float nr = sqrtf(fmaxf(rs, EPSF));
    float ef = tanhf(nr) / nr;
    float nhr = sqrtf(fmaxf(ef*ef*rs, EPSF));
    float adj = 1.0f;
    if (nhr > MAXN) { adj = MAXN/nhr; nhr = MAXN; }
    float f3 = atanhf(fminf(nhr, CLIP1)) / nhr * scale;
    float g = f3 * ef * adj;
    float4 o0 = make_float4(g*rc[0], g*rc[1], g*rc[2], g*rc[3]);
    float4 o1 = make_float4(g*rc[4], g*rc[5], g*rc[6], g*rc[7]);
    float* dst = g_v + (size_t)p*256 + lid*8;
    *(float4*)dst = o0;
    *(float4*)(dst + 4) = o1;
    if (lid == 0) g_q2[p] = f3*f3*nhr*nhr;
}

// ---------------- BN2 apply + residual + hrelu + staged NCHW out ----------------
__global__ void final2_kernel(const float* __restrict__ bias, float* __restrict__ out) {
    __shared__ float so[256][33];
    int tid = threadIdx.x, lane = tid & 31, w8 = tid >> 5;
    int p0 = blockIdx.x * 32;
    int b = p0 >> 10, hw0 = p0 & 1023;
    float mu8[8], b8[8];
#pragma unroll
    for (int j = 0; j < 8; j++) { mu8[j] = g_mu[lane*8 + j]; b8[j] = bias[lane*8 + j]; }
#pragma unroll
    for (int pp = 0; pp < 4; pp++) {
        int pl = w8*4 + pp;
        int p = p0 + pl;
        const float4* row = (const float4*)(g_h + (size_t)p*256 + lane*8);
        float4 a = row[0], cc = row[1];
        float xv[8] = {a.x,a.y,a.z,a.w,cc.x,cc.y,cc.z,cc.w};
        float qy = 0.f;
#pragma unroll
        for (int i = 0; i < 8; i++) qy += xv[i]*xv[i];
        float tot = warpSum(qy);
        float inv = 1.0f / (1.0f + sqrtf(1.0f + tot));
#pragma unroll
        for (int i = 0; i < 8; i++) xv[i] *= inv;
        float hc[8];
        float nh = bn_point_w(xv, mu8, b8, hc);
        const float4* rrow = (const float4*)(g_xl + (size_t)p*256 + lane*8);
        float4 r0 = rrow[0], r1 = rrow[1];
        float res[8] = {r0.x,r0.y,r0.z,r0.w,r1.x,r1.y,r1.z,r1.w};
        float q1 = 0.f, q2 = 0.f;
#pragma unroll
        for (int i = 0; i < 8; i++) { q1 += res[i]*res[i]; q2 += hc[i]*res[i]; }
        float y2 = warpSum(q1), xy = warpSum(q2);
        float x2 = nh*nh;
        float A4 = 1.0f + 2.0f*xy + y2, B4 = 1.0f - x2;
        float den4 = fmaxf(1.0f + 2.0f*xy + x2*y2, EPSF);
        float hm[8];
#pragma unroll
        for (int i = 0; i < 8; i++) hm[i] = (A4*hc[i] + B4*res[i]) / den4;
        float nm2 = fmaxf(A4*A4*x2 + 2.0f*A4*B4*xy + B4*B4*y2, 0.f) / (den4*den4);
        float nmv = sqrtf(fmaxf(nm2, EPSF));
        float lf = atanhf(fminf(nmv, CLIP1)) / nmv;
        float rc[8];
        float q = 0.f;
#pragma unroll
        for (int i = 0; i < 8; i++) { rc[i] = fmaxf(lf*hm[i], 0.f); q += rc[i]*rc[i]; }
        float rs = warpSum(q);
        float nr = sqrtf(fmaxf(rs, EPSF));
        float ef = tanhf(nr) / nr;
        float nhr = sqrtf(fmaxf(ef*ef*rs, EPSF));
        float adj = (nhr > MAXN) ? MAXN/nhr : 1.0f;
#pragma unroll
        for (int i = 0; i < 8; i++) so[lane*8 + i][pl] = ef * adj * rc[i];
    }
    __syncthreads();
#pragma unroll 8
    for (int i = 0; i < 32; i++) {
        int c = i*8 + w8;
        out[(size_t)(b*256 + c)*1024 + hw0 + lane] = so[c][lane];
    }
}

// ---------------- launcher ----------------
extern "C" void kernel_launch(void* const* d_in, const int* in_sizes, int n_in,
                              void* d_out, int out_size) {
    const float* x  = (const float*)d_in[0];
    const float* z1 = (const float*)d_in[1];
    const float* z2 = (const float*)d_in[2];
    const float* w1 = (const float*)d_in[3];
    const float* b1 = (const float*)d_in[4];
    const float* w2 = (const float*)d_in[5];
    const float* b2 = (const float*)d_in[6];
    float* out = (float*)d_out;

    // scale = Beta(1152, 0.5) / Beta(128, 0.5)
    double lg = lgamma(1152.0) - lgamma(1152.5) - lgamma(128.0) + lgamma(128.5);
    float scale = (float)exp(lg);

    static int smem_set = 0;
    if (!smem_set) {
        cudaFuncSetAttribute(wino_gemm, cudaFuncAttributeMaxDynamicSharedMemorySize, CONV_SMEM);
        smem_set = 1;
    }

    dim3 ggrid(8, 2, 36);

    wino_u<<<256, 256>>>(z1, 0);                 // 0
    wino_u<<<256, 256>>>(z2, 1);                 // 1
    pre2_kernel<<<PNUM/32, 256>>>(x, scale);     // 2
    wino_in<<<NTIL, 256>>>();                    // 3  <- ncu capture target this round
    wino_gemm<<<ggrid, 256, CONV_SMEM>>>(0);
    wino_out<<<NTIL, 256>>>(0);

    bnred_w<<<256, 256>>>();
    bnmu_kernel<<<1, 256>>>(b1);
    bnvar_w<<<256, 256>>>(w1);
    bnapply_w<<<PNUM/8, 256>>>(b1, scale);

    wino_in<<<NTIL, 256>>>();
    wino_gemm<<<ggrid, 256, CONV_SMEM>>>(1);
    wino_out<<<NTIL, 256>>>(256);

    bnred_w<<<256, 256>>>();
    bnmu_kernel<<<1, 256>>>(b2);
    bnvar_w<<<256, 256>>>(w2);
    final2_kernel<<<PNUM/32, 256>>>(b2, out);
}

// round 10
// speedup vs baseline: 1.9140x; 1.0233x over previous
#include <cuda_runtime.h>
#include <cuda_bf16.h>
#include <math.h>
#include <stdint.h>

// Problem constants: B=16, C=256, H=W=32
#define PNUM 16384
#define CNUM 256
#define CLIP1 0.9999999f
#define MAXN  0.99999f
#define EPSF  1e-15f

#define NPOS 36
#define NTIL 1024
#define STAGE_BYTES 24576u       // Ahi 8K + Alo 8K + Bhi 4K + Blo 4K
#define YST3  68
#define CONV_SMEM (3*24576)      // 72 KB -> 3 CTAs/SM

// ---------------- device scratch ----------------
__device__ __align__(16) float g_v [PNUM*CNUM];
__device__ __align__(16) __nv_bfloat16 g_Vhi[NPOS*NTIL*CNUM];
__device__ __align__(16) __nv_bfloat16 g_Vlo[NPOS*NTIL*CNUM];
__device__ __align__(16) __nv_bfloat16 g_uhi1[NPOS*CNUM*CNUM];
__device__ __align__(16) __nv_bfloat16 g_ulo1[NPOS*CNUM*CNUM];
__device__ __align__(16) __nv_bfloat16 g_uhi2[NPOS*CNUM*CNUM];
__device__ __align__(16) __nv_bfloat16 g_ulo2[NPOS*CNUM*CNUM];
__device__ __align__(16) float g_m [NPOS*NTIL*CNUM];
__device__ __align__(16) float g_h [PNUM*CNUM];
__device__ __align__(16) float g_xl[PNUM*CNUM];
__device__ float g_q2[PNUM];
__device__ float g_zn[512];
__device__ float g_pm [NTIL*CNUM];   // per-tile-block BN partials (from wino_out)
__device__ float g_pm2[8*CNUM];
__device__ float g_pd[NTIL];
__device__ float g_pv[256];
__device__ float g_mu[CNUM];
__device__ float g_sc[8];
__device__ int   g_ctr  = 0;
__device__ int   g_ctr2 = 0;

// ---------------- PTX helpers ----------------
__device__ __forceinline__ uint32_t smem_u32(const void* p) {
    uint32_t a;
    asm("{ .reg .u64 t; cvta.to.shared.u64 t, %1; cvt.u32.u64 %0, t; }" : "=r"(a) : "l"(p));
    return a;
}
__device__ __forceinline__ void cpa16(uint32_t dst, const void* src) {
    asm volatile("cp.async.cg.shared.global [%0], [%1], 16;" :: "r"(dst), "l"(src) : "memory");
}
__device__ __forceinline__ void cp_commit() {
    asm volatile("cp.async.commit_group;" ::: "memory");
}
template<int N>
__device__ __forceinline__ void cp_wait() {
    asm volatile("cp.async.wait_group %0;" :: "n"(N) : "memory");
}
__device__ __forceinline__ void ldsm4(uint32_t* r, uint32_t addr) {
    asm volatile("ldmatrix.sync.aligned.m8n8.x4.shared.b16 {%0,%1,%2,%3}, [%4];"
        : "=r"(r[0]), "=r"(r[1]), "=r"(r[2]), "=r"(r[3]) : "r"(addr));
}
__device__ __forceinline__ void mma16816(float* d, const uint32_t* a, const uint32_t* b) {
    asm volatile("mma.sync.aligned.m16n8k16.row.col.f32.bf16.bf16.f32 "
        "{%0,%1,%2,%3}, {%4,%5,%6,%7}, {%8,%9}, {%0,%1,%2,%3};"
        : "+f"(d[0]), "+f"(d[1]), "+f"(d[2]), "+f"(d[3])
        : "r"(a[0]), "r"(a[1]), "r"(a[2]), "r"(a[3]), "r"(b[0]), "r"(b[1]));
}
__device__ __forceinline__ uint32_t swz(int r, int c) {
    return (uint32_t)(((r >> 1) << 7) | (((((r & 1) << 2) | c) ^ ((r >> 1) & 7)) << 4));
}

// ---------------- reductions ----------------
__device__ __forceinline__ float warpSum(float v) {
#pragma unroll
    for (int o = 16; o > 0; o >>= 1) v += __shfl_xor_sync(0xffffffffu, v, o);
    return v;
}
template<int K>
__device__ __forceinline__ void blockReduceK(float* v, float* sbuf) {
    int tid = threadIdx.x, lane = tid & 31, wid = tid >> 5;
#pragma unroll
    for (int i = 0; i < K; i++) {
        float x = v[i];
#pragma unroll
        for (int o = 16; o > 0; o >>= 1) x += __shfl_down_sync(0xffffffffu, x, o);
        if (lane == 0) sbuf[i*8 + wid] = x;
    }
    __syncthreads();
    if (tid == 0) {
#pragma unroll
        for (int i = 0; i < K; i++) {
            float s = sbuf[i*8];
            for (int w = 1; w < 8; w++) s += sbuf[i*8 + w];
            sbuf[i*8] = s;
        }
    }
    __syncthreads();
#pragma unroll
    for (int i = 0; i < K; i++) v[i] = sbuf[i*8];
    __syncthreads();
}

// ---------------- Winograd transforms ----------------
__device__ __forceinline__ void bt6(const float* in, float* out) {
    out[0] =  4.f*in[0] - 5.f*in[2] + in[4];
    out[1] = -4.f*in[1] - 4.f*in[2] + in[3] + in[4];
    out[2] =  4.f*in[1] - 4.f*in[2] - in[3] + in[4];
    out[3] = -2.f*in[1] -     in[2] + 2.f*in[3] + in[4];
    out[4] =  2.f*in[1] -     in[2] - 2.f*in[3] + in[4];
    out[5] =  4.f*in[1] - 5.f*in[3] + in[5];
}
__device__ __forceinline__ void g6(const float* in, float* out) {
    out[0] = 0.25f*in[0];
    out[1] = -(in[0] + in[1] + in[2]) * (1.f/6.f);
    out[2] = (-in[0] + in[1] - in[2]) * (1.f/6.f);
    out[3] = in[0]*(1.f/24.f) + in[1]*(1.f/12.f) + in[2]*(1.f/6.f);
    out[4] = in[0]*(1.f/24.f) - in[1]*(1.f/12.f) + in[2]*(1.f/6.f);
    out[5] = in[2];
}
__device__ __forceinline__ void at6(const float* in, float* out) {
    out[0] = in[0] + in[1] + in[2] + in[3] + in[4];
    out[1] = in[1] - in[2] + 2.f*(in[3] - in[4]);
    out[2] = in[1] + in[2] + 4.f*(in[3] + in[4]);
    out[3] = in[1] - in[2] + 8.f*(in[3] - in[4]) + in[5];
}

// ---------------- U = G z G^T (+ fused z column norms) ----------------
__global__ void wino_u(const float* __restrict__ z, int which) {
    __shared__ float sb[8];
    __nv_bfloat16* uh = which ? g_uhi2 : g_uhi1;
    __nv_bfloat16* ul = which ? g_ulo2 : g_ulo1;
    int co = blockIdx.x, ci = threadIdx.x;
    float g[3][3];
    float nsum = 0.f;
#pragma unroll
    for (int i = 0; i < 3; i++)
#pragma unroll
        for (int j = 0; j < 3; j++) {
            float w = z[(size_t)((i*3 + j)*256 + ci)*256 + co];
            g[i][j] = w;
            nsum += w*w;
        }
    float r1[1] = { nsum };
    blockReduceK<1>(r1, sb);
    if (ci == 0) g_zn[which*256 + co] = sqrtf(fmaxf(r1[0], EPSF));

    float t[6][3];
#pragma unroll
    for (int j = 0; j < 3; j++) {
        float in[3] = { g[0][j], g[1][j], g[2][j] };
        float out[6];
        g6(in, out);
#pragma unroll
        for (int a = 0; a < 6; a++) t[a][j] = out[a];
    }
#pragma unroll
    for (int a = 0; a < 6; a++) {
        float out[6];
        g6(t[a], out);
#pragma unroll
        for (int b = 0; b < 6; b++) {
            float u = out[b];
            __nv_bfloat16 hi = __float2bfloat16(u);
            size_t idx = ((size_t)((a*6 + b)*256 + co))*256 + ci;
            uh[idx] = hi;
            ul[idx] = __float2bfloat16(u - __bfloat162float(hi));
        }
    }
}

// ---------------- V = B^T d B per tile ----------------
__global__ void wino_in() {
    int t = blockIdx.x, ci = threadIdx.x;
    int b = t >> 6, tr = (t >> 3) & 7, tc = t & 7;
    int base = b << 10;
    float d[6][6];
#pragma unroll
    for (int y = 0; y < 6; y++) {
        int iy = 4*tr - 1 + y;
#pragma unroll
        for (int x = 0; x < 6; x++) {
            int ix = 4*tc - 1 + x;
            bool ok = ((unsigned)iy < 32u) && ((unsigned)ix < 32u);
            d[y][x] = ok ? g_v[(size_t)(base + iy*32 + ix)*256 + ci] : 0.f;
        }
    }
    float e[6][6];
#pragma unroll
    for (int x = 0; x < 6; x++) {
        float in[6] = { d[0][x], d[1][x], d[2][x], d[3][x], d[4][x], d[5][x] };
        float out[6];
        bt6(in, out);
#pragma unroll
        for (int a = 0; a < 6; a++) e[a][x] = out[a];
    }
#pragma unroll
    for (int a = 0; a < 6; a++) {
        float out[6];
        bt6(e[a], out);
#pragma unroll
        for (int bb = 0; bb < 6; bb++) {
            float v = out[bb];
            __nv_bfloat16 hi = __float2bfloat16(v);
            size_t idx = ((size_t)((a*6 + bb)*NTIL + t))*256 + ci;
            g_Vhi[idx] = hi;
            g_Vlo[idx] = __float2bfloat16(v - __bfloat162float(hi));
        }
    }
}

// ---------------- batched Winograd GEMM: CTA 128x64, warp 32x32, 3 CTAs/SM ----------------
__global__ void __launch_bounds__(256, 3) wino_gemm(int which) {
    extern __shared__ __align__(16) char dsm[];
    uint32_t sbase = smem_u32(dsm);

    const __nv_bfloat16* Bh = which ? g_uhi2 : g_uhi1;
    const __nv_bfloat16* Bl = which ? g_ulo2 : g_ulo1;
    int t0  = blockIdx.x << 7;
    int nq  = blockIdx.y;            // 0..3, 64 outputs each
    int pos = blockIdx.z;

    int tid = threadIdx.x, wid = tid >> 5, l = tid & 31;

    int c4 = tid & 3;
    int r0 = tid >> 2;               // 0..63
    uint32_t ph0 = swz(r0, c4), ph1 = swz(r0 + 64, c4);
    const __nv_bfloat16* Abase_hi = g_Vhi + ((size_t)pos*NTIL + t0)*256;
    const __nv_bfloat16* Abase_lo = g_Vlo + ((size_t)pos*NTIL + t0)*256;
    const __nv_bfloat16* Bbase_hi = Bh + ((size_t)pos*256 + nq*64)*256;
    const __nv_bfloat16* Bbase_lo = Bl + ((size_t)pos*256 + nq*64)*256;
    size_t a0 = (size_t)r0*256 + c4*8, a1 = (size_t)(r0 + 64)*256 + c4*8;

    int m0 = (wid & 3) << 5;
    int n0w = (wid >> 2) << 5;       // 0 or 32
    int mi = l >> 3;
    int rA = m0 + ((mi & 1) << 3) + (l & 7);
    uint32_t qA0 = swz(rA, mi >> 1);
    int rB = n0w + (((mi >> 1) & 1) << 3) + (l & 7);
    uint32_t qB0 = swz(rB, mi & 1);

    float acc[2][4][4];
#pragma unroll
    for (int i = 0; i < 2; i++)
#pragma unroll
        for (int j = 0; j < 4; j++)
#pragma unroll
            for (int k = 0; k < 4; k++) acc[i][j][k] = 0.f;

    auto load_chunk = [&](int kc, int stage) {
        size_t coff = (size_t)(kc << 5);
        uint32_t st = sbase + (uint32_t)stage*STAGE_BYTES;
        cpa16(st + ph0,         Abase_hi + a0 + coff);
        cpa16(st + 8192 + ph0,  Abase_lo + a0 + coff);
        cpa16(st + ph1,         Abase_hi + a1 + coff);
        cpa16(st + 8192 + ph1,  Abase_lo + a1 + coff);
        cpa16(st + 16384 + ph0, Bbase_hi + a0 + coff);
        cpa16(st + 20480 + ph0, Bbase_lo + a0 + coff);
        cp_commit();
    };

    load_chunk(0, 0);
    load_chunk(1, 1);

    for (int kc = 0; kc < 8; kc++) {
        int stage = kc % 3;
        if (kc < 6) cp_wait<1>(); else cp_wait<0>();
        __syncthreads();
        if (kc + 2 < 8) load_chunk(kc + 2, (kc + 2) % 3);

        uint32_t st = sbase + (uint32_t)stage*STAGE_BYTES;
        uint32_t Ahi = st, Alo = st + 8192, Bhi = st + 16384, Blo = st + 20480;
#pragma unroll
        for (int ks = 0; ks < 2; ks++) {
            uint32_t kx = (uint32_t)(ks << 5);
            uint32_t qa = qA0 ^ kx, qb = qB0 ^ kx;
            uint32_t ah[8], al[8], bbv[8];
            ldsm4(ah,     Ahi + qa);
            ldsm4(ah + 4, Ahi + qa + 1024);
            ldsm4(al,     Alo + qa);
            ldsm4(al + 4, Alo + qa + 1024);
            ldsm4(bbv,     Bhi + qb);
            ldsm4(bbv + 4, Bhi + qb + 1024);
#pragma unroll
            for (int nf = 0; nf < 4; nf++) {
                const uint32_t* bp = bbv + nf*2;
                mma16816(acc[0][nf], ah,     bp);
                mma16816(acc[1][nf], ah + 4, bp);
            }
#pragma unroll
            for (int nf = 0; nf < 4; nf++) {
                const uint32_t* bp = bbv + nf*2;
                mma16816(acc[0][nf], al,     bp);
                mma16816(acc[1][nf], al + 4, bp);
            }
            ldsm4(bbv,     Blo + qb);
            ldsm4(bbv + 4, Blo + qb + 1024);
#pragma unroll
            for (int nf = 0; nf < 4; nf++) {
                const uint32_t* bp = bbv + nf*2;
                mma16816(acc[0][nf], ah,     bp);
                mma16816(acc[1][nf], ah + 4, bp);
            }
        }
    }
    __syncthreads();

    float* ybuf = (float*)dsm;
    int row0 = m0 + (l >> 2);
    int col0 = n0w + ((l & 3) << 1);
#pragma unroll
    for (int mf = 0; mf < 2; mf++)
#pragma unroll
        for (int nf = 0; nf < 4; nf++)
#pragma unroll
            for (int hf = 0; hf < 2; hf++) {
                int r = row0 + mf*16 + hf*8;
                *(float2*)&ybuf[r*YST3 + col0 + nf*8] =
                    make_float2(acc[mf][nf][hf*2], acc[mf][nf][hf*2 + 1]);
            }
    __syncthreads();
    {
        int row = tid >> 1, q = tid & 1;
        const float4* yr = (const float4*)(ybuf + row*YST3 + q*32);
        float4* dst = (float4*)(g_m + ((size_t)pos*NTIL + t0 + row)*256 + nq*64 + q*32);
#pragma unroll
        for (int i = 0; i < 8; i++) dst[i] = yr[i];
    }
}

// ---------------- pre2 (+ fused xT) ----------------
__global__ void pre2_kernel(const float* __restrict__ x, float scale) {
    __shared__ float sx[256][33];
    int tid = threadIdx.x, lane = tid & 31, w8 = tid >> 5;
    int p0 = blockIdx.x * 32;
    int b = p0 >> 10, hw0 = p0 & 1023;
#pragma unroll 8
    for (int i = 0; i < 32; i++) {
        int c = i*8 + w8;
        sx[c][lane] = x[(size_t)(b*256 + c)*1024 + hw0 + lane];
    }
    __syncthreads();
#pragma unroll 8
    for (int pl = 0; pl < 32; pl++)
        g_xl[(size_t)(p0 + pl)*256 + tid] = sx[tid][pl];
#pragma unroll
    for (int pp = 0; pp < 4; pp++) {
        int pl = w8*4 + pp;
        int p = p0 + pl;
        float xv[8];
#pragma unroll
        for (int i = 0; i < 8; i++) xv[i] = sx[lane*8 + i][pl];
        float q = 0.f;
#pragma unroll
        for (int i = 0; i < 8; i++) q += xv[i]*xv[i];
        float n2 = warpSum(q);
        float n = sqrtf(fmaxf(n2, EPSF));
        float f = atanhf(fminf(n, CLIP1)) / n * scale;
        float4 o0 = make_float4(f*xv[0], f*xv[1], f*xv[2], f*xv[3]);
        float4 o1 = make_float4(f*xv[4], f*xv[5], f*xv[6], f*xv[7]);
        float* dst = g_v + (size_t)p*256 + lane*8;
        *(float4*)dst = o0;
        *(float4*)(dst + 4) = o1;
        if (lane == 0) g_q2[p] = f*f*n2;
    }
}

// ---------------- per-pixel s ----------------
__device__ __forceinline__ float s_from_q2(int p) {
    int h = (p >> 5) & 31, w = p & 31;
    float np2 = 0.f;
#pragma unroll
    for (int dy = -1; dy <= 1; dy++)
#pragma unroll
        for (int dx = -1; dx <= 1; dx++) {
            int sh = h + dy, sw = w + dx;
            if ((unsigned)sh < 32u && (unsigned)sw < 32u) np2 += g_q2[p + dy*32 + dx];
        }
    float np = sqrtf(fmaxf(np2, EPSF));
    float th = tanhf(np);
    float uf = th / np;
    float un = th;
    if (un > MAXN) { uf *= MAXN/un; un = MAXN; }
    float lam = 2.0f / fmaxf(1.0f - un*un, EPSF);
    return lam * uf;
}

// ---------------- output transform + FC epilogue + fused BN partial sums ----------------
__global__ void wino_out(int znoff) {
    __shared__ float ss[16];
    __shared__ float slam[16];
    __shared__ float sld[16];
    __shared__ float ybuf[16][260];
    int t = blockIdx.x, co = threadIdx.x;
    int b = t >> 6, tr = (t >> 3) & 7, tc = t & 7;
    int prow = (b << 10) + (4*tr)*32 + 4*tc;
    if (co < 16) {
        int r = co >> 2, c = co & 3;
        ss[co] = s_from_q2(prow + r*32 + c);
    }
    float m[36];
#pragma unroll
    for (int pos = 0; pos < 36; pos++)
        m[pos] = g_m[((size_t)pos*NTIL + t)*256 + co];
    float Z[4][6];
#pragma unroll
    for (int bb = 0; bb < 6; bb++) {
        float in[6] = { m[bb], m[6+bb], m[12+bb], m[18+bb], m[24+bb], m[30+bb] };
        float out[4];
        at6(in, out);
#pragma unroll
        for (int r = 0; r < 4; r++) Z[r][bb] = out[r];
    }
    float zn = g_zn[znoff + co];
    __syncthreads();
#pragma unroll
    for (int r = 0; r < 4; r++) {
        float Y[4];
        at6(Z[r], Y);
#pragma unroll
        for (int c = 0; c < 4; c++) {
            int p = prow + r*32 + c;
            float s = ss[r*4 + c];
            float tt = Y[c] * s / zn;
            float y = sinhf(2.0f * zn * asinhf(tt));
            g_h[(size_t)p*256 + co] = y;
            ybuf[r*4 + c][co] = y;
        }
    }
    __syncthreads();
    // fused BN phase-1: per-pixel lam via warp reductions (warp w: pixels 2w, 2w+1)
    int wd = co >> 5, lid = co & 31;
#pragma unroll
    for (int k = 0; k < 2; k++) {
        int pl = wd*2 + k;
        float q = 0.f;
#pragma unroll
        for (int i = 0; i < 8; i++) {
            float v = ybuf[pl][lid*8 + i];
            q += v*v;
        }
        float tot = warpSum(q);
        float inv = 1.0f / (1.0f + sqrtf(1.0f + tot));
        float n2 = tot*inv*inv;
        float lam = 2.0f / fmaxf(1.0f - n2, EPSF);
        if (lid == 0) { slam[pl] = lam*inv; sld[pl] = lam - 1.0f; }
    }
    __syncthreads();
    float accm = 0.f;
#pragma unroll
    for (int pl = 0; pl < 16; pl++)
        accm += slam[pl] * ybuf[pl][co];
    g_pm[t*256 + co] = accm;
    if (co == 0) {
        float d = 0.f;
#pragma unroll
        for (int pl = 0; pl < 16; pl++) d += sld[pl];
        g_pd[t] = d;
    }
}

// ---------------- BN mu: 8-block partial sum + last-block finalize ----------------
__global__ void bnmu_kernel(const float* __restrict__ bias) {
    __shared__ float sb[24];
    __shared__ int slast;
    int c = threadIdx.x;
    float s = 0.f;
    int g0 = blockIdx.x * 128;
    for (int g = 0; g < 128; g++) s += g_pm[(g0 + g)*256 + c];
    g_pm2[blockIdx.x*256 + c] = s;
    __threadfence();
    if (c == 0) slast = (atomicAdd(&g_ctr2, 1) == 7);
    __syncthreads();
    if (!slast) return;
    __threadfence();
    float msum = 0.f;
#pragma unroll
    for (int j = 0; j < 8; j++) msum += g_pm2[j*256 + c];
    float dv = 0.f;
#pragma unroll
    for (int j = 0; j < 4; j++) dv += g_pd[j*256 + c];
    float r1[1] = { dv };
    blockReduceK<1>(r1, sb);
    float den = fmaxf(r1[0], EPSF);
    float m = msum / den;
    float r2[1] = { m*m };
    blockReduceK<1>(r2, sb);
    float nm = sqrtf(fmaxf(r2[0], EPSF));
    float fac = tanhf(0.5f * atanhf(fminf(nm, CLIP1))) / nm;
    float muc = fac * m;
    g_mu[c] = muc;
    float bc = bias[c];
    float r3[3] = { muc*muc, bc*bc, bc*muc };
    blockReduceK<3>(r3, sb);
    if (c == 0) {
        float mu2 = r3[0], b2 = r3[1], bm = r3[2];
        g_sc[0] = mu2;
        g_sc[1] = 2.0f / fmaxf(1.0f - mu2, EPSF);
        g_sc[2] = b2;
        g_sc[3] = 2.0f / fmaxf(1.0f - b2, EPSF);
        g_sc[4] = bm;
        g_ctr2 = 0;
    }
}

// ---------------- BN variance: 256 blocks + fused finalize ----------------
__global__ void bnvar_w(const float* __restrict__ weight) {
    __shared__ float sv[8];
    __shared__ int slast;
    int wid = threadIdx.x >> 5, lid = threadIdx.x & 31;
    int p0 = blockIdx.x * 64;
    float mu8[8];
#pragma unroll
    for (int j = 0; j < 8; j++) mu8[j] = g_mu[lid*8 + j];
    float mu2 = g_sc[0];
    float acc = 0.f;
    for (int i = 0; i < 8; i++) {
        int p = p0 + wid*8 + i;
        const float4* row = (const float4*)(g_h + (size_t)p*256 + lid*8);
        float4 a = row[0], cc = row[1];
        float v[8] = {a.x,a.y,a.z,a.w,cc.x,cc.y,cc.z,cc.w};
        float q1 = 0.f, q2 = 0.f;
#pragma unroll
        for (int j = 0; j < 8; j++) { q1 += v[j]*v[j]; q2 += v[j]*mu8[j]; }
        float tot = warpSum(q1);
        float ipr = warpSum(q2);
        float inv = 1.0f / (1.0f + sqrtf(1.0f + tot));
        float xp2 = tot*inv*inv;
        float ip  = ipr*inv;
        float A = 1.0f - 2.0f*ip + mu2;
        float B = 1.0f - xp2;
        float nn = fmaxf(A*A*xp2 - 2.0f*A*B*ip + B*B*mu2, 0.f);
        float den = fmaxf(1.0f - 2.0f*ip + xp2*mu2, EPSF);
        float nr = sqrtf(fmaxf(nn/(den*den), EPSF));
        float dd = 2.0f * atanhf(fminf(nr, CLIP1));
        acc += dd*dd;
    }
    if (lid == 0) sv[wid] = acc;
    __syncthreads();
    if (threadIdx.x == 0) {
        float s = 0.f;
        for (int w = 0; w < 8; w++) s += sv[w];
        g_pv[blockIdx.x] = s;
        __threadfence();
        slast = (atomicAdd(&g_ctr, 1) == 255);
    }
    __syncthreads();
    if (slast) {
        float v = g_pv[threadIdx.x];
        __shared__ float sb[8];
        float r[1] = { v };
        blockReduceK<1>(r, sb);
        if (threadIdx.x == 0) {
            float var = r[0] / 16384.0f;
            g_sc[5] = sqrtf(weight[0] / fmaxf(var, EPSF));
            g_ctr = 0;
        }
    }
}

// ---------------- shared BN point transform ----------------
__device__ __forceinline__ float bn_point_w(const float* xv, const float* mu8, const float* b8,
                                            float* hc) {
    float mu2 = g_sc[0], lam_mu = g_sc[1], b2 = g_sc[2], lam_b = g_sc[3],
          bm = g_sc[4], rstd = g_sc[5];
    float s0 = 0.f, s1 = 0.f, s2 = 0.f;
#pragma unroll
    for (int i = 0; i < 8; i++) { s0 += xv[i]*xv[i]; s1 += mu8[i]*xv[i]; s2 += b8[i]*xv[i]; }
    float xp2 = warpSum(s0), ip = warpSum(s1), bx = warpSum(s2);
    float A  = 1.0f - 2.0f*ip + xp2;
    float Bc = 1.0f - mu2;
    float den = fmaxf(1.0f - 2.0f*ip + mu2*xp2, EPSF);
    float nd2 = fmaxf(A*A*mu2 - 2.0f*A*Bc*ip + Bc*Bc*xp2, 0.f) / (den*den);
    float nd = sqrtf(fmaxf(nd2, EPSF));
    float cv = (2.0f/lam_mu) * atanhf(fminf(nd, CLIP1)) / nd;
    float uw = cv * (Bc*bx - A*bm) / den;
    float vw = cv * (A*mu2 - Bc*ip) / den;
    float av  = -uw*mu2 - vw - 2.0f*bm*vw;
    float bv2 = -vw*b2 + uw;
    float dgy = fmaxf(1.0f - 2.0f*bm + b2*mu2, EPSF);
    float fac = (lam_mu / lam_b) * rstd;
    float uc[8];
    float t0 = 0.f, t1 = 0.f;
#pragma unroll
    for (int i = 0; i < 8; i++) {
        float vc = cv * (Bc*xv[i] - A*mu8[i]) / den;
        uc[i] = (vc + 2.0f*(av*b8[i] - bv2*mu8[i]) / dgy) * fac;
        t0 += uc[i]*uc[i];
        t1 += b8[i]*uc[i];
    }
    float u2 = warpSum(t0), bu = warpSum(t1);
    float nu = sqrtf(fmaxf(u2, EPSF));
    float tf = tanhf(0.5f * lam_b * nu) / nu;
    float s2m = tf*tf*u2;
    float bs  = tf*bu;
    float A3 = 1.0f + 2.0f*bs + s2m, B3 = 1.0f - b2;
    float den3 = fmaxf(1.0f + 2.0f*bs + b2*s2m, EPSF);
#pragma unroll
    for (int i = 0; i < 8; i++) hc[i] = (A3*b8[i] + B3*tf*uc[i]) / den3;
    float nh2 = fmaxf(A3*A3*b2 + 2.0f*A3*B3*bs + B3*B3*s2m, 0.f) / (den3*den3);
    float nh = sqrtf(fmaxf(nh2, EPSF));
    if (nh > MAXN) {
        float q = MAXN / nh;
#pragma unroll
        for (int i = 0; i < 8; i++) hc[i] *= q;
        nh = MAXN;
    }
    return nh;
}

// ---------------- BN apply + hrelu + pre-for-conv2 ----------------
__global__ void bnapply_w(const float* __restrict__ bias, float scale) {
    int wid = threadIdx.x >> 5, lid = threadIdx.x & 31;
    int p = blockIdx.x * 8 + wid;
    const float4* row = (const float4*)(g_h + (size_t)p*256 + lid*8);
    float4 a = row[0], cc = row[1];
    float xv[8] = {a.x,a.y,a.z,a.w,cc.x,cc.y,cc.z,cc.w};
    float qy = 0.f;
#pragma unroll
    for (int i = 0; i < 8; i++) qy += xv[i]*xv[i];
    float tot = warpSum(qy);
    float inv = 1.0f / (1.0f + sqrtf(1.0f + tot));
#pragma unroll
    for (int i = 0; i < 8; i++) xv[i] *= inv;
    float mu8[8], b8[8];
#pragma unroll
    for (int j = 0; j < 8; j++) { mu8[j] = g_mu[lid*8 + j]; b8[j] = bias[lid*8 + j]; }
    float hc[8];
    float nh = bn_point_w(xv, mu8, b8, hc);
    float lf = atanhf(fminf(nh, CLIP1)) / nh;
    float rc[8];
    float q = 0.f;
#pragma unroll
    for (int i = 0; i < 8; i++) { rc[i] = fmaxf(lf*hc[i], 0.f); q += rc[i]*rc[i]; }
    float rs = warpSum(q);
    float nr = sqrtf(fmaxf(rs, EPSF));
    float ef = tanhf(nr) / nr;
    float nhr = sqrtf(fmaxf(ef*ef*rs, EPSF));
    float adj = 1.0f;
    if (nhr > MAXN) { adj = MAXN/nhr; nhr = MAXN; }
    float f3 = atanhf(fminf(nhr, CLIP1)) / nhr * scale;
    float g = f3 * ef * adj;
    float4 o0 = make_float4(g*rc[0], g*rc[1], g*rc[2], g*rc[3]);
    float4 o1 = make_float4(g*rc[4], g*rc[5], g*rc[6], g*rc[7]);
    float* dst = g_v + (size_t)p*256 + lid*8;
    *(float4*)dst = o0;
    *(float4*)(dst + 4) = o1;
    if (lid == 0) g_q2[p] = f3*f3*nhr*nhr;
}

// ---------------- BN2 apply + residual + hrelu + staged NCHW out ----------------
__global__ void final2_kernel(const float* __restrict__ bias, float* __restrict__ out) {
    __shared__ float so[256][33];
    int tid = threadIdx.x, lane = tid & 31, w8 = tid >> 5;
    int p0 = blockIdx.x * 32;
    int b = p0 >> 10, hw0 = p0 & 1023;
    float mu8[8], b8[8];
#pragma unroll
    for (int j = 0; j < 8; j++) { mu8[j] = g_mu[lane*8 + j]; b8[j] = bias[lane*8 + j]; }
#pragma unroll
    for (int pp = 0; pp < 4; pp++) {
        int pl = w8*4 + pp;
        int p = p0 + pl;
        const float4* row = (const float4*)(g_h + (size_t)p*256 + lane*8);
        float4 a = row[0], cc = row[1];
        float xv[8] = {a.x,a.y,a.z,a.w,cc.x,cc.y,cc.z,cc.w};
        float qy = 0.f;
#pragma unroll
        for (int i = 0; i < 8; i++) qy += xv[i]*xv[i];
        float tot = warpSum(qy);
        float inv = 1.0f / (1.0f + sqrtf(1.0f + tot));
#pragma unroll
        for (int i = 0; i < 8; i++) xv[i] *= inv;
        float hc[8];
        float nh = bn_point_w(xv, mu8, b8, hc);
        const float4* rrow = (const float4*)(g_xl + (size_t)p*256 + lane*8);
        float4 r0 = rrow[0], r1 = rrow[1];
        float res[8] = {r0.x,r0.y,r0.z,r0.w,r1.x,r1.y,r1.z,r1.w};
        float q1 = 0.f, q2 = 0.f;
#pragma unroll
        for (int i = 0; i < 8; i++) { q1 += res[i]*res[i]; q2 += hc[i]*res[i]; }
        float y2 = warpSum(q1), xy = warpSum(q2);
        float x2 = nh*nh;
        float A4 = 1.0f + 2.0f*xy + y2, B4 = 1.0f - x2;
        float den4 = fmaxf(1.0f + 2.0f*xy + x2*y2, EPSF);
        float hm[8];
#pragma unroll
        for (int i = 0; i < 8; i++) hm[i] = (A4*hc[i] + B4*res[i]) / den4;
        float nm2 = fmaxf(A4*A4*x2 + 2.0f*A4*B4*xy + B4*B4*y2, 0.f) / (den4*den4);
        float nmv = sqrtf(fmaxf(nm2, EPSF));
        float lf = atanhf(fminf(nmv, CLIP1)) / nmv;
        float rc[8];
        float q = 0.f;
#pragma unroll
        for (int i = 0; i < 8; i++) { rc[i] = fmaxf(lf*hm[i], 0.f); q += rc[i]*rc[i]; }
        float rs = warpSum(q);
        float nr = sqrtf(fmaxf(rs, EPSF));
        float ef = tanhf(nr) / nr;
        float nhr = sqrtf(fmaxf(ef*ef*rs, EPSF));
        float adj = (nhr > MAXN) ? MAXN/nhr : 1.0f;
#pragma unroll
        for (int i = 0; i < 8; i++) so[lane*8 + i][pl] = ef * adj * rc[i];
    }
    __syncthreads();
#pragma unroll 8
    for (int i = 0; i < 32; i++) {
        int c = i*8 + w8;
        out[(size_t)(b*256 + c)*1024 + hw0 + lane] = so[c][lane];
    }
}

// ---------------- launcher ----------------
extern "C" void kernel_launch(void* const* d_in, const int* in_sizes, int n_in,
                              void* d_out, int out_size) {
    const float* x  = (const float*)d_in[0];
    const float* z1 = (const float*)d_in[1];
    const float* z2 = (const float*)d_in[2];
    const float* w1 = (const float*)d_in[3];
    const float* b1 = (const float*)d_in[4];
    const float* w2 = (const float*)d_in[5];
    const float* b2 = (const float*)d_in[6];
    float* out = (float*)d_out;

    // scale = Beta(1152, 0.5) / Beta(128, 0.5)
    double lg = lgamma(1152.0) - lgamma(1152.5) - lgamma(128.0) + lgamma(128.5);
    float scale = (float)exp(lg);

    static int smem_set = 0;
    if (!smem_set) {
        cudaFuncSetAttribute(wino_gemm, cudaFuncAttributeMaxDynamicSharedMemorySize, CONV_SMEM);
        smem_set = 1;
    }

    dim3 ggrid(8, 4, 36);

    wino_u<<<256, 256>>>(z1, 0);                 // 0
    pre2_kernel<<<PNUM/32, 256>>>(x, scale);     // 1
    wino_in<<<NTIL, 256>>>();                    // 2
    wino_gemm<<<ggrid, 256, CONV_SMEM>>>(0);     // 3  <- ncu capture target
    wino_u<<<256, 256>>>(z2, 1);
    wino_out<<<NTIL, 256>>>(0);                  // fused BN phase-1

    bnmu_kernel<<<8, 256>>>(b1);
    bnvar_w<<<256, 256>>>(w1);
    bnapply_w<<<PNUM/8, 256>>>(b1, scale);

    wino_in<<<NTIL, 256>>>();
    wino_gemm<<<ggrid, 256, CONV_SMEM>>>(1);
    wino_out<<<NTIL, 256>>>(256);

    bnmu_kernel<<<8, 256>>>(b2);
    bnvar_w<<<256, 256>>>(w2);
    final2_kernel<<<PNUM/32, 256>>>(b2, out);
}

// round 11
// speedup vs baseline: 2.1503x; 1.1235x over previous
#include <cuda_runtime.h>
#include <cuda_bf16.h>
#include <math.h>
#include <stdint.h>

// Problem constants: B=16, C=256, H=W=32
#define PNUM 16384
#define CNUM 256
#define CLIP1 0.9999999f
#define MAXN  0.99999f
#define EPSF  1e-15f

#define NPOS 36
#define NTIL 1024
#define STAGE_BYTES 24576u       // Ahi 8K + Alo 8K + Bhi 4K + Blo 4K
#define CONV_SMEM (3*24576)      // 72 KB -> 3 CTAs/SM

// ---------------- device scratch ----------------
__device__ __align__(16) float g_v [PNUM*CNUM];
__device__ __align__(16) __nv_bfloat16 g_Vhi[NPOS*NTIL*CNUM];
__device__ __align__(16) __nv_bfloat16 g_Vlo[NPOS*NTIL*CNUM];
__device__ __align__(16) __nv_bfloat16 g_uhi1[NPOS*CNUM*CNUM];
__device__ __align__(16) __nv_bfloat16 g_ulo1[NPOS*CNUM*CNUM];
__device__ __align__(16) __nv_bfloat16 g_uhi2[NPOS*CNUM*CNUM];
__device__ __align__(16) __nv_bfloat16 g_ulo2[NPOS*CNUM*CNUM];
__device__ __align__(16) float g_m [NPOS*NTIL*CNUM];
__device__ __align__(16) float g_h [PNUM*CNUM];
__device__ __align__(16) float g_xl[PNUM*CNUM];
__device__ float g_q2[PNUM];
__device__ float g_zn[512];
__device__ float g_pm [NTIL*CNUM];
__device__ float g_pm2[8*CNUM];
__device__ float g_pd[NTIL];
__device__ float g_pv[256];
__device__ float g_mu[CNUM];
__device__ float g_sc[8];
__device__ int   g_ctr  = 0;
__device__ int   g_ctr2 = 0;

// ---------------- PTX helpers ----------------
__device__ __forceinline__ uint32_t smem_u32(const void* p) {
    uint32_t a;
    asm("{ .reg .u64 t; cvta.to.shared.u64 t, %1; cvt.u32.u64 %0, t; }" : "=r"(a) : "l"(p));
    return a;
}
__device__ __forceinline__ void cpa16(uint32_t dst, const void* src) {
    asm volatile("cp.async.cg.shared.global [%0], [%1], 16;" :: "r"(dst), "l"(src) : "memory");
}
__device__ __forceinline__ void cp_commit() {
    asm volatile("cp.async.commit_group;" ::: "memory");
}
template<int N>
__device__ __forceinline__ void cp_wait() {
    asm volatile("cp.async.wait_group %0;" :: "n"(N) : "memory");
}
__device__ __forceinline__ void ldsm4(uint32_t* r, uint32_t addr) {
    asm volatile("ldmatrix.sync.aligned.m8n8.x4.shared.b16 {%0,%1,%2,%3}, [%4];"
        : "=r"(r[0]), "=r"(r[1]), "=r"(r[2]), "=r"(r[3]) : "r"(addr));
}
__device__ __forceinline__ void mma16816(float* d, const uint32_t* a, const uint32_t* b) {
    asm volatile("mma.sync.aligned.m16n8k16.row.col.f32.bf16.bf16.f32 "
        "{%0,%1,%2,%3}, {%4,%5,%6,%7}, {%8,%9}, {%0,%1,%2,%3};"
        : "+f"(d[0]), "+f"(d[1]), "+f"(d[2]), "+f"(d[3])
        : "r"(a[0]), "r"(a[1]), "r"(a[2]), "r"(a[3]), "r"(b[0]), "r"(b[1]));
}
__device__ __forceinline__ uint32_t swz(int r, int c) {
    return (uint32_t)(((r >> 1) << 7) | (((((r & 1) << 2) | c) ^ ((r >> 1) & 7)) << 4));
}

// ---------------- reductions ----------------
__device__ __forceinline__ float warpSum(float v) {
#pragma unroll
    for (int o = 16; o > 0; o >>= 1) v += __shfl_xor_sync(0xffffffffu, v, o);
    return v;
}
template<int K>
__device__ __forceinline__ void blockReduceK(float* v, float* sbuf) {
    int tid = threadIdx.x, lane = tid & 31, wid = tid >> 5;
#pragma unroll
    for (int i = 0; i < K; i++) {
        float x = v[i];
#pragma unroll
        for (int o = 16; o > 0; o >>= 1) x += __shfl_down_sync(0xffffffffu, x, o);
        if (lane == 0) sbuf[i*8 + wid] = x;
    }
    __syncthreads();
    if (tid == 0) {
#pragma unroll
        for (int i = 0; i < K; i++) {
            float s = sbuf[i*8];
            for (int w = 1; w < 8; w++) s += sbuf[i*8 + w];
            sbuf[i*8] = s;
        }
    }
    __syncthreads();
#pragma unroll
    for (int i = 0; i < K; i++) v[i] = sbuf[i*8];
    __syncthreads();
}

// ---------------- Winograd transforms ----------------
__device__ __forceinline__ void bt6(const float* in, float* out) {
    out[0] =  4.f*in[0] - 5.f*in[2] + in[4];
    out[1] = -4.f*in[1] - 4.f*in[2] + in[3] + in[4];
    out[2] =  4.f*in[1] - 4.f*in[2] - in[3] + in[4];
    out[3] = -2.f*in[1] -     in[2] + 2.f*in[3] + in[4];
    out[4] =  2.f*in[1] -     in[2] - 2.f*in[3] + in[4];
    out[5] =  4.f*in[1] - 5.f*in[3] + in[5];
}
__device__ __forceinline__ void g6(const float* in, float* out) {
    out[0] = 0.25f*in[0];
    out[1] = -(in[0] + in[1] + in[2]) * (1.f/6.f);
    out[2] = (-in[0] + in[1] - in[2]) * (1.f/6.f);
    out[3] = in[0]*(1.f/24.f) + in[1]*(1.f/12.f) + in[2]*(1.f/6.f);
    out[4] = in[0]*(1.f/24.f) - in[1]*(1.f/12.f) + in[2]*(1.f/6.f);
    out[5] = in[2];
}
__device__ __forceinline__ void at6(const float* in, float* out) {
    out[0] = in[0] + in[1] + in[2] + in[3] + in[4];
    out[1] = in[1] - in[2] + 2.f*(in[3] - in[4]);
    out[2] = in[1] + in[2] + 4.f*(in[3] + in[4]);
    out[3] = in[1] - in[2] + 8.f*(in[3] - in[4]) + in[5];
}

// ---------------- U = G z G^T (+ fused z column norms), both weight sets ----------------
__global__ void wino_u(const float* __restrict__ z1, const float* __restrict__ z2) {
    __shared__ float sb[8];
    const float* z = blockIdx.y ? z2 : z1;
    __nv_bfloat16* uh = blockIdx.y ? g_uhi2 : g_uhi1;
    __nv_bfloat16* ul = blockIdx.y ? g_ulo2 : g_ulo1;
    int co = blockIdx.x, ci = threadIdx.x;
    float g[3][3];
    float nsum = 0.f;
#pragma unroll
    for (int i = 0; i < 3; i++)
#pragma unroll
        for (int j = 0; j < 3; j++) {
            float w = z[(size_t)((i*3 + j)*256 + ci)*256 + co];
            g[i][j] = w;
            nsum += w*w;
        }
    float r1[1] = { nsum };
    blockReduceK<1>(r1, sb);
    if (ci == 0) g_zn[blockIdx.y*256 + co] = sqrtf(fmaxf(r1[0], EPSF));

    float t[6][3];
#pragma unroll
    for (int j = 0; j < 3; j++) {
        float in[3] = { g[0][j], g[1][j], g[2][j] };
        float out[6];
        g6(in, out);
#pragma unroll
        for (int a = 0; a < 6; a++) t[a][j] = out[a];
    }
#pragma unroll
    for (int a = 0; a < 6; a++) {
        float out[6];
        g6(t[a], out);
#pragma unroll
        for (int b = 0; b < 6; b++) {
            float u = out[b];
            __nv_bfloat16 hi = __float2bfloat16(u);
            size_t idx = ((size_t)((a*6 + b)*256 + co))*256 + ci;
            uh[idx] = hi;
            ul[idx] = __float2bfloat16(u - __bfloat162float(hi));
        }
    }
}

// ---------------- V = B^T d B per tile ----------------
__global__ void wino_in() {
    int t = blockIdx.x, ci = threadIdx.x;
    int b = t >> 6, tr = (t >> 3) & 7, tc = t & 7;
    int base = b << 10;
    float d[6][6];
#pragma unroll
    for (int y = 0; y < 6; y++) {
        int iy = 4*tr - 1 + y;
#pragma unroll
        for (int x = 0; x < 6; x++) {
            int ix = 4*tc - 1 + x;
            bool ok = ((unsigned)iy < 32u) && ((unsigned)ix < 32u);
            d[y][x] = ok ? g_v[(size_t)(base + iy*32 + ix)*256 + ci] : 0.f;
        }
    }
    float e[6][6];
#pragma unroll
    for (int x = 0; x < 6; x++) {
        float in[6] = { d[0][x], d[1][x], d[2][x], d[3][x], d[4][x], d[5][x] };
        float out[6];
        bt6(in, out);
#pragma unroll
        for (int a = 0; a < 6; a++) e[a][x] = out[a];
    }
#pragma unroll
    for (int a = 0; a < 6; a++) {
        float out[6];
        bt6(e[a], out);
#pragma unroll
        for (int bb = 0; bb < 6; bb++) {
            float v = out[bb];
            __nv_bfloat16 hi = __float2bfloat16(v);
            size_t idx = ((size_t)((a*6 + bb)*NTIL + t))*256 + ci;
            g_Vhi[idx] = hi;
            g_Vlo[idx] = __float2bfloat16(v - __bfloat162float(hi));
        }
    }
}

// ---------------- batched Winograd GEMM: CTA 128x64, warp 32x32, 3 CTAs/SM ----------------
// Direct register->global epilogue (no smem staging).
__global__ void __launch_bounds__(256, 3) wino_gemm(int which) {
    extern __shared__ __align__(16) char dsm[];
    uint32_t sbase = smem_u32(dsm);

    const __nv_bfloat16* Bh = which ? g_uhi2 : g_uhi1;
    const __nv_bfloat16* Bl = which ? g_ulo2 : g_ulo1;
    int t0  = blockIdx.x << 7;
    int nq  = blockIdx.y;
    int pos = blockIdx.z;

    int tid = threadIdx.x, wid = tid >> 5, l = tid & 31;

    int c4 = tid & 3;
    int r0 = tid >> 2;
    uint32_t ph0 = swz(r0, c4), ph1 = swz(r0 + 64, c4);
    const __nv_bfloat16* Abase_hi = g_Vhi + ((size_t)pos*NTIL + t0)*256;
    const __nv_bfloat16* Abase_lo = g_Vlo + ((size_t)pos*NTIL + t0)*256;
    const __nv_bfloat16* Bbase_hi = Bh + ((size_t)pos*256 + nq*64)*256;
    const __nv_bfloat16* Bbase_lo = Bl + ((size_t)pos*256 + nq*64)*256;
    size_t a0 = (size_t)r0*256 + c4*8, a1 = (size_t)(r0 + 64)*256 + c4*8;

    int m0 = (wid & 3) << 5;
    int n0w = (wid >> 2) << 5;
    int mi = l >> 3;
    int rA = m0 + ((mi & 1) << 3) + (l & 7);
    uint32_t qA0 = swz(rA, mi >> 1);
    int rB = n0w + (((mi >> 1) & 1) << 3) + (l & 7);
    uint32_t qB0 = swz(rB, mi & 1);

    float acc[2][4][4];
#pragma unroll
    for (int i = 0; i < 2; i++)
#pragma unroll
        for (int j = 0; j < 4; j++)
#pragma unroll
            for (int k = 0; k < 4; k++) acc[i][j][k] = 0.f;

    auto load_chunk = [&](int kc, int stage) {
        size_t coff = (size_t)(kc << 5);
        uint32_t st = sbase + (uint32_t)stage*STAGE_BYTES;
        cpa16(st + ph0,         Abase_hi + a0 + coff);
        cpa16(st + 8192 + ph0,  Abase_lo + a0 + coff);
        cpa16(st + ph1,         Abase_hi + a1 + coff);
        cpa16(st + 8192 + ph1,  Abase_lo + a1 + coff);
        cpa16(st + 16384 + ph0, Bbase_hi + a0 + coff);
        cpa16(st + 20480 + ph0, Bbase_lo + a0 + coff);
        cp_commit();
    };

    load_chunk(0, 0);
    load_chunk(1, 1);

    for (int kc = 0; kc < 8; kc++) {
        int stage = kc % 3;
        if (kc < 6) cp_wait<1>(); else cp_wait<0>();
        __syncthreads();
        if (kc + 2 < 8) load_chunk(kc + 2, (kc + 2) % 3);

        uint32_t st = sbase + (uint32_t)stage*STAGE_BYTES;
        uint32_t Ahi = st, Alo = st + 8192, Bhi = st + 16384, Blo = st + 20480;
#pragma unroll
        for (int ks = 0; ks < 2; ks++) {
            uint32_t kx = (uint32_t)(ks << 5);
            uint32_t qa = qA0 ^ kx, qb = qB0 ^ kx;
            uint32_t ah[8], al[8], bbv[8];
            ldsm4(bbv,     Bhi + qb);
            ldsm4(bbv + 4, Bhi + qb + 1024);
            ldsm4(ah,     Ahi + qa);
            ldsm4(ah + 4, Ahi + qa + 1024);
            ldsm4(al,     Alo + qa);
            ldsm4(al + 4, Alo + qa + 1024);
#pragma unroll
            for (int nf = 0; nf < 4; nf++) {
                const uint32_t* bp = bbv + nf*2;
                mma16816(acc[0][nf], ah,     bp);
                mma16816(acc[1][nf], ah + 4, bp);
            }
#pragma unroll
            for (int nf = 0; nf < 4; nf++) {
                const uint32_t* bp = bbv + nf*2;
                mma16816(acc[0][nf], al,     bp);
                mma16816(acc[1][nf], al + 4, bp);
            }
            ldsm4(bbv,     Blo + qb);
            ldsm4(bbv + 4, Blo + qb + 1024);
#pragma unroll
            for (int nf = 0; nf < 4; nf++) {
                const uint32_t* bp = bbv + nf*2;
                mma16816(acc[0][nf], ah,     bp);
                mma16816(acc[1][nf], ah + 4, bp);
            }
        }
    }

    // direct register->global epilogue (quad-coalesced 32B sectors)
    int row0 = m0 + (l >> 2);
    int col0 = n0w + ((l & 3) << 1);
    float* gm = g_m + ((size_t)pos*NTIL + t0)*256 + nq*64;
#pragma unroll
    for (int mf = 0; mf < 2; mf++)
#pragma unroll
        for (int hf = 0; hf < 2; hf++) {
            int r = row0 + mf*16 + hf*8;
            float* rowp = gm + (size_t)r*256;
#pragma unroll
            for (int nf = 0; nf < 4; nf++)
                *(float2*)(rowp + col0 + nf*8) =
                    make_float2(acc[mf][nf][hf*2], acc[mf][nf][hf*2 + 1]);
        }
}

// ---------------- pre2 (+ fused xT) ----------------
__global__ void pre2_kernel(const float* __restrict__ x, float scale) {
    __shared__ float sx[256][33];
    int tid = threadIdx.x, lane = tid & 31, w8 = tid >> 5;
    int p0 = blockIdx.x * 32;
    int b = p0 >> 10, hw0 = p0 & 1023;
#pragma unroll 8
    for (int i = 0; i < 32; i++) {
        int c = i*8 + w8;
        sx[c][lane] = x[(size_t)(b*256 + c)*1024 + hw0 + lane];
    }
    __syncthreads();
#pragma unroll 8
    for (int pl = 0; pl < 32; pl++)
        g_xl[(size_t)(p0 + pl)*256 + tid] = sx[tid][pl];
#pragma unroll
    for (int pp = 0; pp < 4; pp++) {
        int pl = w8*4 + pp;
        int p = p0 + pl;
        float xv[8];
#pragma unroll
        for (int i = 0; i < 8; i++) xv[i] = sx[lane*8 + i][pl];
        float q = 0.f;
#pragma unroll
        for (int i = 0; i < 8; i++) q += xv[i]*xv[i];
        float n2 = warpSum(q);
        float n = sqrtf(fmaxf(n2, EPSF));
        float f = atanhf(fminf(n, CLIP1)) / n * scale;
        float4 o0 = make_float4(f*xv[0], f*xv[1], f*xv[2], f*xv[3]);
        float4 o1 = make_float4(f*xv[4], f*xv[5], f*xv[6], f*xv[7]);
        float* dst = g_v + (size_t)p*256 + lane*8;
        *(float4*)dst = o0;
        *(float4*)(dst + 4) = o1;
        if (lane == 0) g_q2[p] = f*f*n2;
    }
}

// ---------------- per-pixel s ----------------
__device__ __forceinline__ float s_from_q2(int p) {
    int h = (p >> 5) & 31, w = p & 31;
    float np2 = 0.f;
#pragma unroll
    for (int dy = -1; dy <= 1; dy++)
#pragma unroll
        for (int dx = -1; dx <= 1; dx++) {
            int sh = h + dy, sw = w + dx;
            if ((unsigned)sh < 32u && (unsigned)sw < 32u) np2 += g_q2[p + dy*32 + dx];
        }
    float np = sqrtf(fmaxf(np2, EPSF));
    float th = tanhf(np);
    float uf = th / np;
    float un = th;
    if (un > MAXN) { uf *= MAXN/un; un = MAXN; }
    float lam = 2.0f / fmaxf(1.0f - un*un, EPSF);
    return lam * uf;
}

// ---------------- output transform + FC epilogue + fused BN partial sums ----------------
__global__ void wino_out(int znoff) {
    __shared__ float ss[16];
    __shared__ float slam[16];
    __shared__ float sld[16];
    __shared__ float ybuf[16][260];
    int t = blockIdx.x, co = threadIdx.x;
    int b = t >> 6, tr = (t >> 3) & 7, tc = t & 7;
    int prow = (b << 10) + (4*tr)*32 + 4*tc;
    if (co < 16) {
        int r = co >> 2, c = co & 3;
        ss[co] = s_from_q2(prow + r*32 + c);
    }
    float m[36];
#pragma unroll
    for (int pos = 0; pos < 36; pos++)
        m[pos] = g_m[((size_t)pos*NTIL + t)*256 + co];
    float Z[4][6];
#pragma unroll
    for (int bb = 0; bb < 6; bb++) {
        float in[6] = { m[bb], m[6+bb], m[12+bb], m[18+bb], m[24+bb], m[30+bb] };
        float out[4];
        at6(in, out);
#pragma unroll
        for (int r = 0; r < 4; r++) Z[r][bb] = out[r];
    }
    float zn = g_zn[znoff + co];
    __syncthreads();
#pragma unroll
    for (int r = 0; r < 4; r++) {
        float Y[4];
        at6(Z[r], Y);
#pragma unroll
        for (int c = 0; c < 4; c++) {
            int p = prow + r*32 + c;
            float s = ss[r*4 + c];
            float tt = Y[c] * s / zn;
            float y = sinhf(2.0f * zn * asinhf(tt));
            g_h[(size_t)p*256 + co] = y;
            ybuf[r*4 + c][co] = y;
        }
    }
    __syncthreads();
    int wd = co >> 5, lid = co & 31;
#pragma unroll
    for (int k = 0; k < 2; k++) {
        int pl = wd*2 + k;
        float q = 0.f;
#pragma unroll
        for (int i = 0; i < 8; i++) {
            float v = ybuf[pl][lid*8 + i];
            q += v*v;
        }
        float tot = warpSum(q);
        float inv = 1.0f / (1.0f + sqrtf(1.0f + tot));
        float n2 = tot*inv*inv;
        float lam = 2.0f / fmaxf(1.0f - n2, EPSF);
        if (lid == 0) { slam[pl] = lam*inv; sld[pl] = lam - 1.0f; }
    }
    __syncthreads();
    float accm = 0.f;
#pragma unroll
    for (int pl = 0; pl < 16; pl++)
        accm += slam[pl] * ybuf[pl][co];
    g_pm[t*256 + co] = accm;
    if (co == 0) {
        float d = 0.f;
#pragma unroll
        for (int pl = 0; pl < 16; pl++) d += sld[pl];
        g_pd[t] = d;
    }
}

// ---------------- BN mu: 8-block partial sum + last-block finalize ----------------
__global__ void bnmu_kernel(const float* __restrict__ bias) {
    __shared__ float sb[24];
    __shared__ int slast;
    int c = threadIdx.x;
    float s = 0.f;
    int g0 = blockIdx.x * 128;
    for (int g = 0; g < 128; g++) s += g_pm[(g0 + g)*256 + c];
    g_pm2[blockIdx.x*256 + c] = s;
    __threadfence();
    if (c == 0) slast = (atomicAdd(&g_ctr2, 1) == 7);
    __syncthreads();
    if (!slast) return;
    __threadfence();
    float msum = 0.f;
#pragma unroll
    for (int j = 0; j < 8; j++) msum += g_pm2[j*256 + c];
    float dv = 0.f;
#pragma unroll
    for (int j = 0; j < 4; j++) dv += g_pd[j*256 + c];
    float r1[1] = { dv };
    blockReduceK<1>(r1, sb);
    float den = fmaxf(r1[0], EPSF);
    float m = msum / den;
    float r2[1] = { m*m };
    blockReduceK<1>(r2, sb);
    float nm = sqrtf(fmaxf(r2[0], EPSF));
    float fac = tanhf(0.5f * atanhf(fminf(nm, CLIP1))) / nm;
    float muc = fac * m;
    g_mu[c] = muc;
    float bc = bias[c];
    float r3[3] = { muc*muc, bc*bc, bc*muc };
    blockReduceK<3>(r3, sb);
    if (c == 0) {
        float mu2 = r3[0], b2 = r3[1], bm = r3[2];
        g_sc[0] = mu2;
        g_sc[1] = 2.0f / fmaxf(1.0f - mu2, EPSF);
        g_sc[2] = b2;
        g_sc[3] = 2.0f / fmaxf(1.0f - b2, EPSF);
        g_sc[4] = bm;
        g_ctr2 = 0;
    }
}

// ---------------- BN variance: 256 blocks + fused finalize ----------------
__global__ void bnvar_w(const float* __restrict__ weight) {
    __shared__ float sv[8];
    __shared__ int slast;
    int wid = threadIdx.x >> 5, lid = threadIdx.x & 31;
    int p0 = blockIdx.x * 64;
    float mu8[8];
#pragma unroll
    for (int j = 0; j < 8; j++) mu8[j] = g_mu[lid*8 + j];
    float mu2 = g_sc[0];
    float acc = 0.f;
    for (int i = 0; i < 8; i++) {
        int p = p0 + wid*8 + i;
        const float4* row = (const float4*)(g_h + (size_t)p*256 + lid*8);
        float4 a = row[0], cc = row[1];
        float v[8] = {a.x,a.y,a.z,a.w,cc.x,cc.y,cc.z,cc.w};
        float q1 = 0.f, q2 = 0.f;
#pragma unroll
        for (int j = 0; j < 8; j++) { q1 += v[j]*v[j]; q2 += v[j]*mu8[j]; }
        float tot = warpSum(q1);
        float ipr = warpSum(q2);
        float inv = 1.0f / (1.0f + sqrtf(1.0f + tot));
        float xp2 = tot*inv*inv;
        float ip  = ipr*inv;
        float A = 1.0f - 2.0f*ip + mu2;
        float B = 1.0f - xp2;
        float nn = fmaxf(A*A*xp2 - 2.0f*A*B*ip + B*B*mu2, 0.f);
        float den = fmaxf(1.0f - 2.0f*ip + xp2*mu2, EPSF);
        float nr = sqrtf(fmaxf(nn/(den*den), EPSF));
        float dd = 2.0f * atanhf(fminf(nr, CLIP1));
        acc += dd*dd;
    }
    if (lid == 0) sv[wid] = acc;
    __syncthreads();
    if (threadIdx.x == 0) {
        float s = 0.f;
        for (int w = 0; w < 8; w++) s += sv[w];
        g_pv[blockIdx.x] = s;
        __threadfence();
        slast = (atomicAdd(&g_ctr, 1) == 255);
    }
    __syncthreads();
    if (slast) {
        float v = g_pv[threadIdx.x];
        __shared__ float sb[8];
        float r[1] = { v };
        blockReduceK<1>(r, sb);
        if (threadIdx.x == 0) {
            float var = r[0] / 16384.0f;
            g_sc[5] = sqrtf(weight[0] / fmaxf(var, EPSF));
            g_ctr = 0;
        }
    }
}

// ---------------- shared BN point transform ----------------
__device__ __forceinline__ float bn_point_w(const float* xv, const float* mu8, const float* b8,
                                            float* hc) {
    float mu2 = g_sc[0], lam_mu = g_sc[1], b2 = g_sc[2], lam_b = g_sc[3],
          bm = g_sc[4], rstd = g_sc[5];
    float s0 = 0.f, s1 = 0.f, s2 = 0.f;
#pragma unroll
    for (int i = 0; i < 8; i++) { s0 += xv[i]*xv[i]; s1 += mu8[i]*xv[i]; s2 += b8[i]*xv[i]; }
    float xp2 = warpSum(s0), ip = warpSum(s1), bx = warpSum(s2);
    float A  = 1.0f - 2.0f*ip + xp2;
    float Bc = 1.0f - mu2;
    float den = fmaxf(1.0f - 2.0f*ip + mu2*xp2, EPSF);
    float nd2 = fmaxf(A*A*mu2 - 2.0f*A*Bc*ip + Bc*Bc*xp2, 0.f) / (den*den);
    float nd = sqrtf(fmaxf(nd2, EPSF));
    float cv = (2.0f/lam_mu) * atanhf(fminf(nd, CLIP1)) / nd;
    float uw = cv * (Bc*bx - A*bm) / den;
    float vw = cv * (A*mu2 - Bc*ip) / den;
    float av  = -uw*mu2 - vw - 2.0f*bm*vw;
    float bv2 = -vw*b2 + uw;
    float dgy = fmaxf(1.0f - 2.0f*bm + b2*mu2, EPSF);
    float fac = (lam_mu / lam_b) * rstd;
    float uc[8];
    float t0 = 0.f, t1 = 0.f;
#pragma unroll
    for (int i = 0; i < 8; i++) {
        float vc = cv * (Bc*xv[i] - A*mu8[i]) / den;
        uc[i] = (vc + 2.0f*(av*b8[i] - bv2*mu8[i]) / dgy) * fac;
        t0 += uc[i]*uc[i];
        t1 += b8[i]*uc[i];
    }
    float u2 = warpSum(t0), bu = warpSum(t1);
    float nu = sqrtf(fmaxf(u2, EPSF));
    float tf = tanhf(0.5f * lam_b * nu) / nu;
    float s2m = tf*tf*u2;
    float bs  = tf*bu;
    float A3 = 1.0f + 2.0f*bs + s2m, B3 = 1.0f - b2;
    float den3 = fmaxf(1.0f + 2.0f*bs + b2*s2m, EPSF);
#pragma unroll
    for (int i = 0; i < 8; i++) hc[i] = (A3*b8[i] + B3*tf*uc[i]) / den3;
    float nh2 = fmaxf(A3*A3*b2 + 2.0f*A3*B3*bs + B3*B3*s2m, 0.f) / (den3*den3);
    float nh = sqrtf(fmaxf(nh2, EPSF));
    if (nh > MAXN) {
        float q = MAXN / nh;
#pragma unroll
        for (int i = 0; i < 8; i++) hc[i] *= q;
        nh = MAXN;
    }
    return nh;
}

// ---------------- BN apply + hrelu + pre-for-conv2 ----------------
__global__ void bnapply_w(const float* __restrict__ bias, float scale) {
    int wid = threadIdx.x >> 5, lid = threadIdx.x & 31;
    int p = blockIdx.x * 8 + wid;
    const float4* row = (const float4*)(g_h + (size_t)p*256 + lid*8);
    float4 a = row[0], cc = row[1];
    float xv[8] = {a.x,a.y,a.z,a.w,cc.x,cc.y,cc.z,cc.w};
    float qy = 0.f;
#pragma unroll
    for (int i = 0; i < 8; i++) qy += xv[i]*xv[i];
    float tot = warpSum(qy);
    float inv = 1.0f / (1.0f + sqrtf(1.0f + tot));
#pragma unroll
    for (int i = 0; i < 8; i++) xv[i] *= inv;
    float mu8[8], b8[8];
#pragma unroll
    for (int j = 0; j < 8; j++) { mu8[j] = g_mu[lid*8 + j]; b8[j] = bias[lid*8 + j]; }
    float hc[8];
    float nh = bn_point_w(xv, mu8, b8, hc);
    float lf = atanhf(fminf(nh, CLIP1)) / nh;
    float rc[8];
    float q = 0.f;
#pragma unroll
    for (int i = 0; i < 8; i++) { rc[i] = fmaxf(lf*hc[i], 0.f); q += rc[i]*rc[i]; }
    float rs = warpSum(q);
    float nr = sqrtf(fmaxf(rs, EPSF));
    float ef = tanhf(nr) / nr;
    float nhr = sqrtf(fmaxf(ef*ef*rs, EPSF));
    float adj = 1.0f;
    if (nhr > MAXN) { adj = MAXN/nhr; nhr = MAXN; }
    float f3 = atanhf(fminf(nhr, CLIP1)) / nhr * scale;
    float g = f3 * ef * adj;
    float4 o0 = make_float4(g*rc[0], g*rc[1], g*rc[2], g*rc[3]);
    float4 o1 = make_float4(g*rc[4], g*rc[5], g*rc[6], g*rc[7]);
    float* dst = g_v + (size_t)p*256 + lid*8;
    *(float4*)dst = o0;
    *(float4*)(dst + 4) = o1;
    if (lid == 0) g_q2[p] = f3*f3*nhr*nhr;
}

// ---------------- BN2 apply + residual + hrelu + staged NCHW out ----------------
__global__ void final2_kernel(const float* __restrict__ bias, float* __restrict__ out) {
    __shared__ float so[256][33];
    int tid = threadIdx.x, lane = tid & 31, w8 = tid >> 5;
    int p0 = blockIdx.x * 32;
    int b = p0 >> 10, hw0 = p0 & 1023;
    float mu8[8], b8[8];
#pragma unroll
    for (int j = 0; j < 8; j++) { mu8[j] = g_mu[lane*8 + j]; b8[j] = bias[lane*8 + j]; }
#pragma unroll
    for (int pp = 0; pp < 4; pp++) {
        int pl = w8*4 + pp;
        int p = p0 + pl;
        const float4* row = (const float4*)(g_h + (size_t)p*256 + lane*8);
        float4 a = row[0], cc = row[1];
        float xv[8] = {a.x,a.y,a.z,a.w,cc.x,cc.y,cc.z,cc.w};
        float qy = 0.f;
#pragma unroll
        for (int i = 0; i < 8; i++) qy += xv[i]*xv[i];
        float tot = warpSum(qy);
        float inv = 1.0f / (1.0f + sqrtf(1.0f + tot));
#pragma unroll
        for (int i = 0; i < 8; i++) xv[i] *= inv;
        float hc[8];
        float nh = bn_point_w(xv, mu8, b8, hc);
        const float4* rrow = (const float4*)(g_xl + (size_t)p*256 + lane*8);
        float4 r0 = rrow[0], r1 = rrow[1];
        float res[8] = {r0.x,r0.y,r0.z,r0.w,r1.x,r1.y,r1.z,r1.w};
        float q1 = 0.f, q2 = 0.f;
#pragma unroll
        for (int i = 0; i < 8; i++) { q1 += res[i]*res[i]; q2 += hc[i]*res[i]; }
        float y2 = warpSum(q1), xy = warpSum(q2);
        float x2 = nh*nh;
        float A4 = 1.0f + 2.0f*xy + y2, B4 = 1.0f - x2;
        float den4 = fmaxf(1.0f + 2.0f*xy + x2*y2, EPSF);
        float hm[8];
#pragma unroll
        for (int i = 0; i < 8; i++) hm[i] = (A4*hc[i] + B4*res[i]) / den4;
        float nm2 = fmaxf(A4*A4*x2 + 2.0f*A4*B4*xy + B4*B4*y2, 0.f) / (den4*den4);
        float nmv = sqrtf(fmaxf(nm2, EPSF));
        float lf = atanhf(fminf(nmv, CLIP1)) / nmv;
        float rc[8];
        float q = 0.f;
#pragma unroll
        for (int i = 0; i < 8; i++) { rc[i] = fmaxf(lf*hm[i], 0.f); q += rc[i]*rc[i]; }
        float rs = warpSum(q);
        float nr = sqrtf(fmaxf(rs, EPSF));
        float ef = tanhf(nr) / nr;
        float nhr = sqrtf(fmaxf(ef*ef*rs, EPSF));
        float adj = (nhr > MAXN) ? MAXN/nhr : 1.0f;
#pragma unroll
        for (int i = 0; i < 8; i++) so[lane*8 + i][pl] = ef * adj * rc[i];
    }
    __syncthreads();
#pragma unroll 8
    for (int i = 0; i < 32; i++) {
        int c = i*8 + w8;
        out[(size_t)(b*256 + c)*1024 + hw0 + lane] = so[c][lane];
    }
}

// ---------------- launcher ----------------
extern "C" void kernel_launch(void* const* d_in, const int* in_sizes, int n_in,
                              void* d_out, int out_size) {
    const float* x  = (const float*)d_in[0];
    const float* z1 = (const float*)d_in[1];
    const float* z2 = (const float*)d_in[2];
    const float* w1 = (const float*)d_in[3];
    const float* b1 = (const float*)d_in[4];
    const float* w2 = (const float*)d_in[5];
    const float* b2 = (const float*)d_in[6];
    float* out = (float*)d_out;

    // scale = Beta(1152, 0.5) / Beta(128, 0.5)
    double lg = lgamma(1152.0) - lgamma(1152.5) - lgamma(128.0) + lgamma(128.5);
    float scale = (float)exp(lg);

    static int smem_set = 0;
    if (!smem_set) {
        cudaFuncSetAttribute(wino_gemm, cudaFuncAttributeMaxDynamicSharedMemorySize, CONV_SMEM);
        smem_set = 1;
    }

    dim3 ggrid(8, 4, 36);

    wino_u<<<dim3(256, 2), 256>>>(z1, z2);       // 0
    pre2_kernel<<<PNUM/32, 256>>>(x, scale);     // 1
    wino_in<<<NTIL, 256>>>();                    // 2
    wino_gemm<<<ggrid, 256, CONV_SMEM>>>(0);     // 3  <- ncu capture target
    wino_out<<<NTIL, 256>>>(0);

    bnmu_kernel<<<8, 256>>>(b1);
    bnvar_w<<<256, 256>>>(w1);
    bnapply_w<<<PNUM/8, 256>>>(b1, scale);

    wino_in<<<NTIL, 256>>>();
    wino_gemm<<<ggrid, 256, CONV_SMEM>>>(1);
    wino_out<<<NTIL, 256>>>(256);

    bnmu_kernel<<<8, 256>>>(b2);
    bnvar_w<<<256, 256>>>(w2);
    final2_kernel<<<PNUM/32, 256>>>(b2, out);
}

// round 12
// speedup vs baseline: 2.1640x; 1.0064x over previous
#include <cuda_runtime.h>
#include <cuda_bf16.h>
#include <math.h>
#include <stdint.h>

// Problem constants: B=16, C=256, H=W=32
#define PNUM 16384
#define CNUM 256
#define CLIP1 0.9999999f
#define MAXN  0.99999f
#define EPSF  1e-15f

#define NPOS 36
#define NTIL 1024
#define STAGE_BYTES 24576u       // Ahi 8K + Alo 8K + Bhi 4K + Blo 4K
#define CONV_SMEM (3*24576)      // 72 KB -> 3 CTAs/SM

// ---------------- device scratch ----------------
__device__ __align__(16) float g_v [PNUM*CNUM];
__device__ __align__(16) __nv_bfloat16 g_Vhi[NPOS*NTIL*CNUM];
__device__ __align__(16) __nv_bfloat16 g_Vlo[NPOS*NTIL*CNUM];
__device__ __align__(16) __nv_bfloat16 g_uhi1[NPOS*CNUM*CNUM];
__device__ __align__(16) __nv_bfloat16 g_ulo1[NPOS*CNUM*CNUM];
__device__ __align__(16) __nv_bfloat16 g_uhi2[NPOS*CNUM*CNUM];
__device__ __align__(16) __nv_bfloat16 g_ulo2[NPOS*CNUM*CNUM];
__device__ __align__(16) float g_m [NPOS*NTIL*CNUM];
__device__ __align__(16) float g_h [PNUM*CNUM];   // NORMALIZED h (post FC)
__device__ __align__(16) float g_xl[PNUM*CNUM];
__device__ float g_q2[PNUM];
__device__ float g_zn[512];
__device__ float g_pm [NTIL*CNUM];
__device__ float g_pm2[8*CNUM];
__device__ float g_pd[NTIL];
__device__ float g_pv[512];
__device__ float g_mu[CNUM];
__device__ float g_sc[8];
__device__ int   g_ctr  = 0;
__device__ int   g_ctr2 = 0;

// ---------------- PTX helpers ----------------
__device__ __forceinline__ uint32_t smem_u32(const void* p) {
    uint32_t a;
    asm("{ .reg .u64 t; cvta.to.shared.u64 t, %1; cvt.u32.u64 %0, t; }" : "=r"(a) : "l"(p));
    return a;
}
__device__ __forceinline__ void cpa16(uint32_t dst, const void* src) {
    asm volatile("cp.async.cg.shared.global [%0], [%1], 16;" :: "r"(dst), "l"(src) : "memory");
}
__device__ __forceinline__ void cp_commit() {
    asm volatile("cp.async.commit_group;" ::: "memory");
}
template<int N>
__device__ __forceinline__ void cp_wait() {
    asm volatile("cp.async.wait_group %0;" :: "n"(N) : "memory");
}
__device__ __forceinline__ void ldsm4(uint32_t* r, uint32_t addr) {
    asm volatile("ldmatrix.sync.aligned.m8n8.x4.shared.b16 {%0,%1,%2,%3}, [%4];"
        : "=r"(r[0]), "=r"(r[1]), "=r"(r[2]), "=r"(r[3]) : "r"(addr));
}
__device__ __forceinline__ void mma16816(float* d, const uint32_t* a, const uint32_t* b) {
    asm volatile("mma.sync.aligned.m16n8k16.row.col.f32.bf16.bf16.f32 "
        "{%0,%1,%2,%3}, {%4,%5,%6,%7}, {%8,%9}, {%0,%1,%2,%3};"
        : "+f"(d[0]), "+f"(d[1]), "+f"(d[2]), "+f"(d[3])
        : "r"(a[0]), "r"(a[1]), "r"(a[2]), "r"(a[3]), "r"(b[0]), "r"(b[1]));
}
__device__ __forceinline__ uint32_t swz(int r, int c) {
    return (uint32_t)(((r >> 1) << 7) | (((((r & 1) << 2) | c) ^ ((r >> 1) & 7)) << 4));
}

// ---------------- reductions ----------------
__device__ __forceinline__ float warpSum(float v) {
#pragma unroll
    for (int o = 16; o > 0; o >>= 1) v += __shfl_xor_sync(0xffffffffu, v, o);
    return v;
}
template<int K>
__device__ __forceinline__ void blockReduceK(float* v, float* sbuf) {
    int tid = threadIdx.x, lane = tid & 31, wid = tid >> 5;
#pragma unroll
    for (int i = 0; i < K; i++) {
        float x = v[i];
#pragma unroll
        for (int o = 16; o > 0; o >>= 1) x += __shfl_down_sync(0xffffffffu, x, o);
        if (lane == 0) sbuf[i*8 + wid] = x;
    }
    __syncthreads();
    if (tid == 0) {
#pragma unroll
        for (int i = 0; i < K; i++) {
            float s = sbuf[i*8];
            for (int w = 1; w < 8; w++) s += sbuf[i*8 + w];
            sbuf[i*8] = s;
        }
    }
    __syncthreads();
#pragma unroll
    for (int i = 0; i < K; i++) v[i] = sbuf[i*8];
    __syncthreads();
}

// ---------------- Winograd transforms ----------------
__device__ __forceinline__ void bt6(const float* in, float* out) {
    out[0] =  4.f*in[0] - 5.f*in[2] + in[4];
    out[1] = -4.f*in[1] - 4.f*in[2] + in[3] + in[4];
    out[2] =  4.f*in[1] - 4.f*in[2] - in[3] + in[4];
    out[3] = -2.f*in[1] -     in[2] + 2.f*in[3] + in[4];
    out[4] =  2.f*in[1] -     in[2] - 2.f*in[3] + in[4];
    out[5] =  4.f*in[1] - 5.f*in[3] + in[5];
}
__device__ __forceinline__ void g6(const float* in, float* out) {
    out[0] = 0.25f*in[0];
    out[1] = -(in[0] + in[1] + in[2]) * (1.f/6.f);
    out[2] = (-in[0] + in[1] - in[2]) * (1.f/6.f);
    out[3] = in[0]*(1.f/24.f) + in[1]*(1.f/12.f) + in[2]*(1.f/6.f);
    out[4] = in[0]*(1.f/24.f) - in[1]*(1.f/12.f) + in[2]*(1.f/6.f);
    out[5] = in[2];
}
__device__ __forceinline__ void at6(const float* in, float* out) {
    out[0] = in[0] + in[1] + in[2] + in[3] + in[4];
    out[1] = in[1] - in[2] + 2.f*(in[3] - in[4]);
    out[2] = in[1] + in[2] + 4.f*(in[3] + in[4]);
    out[3] = in[1] - in[2] + 8.f*(in[3] - in[4]) + in[5];
}

// ---------------- U = G z G^T (+ fused z column norms), both weight sets ----------------
__global__ void wino_u(const float* __restrict__ z1, const float* __restrict__ z2) {
    __shared__ float sb[8];
    const float* z = blockIdx.y ? z2 : z1;
    __nv_bfloat16* uh = blockIdx.y ? g_uhi2 : g_uhi1;
    __nv_bfloat16* ul = blockIdx.y ? g_ulo2 : g_ulo1;
    int co = blockIdx.x, ci = threadIdx.x;
    float g[3][3];
    float nsum = 0.f;
#pragma unroll
    for (int i = 0; i < 3; i++)
#pragma unroll
        for (int j = 0; j < 3; j++) {
            float w = z[(size_t)((i*3 + j)*256 + ci)*256 + co];
            g[i][j] = w;
            nsum += w*w;
        }
    float r1[1] = { nsum };
    blockReduceK<1>(r1, sb);
    if (ci == 0) g_zn[blockIdx.y*256 + co] = sqrtf(fmaxf(r1[0], EPSF));

    float t[6][3];
#pragma unroll
    for (int j = 0; j < 3; j++) {
        float in[3] = { g[0][j], g[1][j], g[2][j] };
        float out[6];
        g6(in, out);
#pragma unroll
        for (int a = 0; a < 6; a++) t[a][j] = out[a];
    }
#pragma unroll
    for (int a = 0; a < 6; a++) {
        float out[6];
        g6(t[a], out);
#pragma unroll
        for (int b = 0; b < 6; b++) {
            float u = out[b];
            __nv_bfloat16 hi = __float2bfloat16(u);
            size_t idx = ((size_t)((a*6 + b)*256 + co))*256 + ci;
            uh[idx] = hi;
            ul[idx] = __float2bfloat16(u - __bfloat162float(hi));
        }
    }
}

// ---------------- V = B^T d B per tile ----------------
__global__ void wino_in() {
    int t = blockIdx.x, ci = threadIdx.x;
    int b = t >> 6, tr = (t >> 3) & 7, tc = t & 7;
    int base = b << 10;
    float d[6][6];
#pragma unroll
    for (int y = 0; y < 6; y++) {
        int iy = 4*tr - 1 + y;
#pragma unroll
        for (int x = 0; x < 6; x++) {
            int ix = 4*tc - 1 + x;
            bool ok = ((unsigned)iy < 32u) && ((unsigned)ix < 32u);
            d[y][x] = ok ? g_v[(size_t)(base + iy*32 + ix)*256 + ci] : 0.f;
        }
    }
    float e[6][6];
#pragma unroll
    for (int x = 0; x < 6; x++) {
        float in[6] = { d[0][x], d[1][x], d[2][x], d[3][x], d[4][x], d[5][x] };
        float out[6];
        bt6(in, out);
#pragma unroll
        for (int a = 0; a < 6; a++) e[a][x] = out[a];
    }
#pragma unroll
    for (int a = 0; a < 6; a++) {
        float out[6];
        bt6(e[a], out);
#pragma unroll
        for (int bb = 0; bb < 6; bb++) {
            float v = out[bb];
            __nv_bfloat16 hi = __float2bfloat16(v);
            size_t idx = ((size_t)((a*6 + bb)*NTIL + t))*256 + ci;
            g_Vhi[idx] = hi;
            g_Vlo[idx] = __float2bfloat16(v - __bfloat162float(hi));
        }
    }
}

// ---------------- batched Winograd GEMM (direct reg->global epilogue) ----------------
__global__ void __launch_bounds__(256, 3) wino_gemm(int which) {
    extern __shared__ __align__(16) char dsm[];
    uint32_t sbase = smem_u32(dsm);

    const __nv_bfloat16* Bh = which ? g_uhi2 : g_uhi1;
    const __nv_bfloat16* Bl = which ? g_ulo2 : g_ulo1;
    int t0  = blockIdx.x << 7;
    int nq  = blockIdx.y;
    int pos = blockIdx.z;

    int tid = threadIdx.x, wid = tid >> 5, l = tid & 31;

    int c4 = tid & 3;
    int r0 = tid >> 2;
    uint32_t ph0 = swz(r0, c4), ph1 = swz(r0 + 64, c4);
    const __nv_bfloat16* Abase_hi = g_Vhi + ((size_t)pos*NTIL + t0)*256;
    const __nv_bfloat16* Abase_lo = g_Vlo + ((size_t)pos*NTIL + t0)*256;
    const __nv_bfloat16* Bbase_hi = Bh + ((size_t)pos*256 + nq*64)*256;
    const __nv_bfloat16* Bbase_lo = Bl + ((size_t)pos*256 + nq*64)*256;
    size_t a0 = (size_t)r0*256 + c4*8, a1 = (size_t)(r0 + 64)*256 + c4*8;

    int m0 = (wid & 3) << 5;
    int n0w = (wid >> 2) << 5;
    int mi = l >> 3;
    int rA = m0 + ((mi & 1) << 3) + (l & 7);
    uint32_t qA0 = swz(rA, mi >> 1);
    int rB = n0w + (((mi >> 1) & 1) << 3) + (l & 7);
    uint32_t qB0 = swz(rB, mi & 1);

    float acc[2][4][4];
#pragma unroll
    for (int i = 0; i < 2; i++)
#pragma unroll
        for (int j = 0; j < 4; j++)
#pragma unroll
            for (int k = 0; k < 4; k++) acc[i][j][k] = 0.f;

    auto load_chunk = [&](int kc, int stage) {
        size_t coff = (size_t)(kc << 5);
        uint32_t st = sbase + (uint32_t)stage*STAGE_BYTES;
        cpa16(st + ph0,         Abase_hi + a0 + coff);
        cpa16(st + 8192 + ph0,  Abase_lo + a0 + coff);
        cpa16(st + ph1,         Abase_hi + a1 + coff);
        cpa16(st + 8192 + ph1,  Abase_lo + a1 + coff);
        cpa16(st + 16384 + ph0, Bbase_hi + a0 + coff);
        cpa16(st + 20480 + ph0, Bbase_lo + a0 + coff);
        cp_commit();
    };

    load_chunk(0, 0);
    load_chunk(1, 1);

    for (int kc = 0; kc < 8; kc++) {
        int stage = kc % 3;
        if (kc < 6) cp_wait<1>(); else cp_wait<0>();
        __syncthreads();
        if (kc + 2 < 8) load_chunk(kc + 2, (kc + 2) % 3);

        uint32_t st = sbase + (uint32_t)stage*STAGE_BYTES;
        uint32_t Ahi = st, Alo = st + 8192, Bhi = st + 16384, Blo = st + 20480;
#pragma unroll
        for (int ks = 0; ks < 2; ks++) {
            uint32_t kx = (uint32_t)(ks << 5);
            uint32_t qa = qA0 ^ kx, qb = qB0 ^ kx;
            uint32_t ah[8], al[8], bbv[8];
            ldsm4(bbv,     Bhi + qb);
            ldsm4(bbv + 4, Bhi + qb + 1024);
            ldsm4(ah,     Ahi + qa);
            ldsm4(ah + 4, Ahi + qa + 1024);
            ldsm4(al,     Alo + qa);
            ldsm4(al + 4, Alo + qa + 1024);
#pragma unroll
            for (int nf = 0; nf < 4; nf++) {
                const uint32_t* bp = bbv + nf*2;
                mma16816(acc[0][nf], ah,     bp);
                mma16816(acc[1][nf], ah + 4, bp);
            }
#pragma unroll
            for (int nf = 0; nf < 4; nf++) {
                const uint32_t* bp = bbv + nf*2;
                mma16816(acc[0][nf], al,     bp);
                mma16816(acc[1][nf], al + 4, bp);
            }
            ldsm4(bbv,     Blo + qb);
            ldsm4(bbv + 4, Blo + qb + 1024);
#pragma unroll
            for (int nf = 0; nf < 4; nf++) {
                const uint32_t* bp = bbv + nf*2;
                mma16816(acc[0][nf], ah,     bp);
                mma16816(acc[1][nf], ah + 4, bp);
            }
        }
    }

    int row0 = m0 + (l >> 2);
    int col0 = n0w + ((l & 3) << 1);
    float* gm = g_m + ((size_t)pos*NTIL + t0)*256 + nq*64;
#pragma unroll
    for (int mf = 0; mf < 2; mf++)
#pragma unroll
        for (int hf = 0; hf < 2; hf++) {
            int r = row0 + mf*16 + hf*8;
            float* rowp = gm + (size_t)r*256;
#pragma unroll
            for (int nf = 0; nf < 4; nf++)
                *(float2*)(rowp + col0 + nf*8) =
                    make_float2(acc[mf][nf][hf*2], acc[mf][nf][hf*2 + 1]);
        }
}

// ---------------- pre2 (+ fused xT) ----------------
__global__ void pre2_kernel(const float* __restrict__ x, float scale) {
    __shared__ float sx[256][33];
    int tid = threadIdx.x, lane = tid & 31, w8 = tid >> 5;
    int p0 = blockIdx.x * 32;
    int b = p0 >> 10, hw0 = p0 & 1023;
#pragma unroll 8
    for (int i = 0; i < 32; i++) {
        int c = i*8 + w8;
        sx[c][lane] = x[(size_t)(b*256 + c)*1024 + hw0 + lane];
    }
    __syncthreads();
#pragma unroll 8
    for (int pl = 0; pl < 32; pl++)
        g_xl[(size_t)(p0 + pl)*256 + tid] = sx[tid][pl];
#pragma unroll
    for (int pp = 0; pp < 4; pp++) {
        int pl = w8*4 + pp;
        int p = p0 + pl;
        float xv[8];
#pragma unroll
        for (int i = 0; i < 8; i++) xv[i] = sx[lane*8 + i][pl];
        float q = 0.f;
#pragma unroll
        for (int i = 0; i < 8; i++) q += xv[i]*xv[i];
        float n2 = warpSum(q);
        float n = sqrtf(fmaxf(n2, EPSF));
        float f = atanhf(fminf(n, CLIP1)) / n * scale;
        float4 o0 = make_float4(f*xv[0], f*xv[1], f*xv[2], f*xv[3]);
        float4 o1 = make_float4(f*xv[4], f*xv[5], f*xv[6], f*xv[7]);
        float* dst = g_v + (size_t)p*256 + lane*8;
        *(float4*)dst = o0;
        *(float4*)(dst + 4) = o1;
        if (lane == 0) g_q2[p] = f*f*n2;
    }
}

// ---------------- per-pixel s ----------------
__device__ __forceinline__ float s_from_q2(int p) {
    int h = (p >> 5) & 31, w = p & 31;
    float np2 = 0.f;
#pragma unroll
    for (int dy = -1; dy <= 1; dy++)
#pragma unroll
        for (int dx = -1; dx <= 1; dx++) {
            int sh = h + dy, sw = w + dx;
            if ((unsigned)sh < 32u && (unsigned)sw < 32u) np2 += g_q2[p + dy*32 + dx];
        }
    float np = sqrtf(fmaxf(np2, EPSF));
    float th = tanhf(np);
    float uf = th / np;
    float un = th;
    if (un > MAXN) { uf *= MAXN/un; un = MAXN; }
    float lam = 2.0f / fmaxf(1.0f - un*un, EPSF);
    return lam * uf;
}

// ---------------- output transform + FC + BN partials; writes NORMALIZED h ----------------
__global__ void wino_out(int znoff) {
    __shared__ float ss[16];
    __shared__ float slam[16];
    __shared__ float sld[16];
    __shared__ float sinv[16];
    __shared__ float ybuf[16][260];
    int t = blockIdx.x, co = threadIdx.x;
    int b = t >> 6, tr = (t >> 3) & 7, tc = t & 7;
    int prow = (b << 10) + (4*tr)*32 + 4*tc;
    if (co < 16) {
        int r = co >> 2, c = co & 3;
        ss[co] = s_from_q2(prow + r*32 + c);
    }
    float m[36];
#pragma unroll
    for (int pos = 0; pos < 36; pos++)
        m[pos] = g_m[((size_t)pos*NTIL + t)*256 + co];
    float Z[4][6];
#pragma unroll
    for (int bb = 0; bb < 6; bb++) {
        float in[6] = { m[bb], m[6+bb], m[12+bb], m[18+bb], m[24+bb], m[30+bb] };
        float out[4];
        at6(in, out);
#pragma unroll
        for (int r = 0; r < 4; r++) Z[r][bb] = out[r];
    }
    float zn = g_zn[znoff + co];
    __syncthreads();
#pragma unroll
    for (int r = 0; r < 4; r++) {
        float Y[4];
        at6(Z[r], Y);
#pragma unroll
        for (int c = 0; c < 4; c++) {
            float s = ss[r*4 + c];
            float tt = Y[c] * s / zn;
            ybuf[r*4 + c][co] = sinhf(2.0f * zn * asinhf(tt));
        }
    }
    __syncthreads();
    int wd = co >> 5, lid = co & 31;
#pragma unroll
    for (int k = 0; k < 2; k++) {
        int pl = wd*2 + k;
        float q = 0.f;
#pragma unroll
        for (int i = 0; i < 8; i++) {
            float v = ybuf[pl][lid*8 + i];
            q += v*v;
        }
        float tot = warpSum(q);
        float inv = 1.0f / (1.0f + sqrtf(1.0f + tot));
        float n2 = tot*inv*inv;
        float lam = 2.0f / fmaxf(1.0f - n2, EPSF);
        if (lid == 0) { slam[pl] = lam*inv; sld[pl] = lam - 1.0f; sinv[pl] = inv; }
    }
    __syncthreads();
    float accm = 0.f;
#pragma unroll
    for (int pl = 0; pl < 16; pl++)
        accm += slam[pl] * ybuf[pl][co];
    g_pm[t*256 + co] = accm;
    if (co == 0) {
        float d = 0.f;
#pragma unroll
        for (int pl = 0; pl < 16; pl++) d += sld[pl];
        g_pd[t] = d;
    }
#pragma unroll
    for (int pl = 0; pl < 16; pl++) {
        int p = prow + (pl >> 2)*32 + (pl & 3);
        g_h[(size_t)p*256 + co] = ybuf[pl][co] * sinv[pl];
    }
}

// ---------------- BN mu: 8-block partial sum + last-block finalize (zeroes rstd gate) ----------------
__global__ void bnmu_kernel(const float* __restrict__ bias) {
    __shared__ float sb[24];
    __shared__ int slast;
    int c = threadIdx.x;
    float s = 0.f;
    int g0 = blockIdx.x * 128;
    for (int g = 0; g < 128; g++) s += g_pm[(g0 + g)*256 + c];
    g_pm2[blockIdx.x*256 + c] = s;
    __threadfence();
    if (c == 0) slast = (atomicAdd(&g_ctr2, 1) == 7);
    __syncthreads();
    if (!slast) return;
    __threadfence();
    float msum = 0.f;
#pragma unroll
    for (int j = 0; j < 8; j++) msum += g_pm2[j*256 + c];
    float dv = 0.f;
#pragma unroll
    for (int j = 0; j < 4; j++) dv += g_pd[j*256 + c];
    float r1[1] = { dv };
    blockReduceK<1>(r1, sb);
    float den = fmaxf(r1[0], EPSF);
    float m = msum / den;
    float r2[1] = { m*m };
    blockReduceK<1>(r2, sb);
    float nm = sqrtf(fmaxf(r2[0], EPSF));
    float fac = tanhf(0.5f * atanhf(fminf(nm, CLIP1))) / nm;
    float muc = fac * m;
    g_mu[c] = muc;
    float bc = bias[c];
    float r3[3] = { muc*muc, bc*bc, bc*muc };
    blockReduceK<3>(r3, sb);
    if (c == 0) {
        float mu2 = r3[0], b2 = r3[1], bm = r3[2];
        g_sc[0] = mu2;
        g_sc[1] = 2.0f / fmaxf(1.0f - mu2, EPSF);
        g_sc[2] = b2;
        g_sc[3] = 2.0f / fmaxf(1.0f - b2, EPSF);
        g_sc[4] = bm;
        ((volatile float*)g_sc)[5] = 0.f;   // gate for fused var+apply spin
        g_ctr2 = 0;
    }
}

// ---------------- variance partial for 64 or 32 pixels (normalized input) ----------------
__device__ __forceinline__ float var_pixel(int p, const float* mu8, float mu2) {
    int lid = threadIdx.x & 31;
    const float4* row = (const float4*)(g_h + (size_t)p*256 + lid*8);
    float4 a = row[0], cc = row[1];
    float v[8] = {a.x,a.y,a.z,a.w,cc.x,cc.y,cc.z,cc.w};
    float q1 = 0.f, q2 = 0.f;
#pragma unroll
    for (int j = 0; j < 8; j++) { q1 += v[j]*v[j]; q2 += v[j]*mu8[j]; }
    float xp2 = warpSum(q1);
    float ip  = warpSum(q2);
    float A = 1.0f - 2.0f*ip + mu2;
    float B = 1.0f - xp2;
    float nn = fmaxf(A*A*xp2 - 2.0f*A*B*ip + B*B*mu2, 0.f);
    float den = fmaxf(1.0f - 2.0f*ip + xp2*mu2, EPSF);
    float nr = sqrtf(fmaxf(nn/(den*den), EPSF));
    float dd = 2.0f * atanhf(fminf(nr, CLIP1));
    return dd*dd;
}

// ---------------- shared BN point transform (normalized input) ----------------
__device__ __forceinline__ float bn_point_w(const float* xv, const float* mu8, const float* b8,
                                            float* hc) {
    float mu2 = g_sc[0], lam_mu = g_sc[1], b2 = g_sc[2], lam_b = g_sc[3],
          bm = g_sc[4], rstd = g_sc[5];
    float s0 = 0.f, s1 = 0.f, s2 = 0.f;
#pragma unroll
    for (int i = 0; i < 8; i++) { s0 += xv[i]*xv[i]; s1 += mu8[i]*xv[i]; s2 += b8[i]*xv[i]; }
    float xp2 = warpSum(s0), ip = warpSum(s1), bx = warpSum(s2);
    float A  = 1.0f - 2.0f*ip + xp2;
    float Bc = 1.0f - mu2;
    float den = fmaxf(1.0f - 2.0f*ip + mu2*xp2, EPSF);
    float nd2 = fmaxf(A*A*mu2 - 2.0f*A*Bc*ip + Bc*Bc*xp2, 0.f) / (den*den);
    float nd = sqrtf(fmaxf(nd2, EPSF));
    float cv = (2.0f/lam_mu) * atanhf(fminf(nd, CLIP1)) / nd;
    float uw = cv * (Bc*bx - A*bm) / den;
    float vw = cv * (A*mu2 - Bc*ip) / den;
    float av  = -uw*mu2 - vw - 2.0f*bm*vw;
    float bv2 = -vw*b2 + uw;
    float dgy = fmaxf(1.0f - 2.0f*bm + b2*mu2, EPSF);
    float fac = (lam_mu / lam_b) * rstd;
    float uc[8];
    float t0 = 0.f, t1 = 0.f;
#pragma unroll
    for (int i = 0; i < 8; i++) {
        float vc = cv * (Bc*xv[i] - A*mu8[i]) / den;
        uc[i] = (vc + 2.0f*(av*b8[i] - bv2*mu8[i]) / dgy) * fac;
        t0 += uc[i]*uc[i];
        t1 += b8[i]*uc[i];
    }
    float u2 = warpSum(t0), bu = warpSum(t1);
    float nu = sqrtf(fmaxf(u2, EPSF));
    float tf = tanhf(0.5f * lam_b * nu) / nu;
    float s2m = tf*tf*u2;
    float bs  = tf*bu;
    float A3 = 1.0f + 2.0f*bs + s2m, B3 = 1.0f - b2;
    float den3 = fmaxf(1.0f + 2.0f*bs + b2*s2m, EPSF);
#pragma unroll
    for (int i = 0; i < 8; i++) hc[i] = (A3*b8[i] + B3*tf*uc[i]) / den3;
    float nh2 = fmaxf(A3*A3*b2 + 2.0f*A3*B3*bs + B3*B3*s2m, 0.f) / (den3*den3);
    float nh = sqrtf(fmaxf(nh2, EPSF));
    if (nh > MAXN) {
        float q = MAXN / nh;
#pragma unroll
        for (int i = 0; i < 8; i++) hc[i] *= q;
        nh = MAXN;
    }
    return nh;
}

// ---------------- FUSED variance + BN apply + hrelu + pre-for-conv2 ----------------
// 256 blocks x 64 pixels (all resident -> spin is safe)
__global__ void bnva_kernel(const float* __restrict__ bias, const float* __restrict__ weight,
                            float scale) {
    __shared__ float sv[8];
    __shared__ int slast;
    int wid = threadIdx.x >> 5, lid = threadIdx.x & 31;
    int p0 = blockIdx.x * 64;
    float mu8[8];
#pragma unroll
    for (int j = 0; j < 8; j++) mu8[j] = g_mu[lid*8 + j];
    float mu2 = g_sc[0];
    float acc = 0.f;
    for (int i = 0; i < 8; i++)
        acc += var_pixel(p0 + wid*8 + i, mu8, mu2);
    if (lid == 0) sv[wid] = acc;
    __syncthreads();
    if (threadIdx.x == 0) {
        float s = 0.f;
        for (int w = 0; w < 8; w++) s += sv[w];
        g_pv[blockIdx.x] = s;
        __threadfence();
        slast = (atomicAdd(&g_ctr, 1) == 255);
    }
    __syncthreads();
    if (slast) {
        float v = g_pv[threadIdx.x];
        __shared__ float sb[8];
        float r[1] = { v };
        blockReduceK<1>(r, sb);
        if (threadIdx.x == 0) {
            float var = r[0] / 16384.0f;
            g_ctr = 0;
            __threadfence();
            ((volatile float*)g_sc)[5] = sqrtf(weight[0] / fmaxf(var, EPSF));
        }
    }
    if (threadIdx.x == 0) {
        volatile float* vs = g_sc;
        while (vs[5] == 0.f) { }
    }
    __syncthreads();
    // apply phase
    float b8[8];
#pragma unroll
    for (int j = 0; j < 8; j++) b8[j] = bias[lid*8 + j];
    for (int i = 0; i < 8; i++) {
        int p = p0 + wid*8 + i;
        const float4* row = (const float4*)(g_h + (size_t)p*256 + lid*8);
        float4 a = row[0], cc = row[1];
        float xv[8] = {a.x,a.y,a.z,a.w,cc.x,cc.y,cc.z,cc.w};
        float hc[8];
        float nh = bn_point_w(xv, mu8, b8, hc);
        float lf = atanhf(fminf(nh, CLIP1)) / nh;
        float rc[8];
        float q = 0.f;
#pragma unroll
        for (int k = 0; k < 8; k++) { rc[k] = fmaxf(lf*hc[k], 0.f); q += rc[k]*rc[k]; }
        float rs = warpSum(q);
        float nr = sqrtf(fmaxf(rs, EPSF));
        float ef = tanhf(nr) / nr;
        float nhr = sqrtf(fmaxf(ef*ef*rs, EPSF));
        float adj = 1.0f;
        if (nhr > MAXN) { adj = MAXN/nhr; nhr = MAXN; }
        float f3 = atanhf(fminf(nhr, CLIP1)) / nhr * scale;
        float g = f3 * ef * adj;
        float4 o0 = make_float4(g*rc[0], g*rc[1], g*rc[2], g*rc[3]);
        float4 o1 = make_float4(g*rc[4], g*rc[5], g*rc[6], g*rc[7]);
        float* dst = g_v + (size_t)p*256 + lid*8;
        *(float4*)dst = o0;
        *(float4*)(dst + 4) = o1;
        if (lid == 0) g_q2[p] = f3*f3*nhr*nhr;
    }
}

// ---------------- FUSED variance + BN2 apply + residual + hrelu + NCHW out ----------------
// 512 blocks x 32 pixels (all resident)
__global__ void bnvf_kernel(const float* __restrict__ bias, const float* __restrict__ weight,
                            float* __restrict__ out) {
    __shared__ float so[256][33];
    __shared__ float sv[8];
    __shared__ int slast;
    int tid = threadIdx.x, lane = tid & 31, w8 = tid >> 5;
    int p0 = blockIdx.x * 32;
    int b = p0 >> 10, hw0 = p0 & 1023;
    float mu8[8], b8[8];
#pragma unroll
    for (int j = 0; j < 8; j++) { mu8[j] = g_mu[lane*8 + j]; b8[j] = bias[lane*8 + j]; }
    float mu2 = g_sc[0];
    float acc = 0.f;
    for (int i = 0; i < 4; i++)
        acc += var_pixel(p0 + w8*4 + i, mu8, mu2);
    if (lane == 0) sv[w8] = acc;
    __syncthreads();
    if (tid == 0) {
        float s = 0.f;
        for (int w = 0; w < 8; w++) s += sv[w];
        g_pv[blockIdx.x] = s;
        __threadfence();
        slast = (atomicAdd(&g_ctr, 1) == 511);
    }
    __syncthreads();
    if (slast) {
        float v = g_pv[tid] + g_pv[tid + 256];
        __shared__ float sb[8];
        float r[1] = { v };
        blockReduceK<1>(r, sb);
        if (tid == 0) {
            float var = r[0] / 16384.0f;
            g_ctr = 0;
            __threadfence();
            ((volatile float*)g_sc)[5] = sqrtf(weight[0] / fmaxf(var, EPSF));
        }
    }
    if (tid == 0) {
        volatile float* vs = g_sc;
        while (vs[5] == 0.f) { }
    }
    __syncthreads();
#pragma unroll
    for (int pp = 0; pp < 4; pp++) {
        int pl = w8*4 + pp;
        int p = p0 + pl;
        const float4* row = (const float4*)(g_h + (size_t)p*256 + lane*8);
        float4 a = row[0], cc = row[1];
        float xv[8] = {a.x,a.y,a.z,a.w,cc.x,cc.y,cc.z,cc.w};
        float hc[8];
        float nh = bn_point_w(xv, mu8, b8, hc);
        const float4* rrow = (const float4*)(g_xl + (size_t)p*256 + lane*8);
        float4 r0 = rrow[0], r1 = rrow[1];
        float res[8] = {r0.x,r0.y,r0.z,r0.w,r1.x,r1.y,r1.z,r1.w};
        float q1 = 0.f, q2 = 0.f;
#pragma unroll
        for (int i = 0; i < 8; i++) { q1 += res[i]*res[i]; q2 += hc[i]*res[i]; }
        float y2 = warpSum(q1), xy = warpSum(q2);
        float x2 = nh*nh;
        float A4 = 1.0f + 2.0f*xy + y2, B4 = 1.0f - x2;
        float den4 = fmaxf(1.0f + 2.0f*xy + x2*y2, EPSF);
        float hm[8];
#pragma unroll
        for (int i = 0; i < 8; i++) hm[i] = (A4*hc[i] + B4*res[i]) / den4;
        float nm2 = fmaxf(A4*A4*x2 + 2.0f*A4*B4*xy + B4*B4*y2, 0.f) / (den4*den4);
        float nmv = sqrtf(fmaxf(nm2, EPSF));
        float lf = atanhf(fminf(nmv, CLIP1)) / nmv;
        float rc[8];
        float q = 0.f;
#pragma unroll
        for (int i = 0; i < 8; i++) { rc[i] = fmaxf(lf*hm[i], 0.f); q += rc[i]*rc[i]; }
        float rs = warpSum(q);
        float nr = sqrtf(fmaxf(rs, EPSF));
        float ef = tanhf(nr) / nr;
        float nhr = sqrtf(fmaxf(ef*ef*rs, EPSF));
        float adj = (nhr > MAXN) ? MAXN/nhr : 1.0f;
#pragma unroll
        for (int i = 0; i < 8; i++) so[lane*8 + i][pl] = ef * adj * rc[i];
    }
    __syncthreads();
#pragma unroll 8
    for (int i = 0; i < 32; i++) {
        int c = i*8 + w8;
        out[(size_t)(b*256 + c)*1024 + hw0 + lane] = so[c][lane];
    }
}

// ---------------- launcher ----------------
extern "C" void kernel_launch(void* const* d_in, const int* in_sizes, int n_in,
                              void* d_out, int out_size) {
    const float* x  = (const float*)d_in[0];
    const float* z1 = (const float*)d_in[1];
    const float* z2 = (const float*)d_in[2];
    const float* w1 = (const float*)d_in[3];
    const float* b1 = (const float*)d_in[4];
    const float* w2 = (const float*)d_in[5];
    const float* b2 = (const float*)d_in[6];
    float* out = (float*)d_out;

    // scale = Beta(1152, 0.5) / Beta(128, 0.5)
    double lg = lgamma(1152.0) - lgamma(1152.5) - lgamma(128.0) + lgamma(128.5);
    float scale = (float)exp(lg);

    static int smem_set = 0;
    if (!smem_set) {
        cudaFuncSetAttribute(wino_gemm, cudaFuncAttributeMaxDynamicSharedMemorySize, CONV_SMEM);
        smem_set = 1;
    }

    dim3 ggrid(8, 4, 36);

    wino_u<<<dim3(256, 2), 256>>>(z1, z2);       // 0
    pre2_kernel<<<PNUM/32, 256>>>(x, scale);     // 1
    wino_in<<<NTIL, 256>>>();                    // 2
    wino_gemm<<<ggrid, 256, CONV_SMEM>>>(0);     // 3  <- ncu capture target
    wino_out<<<NTIL, 256>>>(0);

    bnmu_kernel<<<8, 256>>>(b1);                 // zeroes rstd gate
    bnva_kernel<<<256, 256>>>(b1, w1, scale);    // fused var + apply

    wino_in<<<NTIL, 256>>>();
    wino_gemm<<<ggrid, 256, CONV_SMEM>>>(1);
    wino_out<<<NTIL, 256>>>(256);

    bnmu_kernel<<<8, 256>>>(b2);
    bnvf_kernel<<<512, 256>>>(b2, w2, out);      // fused var + final
}